// round 1
// baseline (speedup 1.0000x reference)
#include <cuda_runtime.h>

#define B_   4
#define C_   256
#define H_   48
#define W_   48
#define HW   2304
#define HEADS 8
#define DH   64
#define HID  512
#define S_   2304
#define EPSF 1e-5f
#define SCALEF 0.125f
#define LOG2E 1.4426950408889634f
#define LOG2_10000 13.287712379549449f

// ---------------- scratch (static device globals; no runtime alloc) ----------------
__device__ float g_xn  [B_*C_*HW];          // layernorm output  [B][C][HW]
__device__ float g_qkv [B_*3*HID*HW];       // qkv gemm output   [B][1536][HW]
__device__ float g_conv[B_*3*HID*HW];       // dwconv output     [B][1536][HW]
__device__ float g_q   [B_*HEADS*S_*DH];    // [B][H][S][DH]  (rope'd, *SCALE*LOG2E)
__device__ float g_k   [B_*HEADS*S_*DH];    // [B][H][S][DH]  (rope'd)
__device__ float g_v   [B_*HEADS*S_*DH];    // [B][H][S][DH]
__device__ float g_o   [B_*HEADS*S_*DH];    // attention output [B][H][S][DH]

// ---------------- 1) layernorm over channel dim ----------------
__global__ void ln_kernel(const float* __restrict__ x, const float* __restrict__ g) {
    int idx = blockIdx.x * blockDim.x + threadIdx.x;  // b*HW + hw
    if (idx >= B_ * HW) return;
    int b = idx / HW, hw = idx - b * HW;
    const float* xp = x + (size_t)b * C_ * HW + hw;
    float s0 = 0.f, s1 = 0.f, s2 = 0.f, s3 = 0.f;
    float q0 = 0.f, q1 = 0.f, q2 = 0.f, q3 = 0.f;
    #pragma unroll 4
    for (int c = 0; c < C_; c += 4) {
        float v0 = xp[(size_t)(c + 0) * HW];
        float v1 = xp[(size_t)(c + 1) * HW];
        float v2 = xp[(size_t)(c + 2) * HW];
        float v3 = xp[(size_t)(c + 3) * HW];
        s0 += v0; q0 += v0 * v0;
        s1 += v1; q1 += v1 * v1;
        s2 += v2; q2 += v2 * v2;
        s3 += v3; q3 += v3 * v3;
    }
    float mean = (s0 + s1 + s2 + s3) * (1.f / C_);
    float var  = (q0 + q1 + q2 + q3) * (1.f / C_) - mean * mean;
    float r = rsqrtf(var + EPSF);
    float* op = g_xn + (size_t)b * C_ * HW + hw;
    #pragma unroll 4
    for (int c = 0; c < C_; c++)
        op[(size_t)c * HW] = (xp[(size_t)c * HW] - mean) * r * g[c];
}

// ---------------- 2) QKV gemm: g_qkv[b,o,hw] = sum_c W[o,c] * g_xn[b,c,hw] ----------------
__global__ void __launch_bounds__(256) qkv_gemm(const float* __restrict__ Wq) {
    __shared__ float As[16][64];
    __shared__ float Bs[16][64];
    const int b  = blockIdx.z;
    const int m0 = blockIdx.y * 64, n0 = blockIdx.x * 64;
    const int tx = threadIdx.x & 15, ty = threadIdx.x >> 4;
    const float* Bmat = g_xn + (size_t)b * C_ * HW;
    float acc[4][4] = {};
    const int am = threadIdx.x >> 2, ak = (threadIdx.x & 3) << 2;
    const int bk = threadIdx.x >> 4, bn = (threadIdx.x & 15) << 2;
    for (int k0 = 0; k0 < C_; k0 += 16) {
        float4 av = *(const float4*)(Wq + (size_t)(m0 + am) * C_ + k0 + ak);
        As[ak + 0][am] = av.x; As[ak + 1][am] = av.y;
        As[ak + 2][am] = av.z; As[ak + 3][am] = av.w;
        *(float4*)(&Bs[bk][bn]) =
            *(const float4*)(Bmat + (size_t)(k0 + bk) * HW + n0 + bn);
        __syncthreads();
        #pragma unroll
        for (int kk = 0; kk < 16; kk++) {
            float4 a0 = *(float4*)(&As[kk][ty << 2]);
            float4 b0 = *(float4*)(&Bs[kk][tx << 2]);
            acc[0][0] += a0.x * b0.x; acc[0][1] += a0.x * b0.y; acc[0][2] += a0.x * b0.z; acc[0][3] += a0.x * b0.w;
            acc[1][0] += a0.y * b0.x; acc[1][1] += a0.y * b0.y; acc[1][2] += a0.y * b0.z; acc[1][3] += a0.y * b0.w;
            acc[2][0] += a0.z * b0.x; acc[2][1] += a0.z * b0.y; acc[2][2] += a0.z * b0.z; acc[2][3] += a0.z * b0.w;
            acc[3][0] += a0.w * b0.x; acc[3][1] += a0.w * b0.y; acc[3][2] += a0.w * b0.z; acc[3][3] += a0.w * b0.w;
        }
        __syncthreads();
    }
    float* Cm = g_qkv + (size_t)b * 3 * HID * HW;
    #pragma unroll
    for (int i = 0; i < 4; i++) {
        float4 r;
        r.x = acc[i][0]; r.y = acc[i][1]; r.z = acc[i][2]; r.w = acc[i][3];
        *(float4*)(Cm + (size_t)(m0 + (ty << 2) + i) * HW + n0 + (tx << 2)) = r;
    }
}

// ---------------- 3) depthwise 3x3 conv, SAME padding ----------------
__global__ void dwconv_kernel(const float* __restrict__ wq,
                              const float* __restrict__ wk,
                              const float* __restrict__ wv) {
    int idx = blockIdx.x * blockDim.x + threadIdx.x;
    if (idx >= B_ * 3 * HID * HW) return;
    int xx = idx % W_;
    int yy = (idx / W_) % H_;
    int c  = (idx / HW) % (3 * HID);
    const float* wsel = (c < HID) ? wq : (c < 2 * HID) ? wk : wv;
    const float* w = wsel + (size_t)(c & (HID - 1)) * 9;  // c % 512
    float w9[9];
    #pragma unroll
    for (int i = 0; i < 9; i++) w9[i] = __ldg(&w[i]);
    const float* ip = g_qkv + (size_t)(idx / HW) * HW;
    float acc = 0.f;
    #pragma unroll
    for (int dy = -1; dy <= 1; dy++) {
        int y = yy + dy;
        if (y < 0 || y >= H_) continue;
        #pragma unroll
        for (int dx = -1; dx <= 1; dx++) {
            int x = xx + dx;
            if (x < 0 || x >= W_) continue;
            acc += ip[y * W_ + x] * w9[(dy + 1) * 3 + (dx + 1)];
        }
    }
    g_conv[idx] = acc;
}

// ---------------- 4) rope + transpose to [B][H][S][DH] ----------------
__global__ void __launch_bounds__(256) rope_kernel() {
    __shared__ float tile[64][33];
    const int b   = blockIdx.z;
    const int sel = blockIdx.y >> 3;      // 0:q 1:k 2:v
    const int h   = blockIdx.y & 7;
    const int i0  = blockIdx.x * 32;
    const int cbase = sel * HID + h * DH;
    const int t  = threadIdx.x;
    const int ii = t & 31, dr = t >> 5;
    const float* src = g_conv + ((size_t)(b * 3 * HID + cbase)) * HW + i0;
    #pragma unroll
    for (int r = 0; r < 8; r++) {
        int dd = dr + r * 8;
        tile[dd][ii] = src[(size_t)dd * HW + ii];
    }
    __syncthreads();
    float* dst = (sel == 0 ? g_q : sel == 1 ? g_k : g_v)
                 + ((size_t)(b * HEADS + h) * S_ + i0) * DH;
    #pragma unroll
    for (int p = 0; p < 8; p++) {
        int e  = p * 256 + t;
        int dd = e & 63, jj = e >> 6;     // jj in 0..31
        float t1 = tile[dd][jj];
        float val;
        if (sel == 2) {
            val = t1;
        } else {
            int j = dd & 31;
            float invf = exp2f(-((float)(2 * j) * (1.0f / 64.0f)) * LOG2_10000);
            float a = (float)(i0 + jj) * invf;
            float sa, ca;
            sincosf(a, &sa, &ca);
            float t2 = tile[dd ^ 32][jj];
            val = (dd < 32) ? (t1 * ca - t2 * sa) : (t1 * ca + t2 * sa);
            if (sel == 0) val *= SCALEF * LOG2E;  // fold scale + base-2 conversion into q
        }
        dst[(size_t)jj * DH + dd] = val;
    }
}

// ---------------- 5) flash attention (fp32, online softmax in base 2) ----------------
__global__ void __launch_bounds__(128) flash_kernel() {
    __shared__ float4 Ks[32][16];
    __shared__ float4 Vs[32][16];
    const int b = blockIdx.z, h = blockIdx.y;
    const size_t base = (size_t)(b * HEADS + h) * S_ * DH;
    const int row = blockIdx.x * 128 + threadIdx.x;

    float q[64], o[64];
    const float4* qp = (const float4*)(g_q + base + (size_t)row * DH);
    #pragma unroll
    for (int d4 = 0; d4 < 16; d4++) {
        float4 tq = qp[d4];
        q[4 * d4 + 0] = tq.x; q[4 * d4 + 1] = tq.y;
        q[4 * d4 + 2] = tq.z; q[4 * d4 + 3] = tq.w;
        o[4 * d4 + 0] = 0.f; o[4 * d4 + 1] = 0.f;
        o[4 * d4 + 2] = 0.f; o[4 * d4 + 3] = 0.f;
    }
    float m = -3.0e38f, l = 0.f;

    const float4* kp = (const float4*)(g_k + base);
    const float4* vp = (const float4*)(g_v + base);

    for (int t0 = 0; t0 < S_; t0 += 32) {
        const float4* kt = kp + (size_t)t0 * 16;
        const float4* vt = vp + (size_t)t0 * 16;
        #pragma unroll
        for (int r = 0; r < 4; r++) {
            int e = r * 128 + threadIdx.x;
            ((float4*)Ks)[e] = kt[e];
            ((float4*)Vs)[e] = vt[e];
        }
        __syncthreads();

        float s[32];
        #pragma unroll 4
        for (int j = 0; j < 32; j++) {
            float a0 = 0.f, a1 = 0.f;
            #pragma unroll
            for (int d4 = 0; d4 < 16; d4 += 2) {
                float4 k0 = Ks[j][d4];
                float4 k1 = Ks[j][d4 + 1];
                a0 += q[4 * d4 + 0] * k0.x + q[4 * d4 + 1] * k0.y
                    + q[4 * d4 + 2] * k0.z + q[4 * d4 + 3] * k0.w;
                a1 += q[4 * d4 + 4] * k1.x + q[4 * d4 + 5] * k1.y
                    + q[4 * d4 + 6] * k1.z + q[4 * d4 + 7] * k1.w;
            }
            s[j] = a0 + a1;
        }

        float mt = m;
        #pragma unroll
        for (int j = 0; j < 32; j++) mt = fmaxf(mt, s[j]);
        float cf = exp2f(m - mt);
        m = mt;
        l *= cf;
        #pragma unroll
        for (int d = 0; d < 64; d++) o[d] *= cf;
        #pragma unroll
        for (int j = 0; j < 32; j++) {
            float p = exp2f(s[j] - m);
            l += p;
            s[j] = p;
        }
        #pragma unroll 2
        for (int j = 0; j < 32; j++) {
            float p = s[j];
            #pragma unroll
            for (int d4 = 0; d4 < 16; d4++) {
                float4 vv = Vs[j][d4];
                o[4 * d4 + 0] += p * vv.x; o[4 * d4 + 1] += p * vv.y;
                o[4 * d4 + 2] += p * vv.z; o[4 * d4 + 3] += p * vv.w;
            }
        }
        __syncthreads();
    }

    float inv = 1.f / l;
    float4* op = (float4*)(g_o + base + (size_t)row * DH);
    #pragma unroll
    for (int d4 = 0; d4 < 16; d4++) {
        float4 r;
        r.x = o[4 * d4 + 0] * inv; r.y = o[4 * d4 + 1] * inv;
        r.z = o[4 * d4 + 2] * inv; r.w = o[4 * d4 + 3] * inv;
        op[d4] = r;
    }
}

// ---------------- 6) output projection + bias ----------------
__global__ void __launch_bounds__(256) outproj_gemm(const float* __restrict__ Wo,
                                                    const float* __restrict__ bias,
                                                    float* __restrict__ out) {
    __shared__ float As[16][64];
    __shared__ float Bs[16][68];  // padded: gathered fill + aligned float4 reads
    const int b  = blockIdx.z;
    const int m0 = blockIdx.y * 64, n0 = blockIdx.x * 64;
    const int tx = threadIdx.x & 15, ty = threadIdx.x >> 4;
    float acc[4][4] = {};
    const int am = threadIdx.x >> 2, ak = (threadIdx.x & 3) << 2;
    const int kl = threadIdx.x & 15, nn0 = threadIdx.x >> 4;
    const float* Ob = g_o + (size_t)b * HEADS * S_ * DH;
    for (int k0 = 0; k0 < HID; k0 += 16) {
        float4 av = *(const float4*)(Wo + (size_t)(m0 + am) * HID + k0 + ak);
        As[ak + 0][am] = av.x; As[ak + 1][am] = av.y;
        As[ak + 2][am] = av.z; As[ak + 3][am] = av.w;
        int c = k0 + kl;
        const float* src = Ob + (size_t)(c >> 6) * S_ * DH + (c & 63);
        #pragma unroll
        for (int p = 0; p < 4; p++) {
            int nn = nn0 + p * 16;
            Bs[kl][nn] = src[(size_t)(n0 + nn) * DH];
        }
        __syncthreads();
        #pragma unroll
        for (int kk = 0; kk < 16; kk++) {
            float4 a0 = *(float4*)(&As[kk][ty << 2]);
            float4 b0 = *(float4*)(&Bs[kk][tx << 2]);
            acc[0][0] += a0.x * b0.x; acc[0][1] += a0.x * b0.y; acc[0][2] += a0.x * b0.z; acc[0][3] += a0.x * b0.w;
            acc[1][0] += a0.y * b0.x; acc[1][1] += a0.y * b0.y; acc[1][2] += a0.y * b0.z; acc[1][3] += a0.y * b0.w;
            acc[2][0] += a0.z * b0.x; acc[2][1] += a0.z * b0.y; acc[2][2] += a0.z * b0.z; acc[2][3] += a0.z * b0.w;
            acc[3][0] += a0.w * b0.x; acc[3][1] += a0.w * b0.y; acc[3][2] += a0.w * b0.z; acc[3][3] += a0.w * b0.w;
        }
        __syncthreads();
    }
    float* Cm = out + (size_t)b * C_ * HW;
    #pragma unroll
    for (int i = 0; i < 4; i++) {
        float bb = bias[m0 + (ty << 2) + i];
        float4 r;
        r.x = acc[i][0] + bb; r.y = acc[i][1] + bb;
        r.z = acc[i][2] + bb; r.w = acc[i][3] + bb;
        *(float4*)(Cm + (size_t)(m0 + (ty << 2) + i) * HW + n0 + (tx << 2)) = r;
    }
}

// ---------------- launcher ----------------
extern "C" void kernel_launch(void* const* d_in, const int* in_sizes, int n_in,
                              void* d_out, int out_size) {
    const float* x      = (const float*)d_in[0];
    const float* norm_g = (const float*)d_in[1];
    const float* w_qkv  = (const float*)d_in[2];
    const float* dw_q   = (const float*)d_in[3];
    const float* dw_k   = (const float*)d_in[4];
    const float* dw_v   = (const float*)d_in[5];
    const float* w_out  = (const float*)d_in[6];
    const float* b_out  = (const float*)d_in[7];
    float* out = (float*)d_out;

    ln_kernel<<<(B_ * HW + 127) / 128, 128>>>(x, norm_g);
    qkv_gemm<<<dim3(HW / 64, 3 * HID / 64, B_), 256>>>(w_qkv);
    dwconv_kernel<<<(B_ * 3 * HID * HW + 255) / 256, 256>>>(dw_q, dw_k, dw_v);
    rope_kernel<<<dim3(HW / 32, 3 * HEADS, B_), 256>>>();
    flash_kernel<<<dim3(S_ / 128, HEADS, B_), 128>>>();
    outproj_gemm<<<dim3(HW / 64, C_ / 64, B_), 256>>>(w_out, b_out, out);
}

// round 2
// speedup vs baseline: 2.7742x; 2.7742x over previous
#include <cuda_runtime.h>

#define B_   4
#define C_   256
#define H_   48
#define W_   48
#define HW   2304
#define HEADS 8
#define DH   64
#define HID  512
#define S_   2304
#define EPSF 1e-5f
#define SCALEF 0.125f
#define LOG2E 1.4426950408889634f
#define LOG2_10000 13.287712379549449f

// ---------------- scratch ----------------
__device__ float  g_xn  [B_*C_*HW];
__device__ float  g_qkv [B_*3*HID*HW];
__device__ float  g_conv[B_*3*HID*HW];
__device__ float4 g_qf4 [32*144*8*32];   // [bh][r16grp 144][ks 8][lane 32] -> 4 A-frag elems (tf32 bits)
__device__ float4 g_kf4 [32*36*8*4*32];  // [bh][tile 36][nb 8][ksp 4][lane 32] -> B frags for 2 k-steps
__device__ float4 g_vf4 [32*36*8*4*32];  // [bh][tile 36][nb2 8][kp 4][lane 32] -> B frags for 2 k-steps
__device__ float  g_o   [B_*HEADS*S_*DH];

__device__ __forceinline__ unsigned f2tf(float f) {
    unsigned u;
    asm("cvt.rna.tf32.f32 %0, %1;" : "=r"(u) : "f"(f));
    return u;
}

__device__ __forceinline__ void mma8(float* c, const unsigned* a, unsigned b0, unsigned b1) {
    asm("mma.sync.aligned.m16n8k8.row.col.f32.tf32.tf32.f32 "
        "{%0,%1,%2,%3},{%4,%5,%6,%7},{%8,%9},{%0,%1,%2,%3};"
        : "+f"(c[0]), "+f"(c[1]), "+f"(c[2]), "+f"(c[3])
        : "r"(a[0]), "r"(a[1]), "r"(a[2]), "r"(a[3]), "r"(b0), "r"(b1));
}

// ---------------- 1) layernorm over channel dim ----------------
__global__ void ln_kernel(const float* __restrict__ x, const float* __restrict__ g) {
    int idx = blockIdx.x * blockDim.x + threadIdx.x;
    if (idx >= B_ * HW) return;
    int b = idx / HW, hw = idx - b * HW;
    const float* xp = x + (size_t)b * C_ * HW + hw;
    float s0 = 0.f, s1 = 0.f, s2 = 0.f, s3 = 0.f;
    float q0 = 0.f, q1 = 0.f, q2 = 0.f, q3 = 0.f;
    #pragma unroll 4
    for (int c = 0; c < C_; c += 4) {
        float v0 = xp[(size_t)(c + 0) * HW];
        float v1 = xp[(size_t)(c + 1) * HW];
        float v2 = xp[(size_t)(c + 2) * HW];
        float v3 = xp[(size_t)(c + 3) * HW];
        s0 += v0; q0 += v0 * v0;
        s1 += v1; q1 += v1 * v1;
        s2 += v2; q2 += v2 * v2;
        s3 += v3; q3 += v3 * v3;
    }
    float mean = (s0 + s1 + s2 + s3) * (1.f / C_);
    float var  = (q0 + q1 + q2 + q3) * (1.f / C_) - mean * mean;
    float r = rsqrtf(var + EPSF);
    float* op = g_xn + (size_t)b * C_ * HW + hw;
    #pragma unroll 4
    for (int c = 0; c < C_; c++)
        op[(size_t)c * HW] = (xp[(size_t)c * HW] - mean) * r * g[c];
}

// ---------------- 2) QKV gemm ----------------
__global__ void __launch_bounds__(256) qkv_gemm(const float* __restrict__ Wq) {
    __shared__ float As[16][64];
    __shared__ float Bs[16][64];
    const int b  = blockIdx.z;
    const int m0 = blockIdx.y * 64, n0 = blockIdx.x * 64;
    const int tx = threadIdx.x & 15, ty = threadIdx.x >> 4;
    const float* Bmat = g_xn + (size_t)b * C_ * HW;
    float acc[4][4] = {};
    const int am = threadIdx.x >> 2, ak = (threadIdx.x & 3) << 2;
    const int bk = threadIdx.x >> 4, bn = (threadIdx.x & 15) << 2;
    for (int k0 = 0; k0 < C_; k0 += 16) {
        float4 av = *(const float4*)(Wq + (size_t)(m0 + am) * C_ + k0 + ak);
        As[ak + 0][am] = av.x; As[ak + 1][am] = av.y;
        As[ak + 2][am] = av.z; As[ak + 3][am] = av.w;
        *(float4*)(&Bs[bk][bn]) =
            *(const float4*)(Bmat + (size_t)(k0 + bk) * HW + n0 + bn);
        __syncthreads();
        #pragma unroll
        for (int kk = 0; kk < 16; kk++) {
            float4 a0 = *(float4*)(&As[kk][ty << 2]);
            float4 b0 = *(float4*)(&Bs[kk][tx << 2]);
            acc[0][0] += a0.x * b0.x; acc[0][1] += a0.x * b0.y; acc[0][2] += a0.x * b0.z; acc[0][3] += a0.x * b0.w;
            acc[1][0] += a0.y * b0.x; acc[1][1] += a0.y * b0.y; acc[1][2] += a0.y * b0.z; acc[1][3] += a0.y * b0.w;
            acc[2][0] += a0.z * b0.x; acc[2][1] += a0.z * b0.y; acc[2][2] += a0.z * b0.z; acc[2][3] += a0.z * b0.w;
            acc[3][0] += a0.w * b0.x; acc[3][1] += a0.w * b0.y; acc[3][2] += a0.w * b0.z; acc[3][3] += a0.w * b0.w;
        }
        __syncthreads();
    }
    float* Cm = g_qkv + (size_t)b * 3 * HID * HW;
    #pragma unroll
    for (int i = 0; i < 4; i++) {
        float4 r;
        r.x = acc[i][0]; r.y = acc[i][1]; r.z = acc[i][2]; r.w = acc[i][3];
        *(float4*)(Cm + (size_t)(m0 + (ty << 2) + i) * HW + n0 + (tx << 2)) = r;
    }
}

// ---------------- 3) depthwise 3x3 conv ----------------
__global__ void dwconv_kernel(const float* __restrict__ wq,
                              const float* __restrict__ wk,
                              const float* __restrict__ wv) {
    int idx = blockIdx.x * blockDim.x + threadIdx.x;
    if (idx >= B_ * 3 * HID * HW) return;
    int xx = idx % W_;
    int yy = (idx / W_) % H_;
    int c  = (idx / HW) % (3 * HID);
    const float* wsel = (c < HID) ? wq : (c < 2 * HID) ? wk : wv;
    const float* w = wsel + (size_t)(c & (HID - 1)) * 9;
    float w9[9];
    #pragma unroll
    for (int i = 0; i < 9; i++) w9[i] = __ldg(&w[i]);
    const float* ip = g_qkv + (size_t)(idx / HW) * HW;
    float acc = 0.f;
    #pragma unroll
    for (int dy = -1; dy <= 1; dy++) {
        int y = yy + dy;
        if (y < 0 || y >= H_) continue;
        #pragma unroll
        for (int dx = -1; dx <= 1; dx++) {
            int x = xx + dx;
            if (x < 0 || x >= W_) continue;
            acc += ip[y * W_ + x] * w9[(dy + 1) * 3 + (dx + 1)];
        }
    }
    g_conv[idx] = acc;
}

// ---------------- 4) rope + tf32 round + mma-fragment packing ----------------
__global__ void __launch_bounds__(256) rope_kernel() {
    __shared__ float tile[64][33];
    const int b   = blockIdx.z;
    const int sel = blockIdx.y >> 3;      // 0:q 1:k 2:v
    const int h   = blockIdx.y & 7;
    const int bh  = b * HEADS + h;
    const int i0  = blockIdx.x * 32;
    const int cbase = sel * HID + h * DH;
    const int t  = threadIdx.x;
    const int ii = t & 31, dr = t >> 5;
    const float* src = g_conv + ((size_t)(b * 3 * HID + cbase)) * HW + i0;
    #pragma unroll
    for (int r = 0; r < 8; r++) {
        int dd = dr + r * 8;
        tile[dd][ii] = src[(size_t)dd * HW + ii];
    }
    __syncthreads();
    #pragma unroll
    for (int p = 0; p < 8; p++) {
        int e  = p * 256 + t;
        int dd = e & 63, jj = e >> 6;
        int s  = i0 + jj;                 // global seq index
        float t1 = tile[dd][jj];
        float val;
        if (sel == 2) {
            val = t1;
        } else {
            int j = dd & 31;
            float invf = exp2f(-((float)(2 * j) * (1.0f / 64.0f)) * LOG2_10000);
            float a = (float)s * invf;
            float sa, ca;
            sincosf(a, &sa, &ca);
            float t2 = tile[dd ^ 32][jj];
            val = (dd < 32) ? (t1 * ca - t2 * sa) : (t1 * ca + t2 * sa);
            if (sel == 0) val *= SCALEF * LOG2E;
        }
        unsigned ub = f2tf(val);
        float fv = __uint_as_float(ub);
        if (sel == 0) {
            // A-fragment layout for Q
            int r16 = s >> 4, g = s & 7, half = (s >> 3) & 1;
            int ks = dd >> 3, q2 = dd & 3, dh2 = (dd >> 2) & 1;
            int lane = 4 * g + q2, j4 = half + 2 * dh2;
            ((float*)g_qf4)[(size_t)((((bh * 144 + r16) * 8 + ks) * 32 + lane)) * 4 + j4] = fv;
        } else if (sel == 1) {
            // B-fragment layout for K (QK^T)
            int tl = s >> 6, nb = (s >> 3) & 7, g = s & 7;
            int ks = dd >> 3, q2 = dd & 3, bb = (dd >> 2) & 1;
            int lane = 4 * g + q2, j4 = (ks & 1) * 2 + bb;
            ((float*)g_kf4)[(size_t)(((((bh * 36 + tl) * 8 + nb) * 4 + (ks >> 1)) * 32 + lane)) * 4 + j4] = fv;
        } else {
            // B-fragment layout for V (P*V): k-dim = seq, n-dim = head dim
            int tl = s >> 6, ks2 = (s >> 3) & 7, q2 = s & 3, bb = (s >> 2) & 1;
            int nb2 = dd >> 3, g = dd & 7;
            int lane = 4 * g + q2, j4 = (ks2 & 1) * 2 + bb;
            ((float*)g_vf4)[(size_t)(((((bh * 36 + tl) * 8 + nb2) * 4 + (ks2 >> 1)) * 32 + lane)) * 4 + j4] = fv;
        }
    }
}

// ---------------- 5) flash attention: tf32 tensor-core, online softmax ----------------
__global__ void __launch_bounds__(128) flash_tc() {
    __shared__ float4 Ks[1024];   // 16 KB: one 64-key K tile in frag layout
    __shared__ float4 Vs[1024];   // 16 KB
    const int bh   = blockIdx.z * HEADS + blockIdx.y;
    const int w    = threadIdx.x >> 5, lane = threadIdx.x & 31;
    const int q    = lane & 3, g = lane >> 2;
    const int grp0 = blockIdx.x * 8 + w * 2;   // first 16-row group for this warp

    // Q fragments (already tf32, scaled): 64 regs
    unsigned qa[2][8][4];
    {
        const float4* qf = g_qf4 + (size_t)bh * 144 * 8 * 32;
        #pragma unroll
        for (int h2 = 0; h2 < 2; h2++)
            #pragma unroll
            for (int ks = 0; ks < 8; ks++) {
                float4 v = qf[(size_t)((grp0 + h2) * 8 + ks) * 32 + lane];
                qa[h2][ks][0] = __float_as_uint(v.x);
                qa[h2][ks][1] = __float_as_uint(v.y);
                qa[h2][ks][2] = __float_as_uint(v.z);
                qa[h2][ks][3] = __float_as_uint(v.w);
            }
    }

    float o[2][8][4] = {};
    float m0[2] = {-1e30f, -1e30f}, m1[2] = {-1e30f, -1e30f};
    float l0[2] = {0.f, 0.f}, l1[2] = {0.f, 0.f};

    const float4* kg = g_kf4 + (size_t)bh * 36 * 1024;
    const float4* vg = g_vf4 + (size_t)bh * 36 * 1024;

    for (int t = 0; t < 36; t++) {
        __syncthreads();
        #pragma unroll
        for (int i = 0; i < 8; i++) {
            Ks[threadIdx.x + 128 * i] = kg[(size_t)t * 1024 + threadIdx.x + 128 * i];
            Vs[threadIdx.x + 128 * i] = vg[(size_t)t * 1024 + threadIdx.x + 128 * i];
        }
        __syncthreads();

        // ---- S = Q K^T (tile 32 x 64 per warp) ----
        float s[2][8][4] = {};
        #pragma unroll
        for (int nb = 0; nb < 8; nb++) {
            #pragma unroll
            for (int kp = 0; kp < 4; kp++) {
                float4 bb = Ks[(nb * 4 + kp) * 32 + lane];
                unsigned b0 = __float_as_uint(bb.x), b1 = __float_as_uint(bb.y);
                unsigned b2 = __float_as_uint(bb.z), b3 = __float_as_uint(bb.w);
                mma8(s[0][nb], qa[0][2 * kp + 0], b0, b1);
                mma8(s[0][nb], qa[0][2 * kp + 1], b2, b3);
                mma8(s[1][nb], qa[1][2 * kp + 0], b0, b1);
                mma8(s[1][nb], qa[1][2 * kp + 1], b2, b3);
            }
        }

        // ---- online softmax (base-2; LOG2E folded into Q) ----
        #pragma unroll
        for (int h2 = 0; h2 < 2; h2++) {
            float mx0 = -1e30f, mx1 = -1e30f;
            #pragma unroll
            for (int nb = 0; nb < 8; nb++) {
                mx0 = fmaxf(mx0, fmaxf(s[h2][nb][0], s[h2][nb][1]));
                mx1 = fmaxf(mx1, fmaxf(s[h2][nb][2], s[h2][nb][3]));
            }
            mx0 = fmaxf(mx0, __shfl_xor_sync(0xffffffffu, mx0, 1));
            mx0 = fmaxf(mx0, __shfl_xor_sync(0xffffffffu, mx0, 2));
            mx1 = fmaxf(mx1, __shfl_xor_sync(0xffffffffu, mx1, 1));
            mx1 = fmaxf(mx1, __shfl_xor_sync(0xffffffffu, mx1, 2));
            float nm0 = fmaxf(m0[h2], mx0), nm1 = fmaxf(m1[h2], mx1);
            float cf0 = exp2f(m0[h2] - nm0), cf1 = exp2f(m1[h2] - nm1);
            m0[h2] = nm0; m1[h2] = nm1;
            l0[h2] *= cf0; l1[h2] *= cf1;
            #pragma unroll
            for (int nb = 0; nb < 8; nb++) {
                o[h2][nb][0] *= cf0; o[h2][nb][1] *= cf0;
                o[h2][nb][2] *= cf1; o[h2][nb][3] *= cf1;
            }
            #pragma unroll
            for (int nb = 0; nb < 8; nb++) {
                float p0 = exp2f(s[h2][nb][0] - nm0);
                float p1 = exp2f(s[h2][nb][1] - nm0);
                float p2 = exp2f(s[h2][nb][2] - nm1);
                float p3 = exp2f(s[h2][nb][3] - nm1);
                l0[h2] += p0 + p1; l1[h2] += p2 + p3;
                s[h2][nb][0] = p0; s[h2][nb][1] = p1;
                s[h2][nb][2] = p2; s[h2][nb][3] = p3;
            }
        }

        // ---- O += P V ----
        const int src1 = (lane & ~3) | (q >> 1);
        const int src2 = src1 + 2;
        const bool odd = (q & 1);
        #pragma unroll
        for (int kp = 0; kp < 4; kp++) {
            unsigned a[2][2][4];
            #pragma unroll
            for (int h2 = 0; h2 < 2; h2++) {
                #pragma unroll
                for (int e = 0; e < 2; e++) {
                    int ks2 = 2 * kp + e;
                    float c0 = s[h2][ks2][0], c1 = s[h2][ks2][1];
                    float c2 = s[h2][ks2][2], c3 = s[h2][ks2][3];
                    float t0 = __shfl_sync(0xffffffffu, c0, src1);
                    float t1 = __shfl_sync(0xffffffffu, c1, src1);
                    float u0 = __shfl_sync(0xffffffffu, c2, src1);
                    float u1 = __shfl_sync(0xffffffffu, c3, src1);
                    float t2 = __shfl_sync(0xffffffffu, c0, src2);
                    float t3 = __shfl_sync(0xffffffffu, c1, src2);
                    float u2 = __shfl_sync(0xffffffffu, c2, src2);
                    float u3 = __shfl_sync(0xffffffffu, c3, src2);
                    a[h2][e][0] = f2tf(odd ? t1 : t0);
                    a[h2][e][1] = f2tf(odd ? u1 : u0);
                    a[h2][e][2] = f2tf(odd ? t3 : t2);
                    a[h2][e][3] = f2tf(odd ? u3 : u2);
                }
            }
            #pragma unroll
            for (int nb2 = 0; nb2 < 8; nb2++) {
                float4 bb = Vs[(nb2 * 4 + kp) * 32 + lane];
                unsigned b0 = __float_as_uint(bb.x), b1 = __float_as_uint(bb.y);
                unsigned b2 = __float_as_uint(bb.z), b3 = __float_as_uint(bb.w);
                mma8(o[0][nb2], a[0][0], b0, b1);
                mma8(o[0][nb2], a[0][1], b2, b3);
                mma8(o[1][nb2], a[1][0], b0, b1);
                mma8(o[1][nb2], a[1][1], b2, b3);
            }
        }
    }

    // ---- epilogue: normalize, write ----
    #pragma unroll
    for (int h2 = 0; h2 < 2; h2++) {
        float L0 = l0[h2];
        L0 += __shfl_xor_sync(0xffffffffu, L0, 1);
        L0 += __shfl_xor_sync(0xffffffffu, L0, 2);
        float L1 = l1[h2];
        L1 += __shfl_xor_sync(0xffffffffu, L1, 1);
        L1 += __shfl_xor_sync(0xffffffffu, L1, 2);
        float inv0 = 1.f / L0, inv1 = 1.f / L1;
        int r0 = (grp0 + h2) * 16 + g;
        float* base0 = g_o + ((size_t)bh * S_ + r0) * DH;
        float* base1 = base0 + 8 * DH;
        #pragma unroll
        for (int nb2 = 0; nb2 < 8; nb2++) {
            int col = nb2 * 8 + 2 * q;
            *(float2*)(base0 + col) = make_float2(o[h2][nb2][0] * inv0, o[h2][nb2][1] * inv0);
            *(float2*)(base1 + col) = make_float2(o[h2][nb2][2] * inv1, o[h2][nb2][3] * inv1);
        }
    }
}

// ---------------- 6) output projection + bias ----------------
__global__ void __launch_bounds__(256) outproj_gemm(const float* __restrict__ Wo,
                                                    const float* __restrict__ bias,
                                                    float* __restrict__ out) {
    __shared__ float As[16][64];
    __shared__ float Bs[16][68];
    const int b  = blockIdx.z;
    const int m0 = blockIdx.y * 64, n0 = blockIdx.x * 64;
    const int tx = threadIdx.x & 15, ty = threadIdx.x >> 4;
    float acc[4][4] = {};
    const int am = threadIdx.x >> 2, ak = (threadIdx.x & 3) << 2;
    const int kl = threadIdx.x & 15, nn0 = threadIdx.x >> 4;
    const float* Ob = g_o + (size_t)b * HEADS * S_ * DH;
    for (int k0 = 0; k0 < HID; k0 += 16) {
        float4 av = *(const float4*)(Wo + (size_t)(m0 + am) * HID + k0 + ak);
        As[ak + 0][am] = av.x; As[ak + 1][am] = av.y;
        As[ak + 2][am] = av.z; As[ak + 3][am] = av.w;
        int c = k0 + kl;
        const float* src = Ob + (size_t)(c >> 6) * S_ * DH + (c & 63);
        #pragma unroll
        for (int p = 0; p < 4; p++) {
            int nn = nn0 + p * 16;
            Bs[kl][nn] = src[(size_t)(n0 + nn) * DH];
        }
        __syncthreads();
        #pragma unroll
        for (int kk = 0; kk < 16; kk++) {
            float4 a0 = *(float4*)(&As[kk][ty << 2]);
            float4 b0 = *(float4*)(&Bs[kk][tx << 2]);
            acc[0][0] += a0.x * b0.x; acc[0][1] += a0.x * b0.y; acc[0][2] += a0.x * b0.z; acc[0][3] += a0.x * b0.w;
            acc[1][0] += a0.y * b0.x; acc[1][1] += a0.y * b0.y; acc[1][2] += a0.y * b0.z; acc[1][3] += a0.y * b0.w;
            acc[2][0] += a0.z * b0.x; acc[2][1] += a0.z * b0.y; acc[2][2] += a0.z * b0.z; acc[2][3] += a0.z * b0.w;
            acc[3][0] += a0.w * b0.x; acc[3][1] += a0.w * b0.y; acc[3][2] += a0.w * b0.z; acc[3][3] += a0.w * b0.w;
        }
        __syncthreads();
    }
    float* Cm = out + (size_t)b * C_ * HW;
    #pragma unroll
    for (int i = 0; i < 4; i++) {
        float bb = bias[m0 + (ty << 2) + i];
        float4 r;
        r.x = acc[i][0] + bb; r.y = acc[i][1] + bb;
        r.z = acc[i][2] + bb; r.w = acc[i][3] + bb;
        *(float4*)(Cm + (size_t)(m0 + (ty << 2) + i) * HW + n0 + (tx << 2)) = r;
    }
}

// ---------------- launcher ----------------
extern "C" void kernel_launch(void* const* d_in, const int* in_sizes, int n_in,
                              void* d_out, int out_size) {
    const float* x      = (const float*)d_in[0];
    const float* norm_g = (const float*)d_in[1];
    const float* w_qkv  = (const float*)d_in[2];
    const float* dw_q   = (const float*)d_in[3];
    const float* dw_k   = (const float*)d_in[4];
    const float* dw_v   = (const float*)d_in[5];
    const float* w_out  = (const float*)d_in[6];
    const float* b_out  = (const float*)d_in[7];
    float* out = (float*)d_out;

    ln_kernel<<<(B_ * HW + 127) / 128, 128>>>(x, norm_g);
    qkv_gemm<<<dim3(HW / 64, 3 * HID / 64, B_), 256>>>(w_qkv);
    dwconv_kernel<<<(B_ * 3 * HID * HW + 255) / 256, 256>>>(dw_q, dw_k, dw_v);
    rope_kernel<<<dim3(HW / 32, 3 * HEADS, B_), 256>>>();
    flash_tc<<<dim3(S_ / 128, HEADS, B_), 128>>>();
    outproj_gemm<<<dim3(HW / 64, C_ / 64, B_), 256>>>(w_out, b_out, out);
}

// round 3
// speedup vs baseline: 3.7301x; 1.3446x over previous
#include <cuda_runtime.h>

#define B_   4
#define C_   256
#define H_   48
#define W_   48
#define HW   2304
#define HEADS 8
#define DH   64
#define HID  512
#define S_   2304
#define EPSF 1e-5f
#define SCALEF 0.125f
#define LOG2E 1.4426950408889634f
#define LOG2_10000 13.287712379549449f

// ---------------- scratch ----------------
__device__ float  g_xn  [B_*C_*HW];
__device__ float  g_qkv [B_*3*HID*HW];
__device__ float  g_conv[B_*3*HID*HW];
__device__ float4 g_qf4 [32*144*8*32];
__device__ float4 g_kf4 [32*36*8*4*32];
__device__ float4 g_vf4 [32*36*8*4*32];
__device__ float  g_oT  [B_*HID*HW];     // attention out, channel-major [b][c][s]

__device__ __forceinline__ unsigned f2tf(float f) {
    unsigned u;
    asm("cvt.rna.tf32.f32 %0, %1;" : "=r"(u) : "f"(f));
    return u;
}
__device__ __forceinline__ float f2tff(float f) {
    return __uint_as_float(f2tf(f));
}

__device__ __forceinline__ void mma8(float* c, const unsigned* a, unsigned b0, unsigned b1) {
    asm("mma.sync.aligned.m16n8k8.row.col.f32.tf32.tf32.f32 "
        "{%0,%1,%2,%3},{%4,%5,%6,%7},{%8,%9},{%0,%1,%2,%3};"
        : "+f"(c[0]), "+f"(c[1]), "+f"(c[2]), "+f"(c[3])
        : "r"(a[0]), "r"(a[1]), "r"(a[2]), "r"(a[3]), "r"(b0), "r"(b1));
}

// ---------------- 1) layernorm over channel dim ----------------
__global__ void ln_kernel(const float* __restrict__ x, const float* __restrict__ g) {
    int idx = blockIdx.x * blockDim.x + threadIdx.x;
    if (idx >= B_ * HW) return;
    int b = idx / HW, hw = idx - b * HW;
    const float* xp = x + (size_t)b * C_ * HW + hw;
    float s0 = 0.f, s1 = 0.f, s2 = 0.f, s3 = 0.f;
    float q0 = 0.f, q1 = 0.f, q2 = 0.f, q3 = 0.f;
    #pragma unroll 4
    for (int c = 0; c < C_; c += 4) {
        float v0 = xp[(size_t)(c + 0) * HW];
        float v1 = xp[(size_t)(c + 1) * HW];
        float v2 = xp[(size_t)(c + 2) * HW];
        float v3 = xp[(size_t)(c + 3) * HW];
        s0 += v0; q0 += v0 * v0;
        s1 += v1; q1 += v1 * v1;
        s2 += v2; q2 += v2 * v2;
        s3 += v3; q3 += v3 * v3;
    }
    float mean = (s0 + s1 + s2 + s3) * (1.f / C_);
    float var  = (q0 + q1 + q2 + q3) * (1.f / C_) - mean * mean;
    float r = rsqrtf(var + EPSF);
    float* op = g_xn + (size_t)b * C_ * HW + hw;
    #pragma unroll 4
    for (int c = 0; c < C_; c++)
        op[(size_t)c * HW] = (xp[(size_t)c * HW] - mean) * r * g[c];
}

// ---------------- 2/6) tf32 tensor-core GEMM: C[b][m][n] = A[m][k] * B[b][k][n] ----------------
// CTA tile 128(M) x 128(N); 8 warps as 4(m) x 2(n); warp tile 32x64.
template<int KD, bool BIAS>
__global__ void __launch_bounds__(256) gemm_tc(const float* __restrict__ A,
                                               const float* __restrict__ Bmat,
                                               float* __restrict__ Cmat,
                                               const float* __restrict__ bias) {
    __shared__ float As[128][20];   // [m][k] padded: conflict-free frag reads
    __shared__ float Bs[16][136];   // [k][n] padded (136 mod 32 == 8)
    const int b  = blockIdx.z;
    const int n0 = blockIdx.x * 128, m0 = blockIdx.y * 128;
    const int tid = threadIdx.x;
    const int w = tid >> 5, lane = tid & 31;
    const int wm = w >> 1, wn = w & 1;
    const int g = lane >> 2, q = lane & 3;
    const float* Bb = Bmat + (size_t)b * KD * HW;
    float c[2][8][4] = {};
    const int ar = tid >> 2, ac = tid & 3;   // A: rows ar, ar+64; float4 col ac
    const int br = tid >> 4, bc = tid & 15;  // B: row br; float4 cols bc, bc+16

    for (int k0 = 0; k0 < KD; k0 += 16) {
        #pragma unroll
        for (int i = 0; i < 2; i++) {
            int m = ar + 64 * i;
            float4 v = *(const float4*)(A + (size_t)(m0 + m) * KD + k0 + 4 * ac);
            float* d = &As[m][4 * ac];
            d[0] = f2tff(v.x); d[1] = f2tff(v.y); d[2] = f2tff(v.z); d[3] = f2tff(v.w);
        }
        #pragma unroll
        for (int i = 0; i < 2; i++) {
            int n = 4 * (bc + 16 * i);
            float4 v = *(const float4*)(Bb + (size_t)(k0 + br) * HW + n0 + n);
            float* d = &Bs[br][n];
            d[0] = f2tff(v.x); d[1] = f2tff(v.y); d[2] = f2tff(v.z); d[3] = f2tff(v.w);
        }
        __syncthreads();
        #pragma unroll
        for (int h8 = 0; h8 < 2; h8++) {
            unsigned a[2][4];
            #pragma unroll
            for (int i = 0; i < 2; i++) {
                int m = wm * 32 + i * 16;
                a[i][0] = __float_as_uint(As[m + g    ][8 * h8 + q]);
                a[i][1] = __float_as_uint(As[m + g + 8][8 * h8 + q]);
                a[i][2] = __float_as_uint(As[m + g    ][8 * h8 + q + 4]);
                a[i][3] = __float_as_uint(As[m + g + 8][8 * h8 + q + 4]);
            }
            #pragma unroll
            for (int nb = 0; nb < 8; nb++) {
                int n = wn * 64 + nb * 8 + g;
                unsigned b0 = __float_as_uint(Bs[8 * h8 + q    ][n]);
                unsigned b1 = __float_as_uint(Bs[8 * h8 + q + 4][n]);
                mma8(c[0][nb], a[0], b0, b1);
                mma8(c[1][nb], a[1], b0, b1);
            }
        }
        __syncthreads();
    }

    float* Cb = Cmat + (size_t)b * (BIAS ? C_ : 3 * HID) * HW;
    #pragma unroll
    for (int i = 0; i < 2; i++) {
        int m = m0 + wm * 32 + i * 16 + g;
        float bb0 = BIAS ? bias[m] : 0.f;
        float bb8 = BIAS ? bias[m + 8] : 0.f;
        #pragma unroll
        for (int nb = 0; nb < 8; nb++) {
            int n = n0 + wn * 64 + nb * 8 + 2 * q;
            *(float2*)(Cb + (size_t)m * HW + n) =
                make_float2(c[i][nb][0] + bb0, c[i][nb][1] + bb0);
            *(float2*)(Cb + (size_t)(m + 8) * HW + n) =
                make_float2(c[i][nb][2] + bb8, c[i][nb][3] + bb8);
        }
    }
}

// ---------------- 3) depthwise 3x3 conv ----------------
__global__ void dwconv_kernel(const float* __restrict__ wq,
                              const float* __restrict__ wk,
                              const float* __restrict__ wv) {
    int idx = blockIdx.x * blockDim.x + threadIdx.x;
    if (idx >= B_ * 3 * HID * HW) return;
    int xx = idx % W_;
    int yy = (idx / W_) % H_;
    int c  = (idx / HW) % (3 * HID);
    const float* wsel = (c < HID) ? wq : (c < 2 * HID) ? wk : wv;
    const float* w = wsel + (size_t)(c & (HID - 1)) * 9;
    float w9[9];
    #pragma unroll
    for (int i = 0; i < 9; i++) w9[i] = __ldg(&w[i]);
    const float* ip = g_qkv + (size_t)(idx / HW) * HW;
    float acc = 0.f;
    #pragma unroll
    for (int dy = -1; dy <= 1; dy++) {
        int y = yy + dy;
        if (y < 0 || y >= H_) continue;
        #pragma unroll
        for (int dx = -1; dx <= 1; dx++) {
            int x = xx + dx;
            if (x < 0 || x >= W_) continue;
            acc += ip[y * W_ + x] * w9[(dy + 1) * 3 + (dx + 1)];
        }
    }
    g_conv[idx] = acc;
}

// ---------------- 4) rope + tf32 round + mma-fragment packing ----------------
__global__ void __launch_bounds__(256) rope_kernel() {
    __shared__ float tile[64][33];
    const int b   = blockIdx.z;
    const int sel = blockIdx.y >> 3;
    const int h   = blockIdx.y & 7;
    const int bh  = b * HEADS + h;
    const int i0  = blockIdx.x * 32;
    const int cbase = sel * HID + h * DH;
    const int t  = threadIdx.x;
    const int ii = t & 31, dr = t >> 5;
    const float* src = g_conv + ((size_t)(b * 3 * HID + cbase)) * HW + i0;
    #pragma unroll
    for (int r = 0; r < 8; r++) {
        int dd = dr + r * 8;
        tile[dd][ii] = src[(size_t)dd * HW + ii];
    }
    __syncthreads();
    #pragma unroll
    for (int p = 0; p < 8; p++) {
        int e  = p * 256 + t;
        int dd = e & 63, jj = e >> 6;
        int s  = i0 + jj;
        float t1 = tile[dd][jj];
        float val;
        if (sel == 2) {
            val = t1;
        } else {
            int j = dd & 31;
            float invf = exp2f(-((float)(2 * j) * (1.0f / 64.0f)) * LOG2_10000);
            float a = (float)s * invf;
            float sa, ca;
            sincosf(a, &sa, &ca);
            float t2 = tile[dd ^ 32][jj];
            val = (dd < 32) ? (t1 * ca - t2 * sa) : (t1 * ca + t2 * sa);
            if (sel == 0) val *= SCALEF * LOG2E;
        }
        float fv = f2tff(val);
        if (sel == 0) {
            int r16 = s >> 4, g = s & 7, half = (s >> 3) & 1;
            int ks = dd >> 3, q2 = dd & 3, dh2 = (dd >> 2) & 1;
            int lane = 4 * g + q2, j4 = half + 2 * dh2;
            ((float*)g_qf4)[(size_t)((((bh * 144 + r16) * 8 + ks) * 32 + lane)) * 4 + j4] = fv;
        } else if (sel == 1) {
            int tl = s >> 6, nb = (s >> 3) & 7, g = s & 7;
            int ks = dd >> 3, q2 = dd & 3, bb = (dd >> 2) & 1;
            int lane = 4 * g + q2, j4 = (ks & 1) * 2 + bb;
            ((float*)g_kf4)[(size_t)(((((bh * 36 + tl) * 8 + nb) * 4 + (ks >> 1)) * 32 + lane)) * 4 + j4] = fv;
        } else {
            int tl = s >> 6, ks2 = (s >> 3) & 7, q2 = s & 3, bb = (s >> 2) & 1;
            int nb2 = dd >> 3, g = dd & 7;
            int lane = 4 * g + q2, j4 = (ks2 & 1) * 2 + bb;
            ((float*)g_vf4)[(size_t)(((((bh * 36 + tl) * 8 + nb2) * 4 + (ks2 >> 1)) * 32 + lane)) * 4 + j4] = fv;
        }
    }
}

// ---------------- 5) flash attention: tf32 tensor-core, online softmax ----------------
__global__ void __launch_bounds__(128) flash_tc() {
    __shared__ float4 Ks[1024];
    __shared__ float4 Vs[1024];
    const int b = blockIdx.z, h = blockIdx.y;
    const int bh = b * HEADS + h;
    const int w    = threadIdx.x >> 5, lane = threadIdx.x & 31;
    const int q    = lane & 3, g = lane >> 2;
    const int grp0 = blockIdx.x * 8 + w * 2;

    unsigned qa[2][8][4];
    {
        const float4* qf = g_qf4 + (size_t)bh * 144 * 8 * 32;
        #pragma unroll
        for (int h2 = 0; h2 < 2; h2++)
            #pragma unroll
            for (int ks = 0; ks < 8; ks++) {
                float4 v = qf[(size_t)((grp0 + h2) * 8 + ks) * 32 + lane];
                qa[h2][ks][0] = __float_as_uint(v.x);
                qa[h2][ks][1] = __float_as_uint(v.y);
                qa[h2][ks][2] = __float_as_uint(v.z);
                qa[h2][ks][3] = __float_as_uint(v.w);
            }
    }

    float o[2][8][4] = {};
    float m0[2] = {-1e30f, -1e30f}, m1[2] = {-1e30f, -1e30f};
    float l0[2] = {0.f, 0.f}, l1[2] = {0.f, 0.f};

    const float4* kg = g_kf4 + (size_t)bh * 36 * 1024;
    const float4* vg = g_vf4 + (size_t)bh * 36 * 1024;

    for (int t = 0; t < 36; t++) {
        __syncthreads();
        #pragma unroll
        for (int i = 0; i < 8; i++) {
            Ks[threadIdx.x + 128 * i] = kg[(size_t)t * 1024 + threadIdx.x + 128 * i];
            Vs[threadIdx.x + 128 * i] = vg[(size_t)t * 1024 + threadIdx.x + 128 * i];
        }
        __syncthreads();

        float s[2][8][4] = {};
        #pragma unroll
        for (int nb = 0; nb < 8; nb++) {
            #pragma unroll
            for (int kp = 0; kp < 4; kp++) {
                float4 bb = Ks[(nb * 4 + kp) * 32 + lane];
                unsigned b0 = __float_as_uint(bb.x), b1 = __float_as_uint(bb.y);
                unsigned b2 = __float_as_uint(bb.z), b3 = __float_as_uint(bb.w);
                mma8(s[0][nb], qa[0][2 * kp + 0], b0, b1);
                mma8(s[0][nb], qa[0][2 * kp + 1], b2, b3);
                mma8(s[1][nb], qa[1][2 * kp + 0], b0, b1);
                mma8(s[1][nb], qa[1][2 * kp + 1], b2, b3);
            }
        }

        #pragma unroll
        for (int h2 = 0; h2 < 2; h2++) {
            float mx0 = -1e30f, mx1 = -1e30f;
            #pragma unroll
            for (int nb = 0; nb < 8; nb++) {
                mx0 = fmaxf(mx0, fmaxf(s[h2][nb][0], s[h2][nb][1]));
                mx1 = fmaxf(mx1, fmaxf(s[h2][nb][2], s[h2][nb][3]));
            }
            mx0 = fmaxf(mx0, __shfl_xor_sync(0xffffffffu, mx0, 1));
            mx0 = fmaxf(mx0, __shfl_xor_sync(0xffffffffu, mx0, 2));
            mx1 = fmaxf(mx1, __shfl_xor_sync(0xffffffffu, mx1, 1));
            mx1 = fmaxf(mx1, __shfl_xor_sync(0xffffffffu, mx1, 2));
            float nm0 = fmaxf(m0[h2], mx0), nm1 = fmaxf(m1[h2], mx1);
            float cf0 = exp2f(m0[h2] - nm0), cf1 = exp2f(m1[h2] - nm1);
            m0[h2] = nm0; m1[h2] = nm1;
            l0[h2] *= cf0; l1[h2] *= cf1;
            #pragma unroll
            for (int nb = 0; nb < 8; nb++) {
                o[h2][nb][0] *= cf0; o[h2][nb][1] *= cf0;
                o[h2][nb][2] *= cf1; o[h2][nb][3] *= cf1;
            }
            #pragma unroll
            for (int nb = 0; nb < 8; nb++) {
                float p0 = exp2f(s[h2][nb][0] - nm0);
                float p1 = exp2f(s[h2][nb][1] - nm0);
                float p2 = exp2f(s[h2][nb][2] - nm1);
                float p3 = exp2f(s[h2][nb][3] - nm1);
                l0[h2] += p0 + p1; l1[h2] += p2 + p3;
                s[h2][nb][0] = p0; s[h2][nb][1] = p1;
                s[h2][nb][2] = p2; s[h2][nb][3] = p3;
            }
        }

        const int src1 = (lane & ~3) | (q >> 1);
        const int src2 = src1 + 2;
        const bool odd = (q & 1);
        #pragma unroll
        for (int kp = 0; kp < 4; kp++) {
            unsigned a[2][2][4];
            #pragma unroll
            for (int h2 = 0; h2 < 2; h2++) {
                #pragma unroll
                for (int e = 0; e < 2; e++) {
                    int ks2 = 2 * kp + e;
                    float c0 = s[h2][ks2][0], c1 = s[h2][ks2][1];
                    float c2 = s[h2][ks2][2], c3 = s[h2][ks2][3];
                    float t0 = __shfl_sync(0xffffffffu, c0, src1);
                    float t1 = __shfl_sync(0xffffffffu, c1, src1);
                    float u0 = __shfl_sync(0xffffffffu, c2, src1);
                    float u1 = __shfl_sync(0xffffffffu, c3, src1);
                    float t2 = __shfl_sync(0xffffffffu, c0, src2);
                    float t3 = __shfl_sync(0xffffffffu, c1, src2);
                    float u2 = __shfl_sync(0xffffffffu, c2, src2);
                    float u3 = __shfl_sync(0xffffffffu, c3, src2);
                    a[h2][e][0] = f2tf(odd ? t1 : t0);
                    a[h2][e][1] = f2tf(odd ? u1 : u0);
                    a[h2][e][2] = f2tf(odd ? t3 : t2);
                    a[h2][e][3] = f2tf(odd ? u3 : u2);
                }
            }
            #pragma unroll
            for (int nb2 = 0; nb2 < 8; nb2++) {
                float4 bb = Vs[(nb2 * 4 + kp) * 32 + lane];
                unsigned b0 = __float_as_uint(bb.x), b1 = __float_as_uint(bb.y);
                unsigned b2 = __float_as_uint(bb.z), b3 = __float_as_uint(bb.w);
                mma8(o[0][nb2], a[0][0], b0, b1);
                mma8(o[0][nb2], a[0][1], b2, b3);
                mma8(o[1][nb2], a[1][0], b0, b1);
                mma8(o[1][nb2], a[1][1], b2, b3);
            }
        }
    }

    // ---- epilogue: normalize, write channel-major O^T [b][c][s] ----
    #pragma unroll
    for (int h2 = 0; h2 < 2; h2++) {
        float L0 = l0[h2];
        L0 += __shfl_xor_sync(0xffffffffu, L0, 1);
        L0 += __shfl_xor_sync(0xffffffffu, L0, 2);
        float L1 = l1[h2];
        L1 += __shfl_xor_sync(0xffffffffu, L1, 1);
        L1 += __shfl_xor_sync(0xffffffffu, L1, 2);
        float inv0 = 1.f / L0, inv1 = 1.f / L1;
        int r0 = (grp0 + h2) * 16 + g;       // sequence index (rows r0, r0+8)
        float* base = g_oT + ((size_t)b * HID + h * DH) * HW;
        #pragma unroll
        for (int nb2 = 0; nb2 < 8; nb2++) {
            int col = nb2 * 8 + 2 * q;       // head-dim channel
            base[(size_t)(col    ) * HW + r0    ] = o[h2][nb2][0] * inv0;
            base[(size_t)(col + 1) * HW + r0    ] = o[h2][nb2][1] * inv0;
            base[(size_t)(col    ) * HW + r0 + 8] = o[h2][nb2][2] * inv1;
            base[(size_t)(col + 1) * HW + r0 + 8] = o[h2][nb2][3] * inv1;
        }
    }
}

// ---------------- launcher ----------------
extern "C" void kernel_launch(void* const* d_in, const int* in_sizes, int n_in,
                              void* d_out, int out_size) {
    const float* x      = (const float*)d_in[0];
    const float* norm_g = (const float*)d_in[1];
    const float* w_qkv  = (const float*)d_in[2];
    const float* dw_q   = (const float*)d_in[3];
    const float* dw_k   = (const float*)d_in[4];
    const float* dw_v   = (const float*)d_in[5];
    const float* w_out  = (const float*)d_in[6];
    const float* b_out  = (const float*)d_in[7];
    float* out = (float*)d_out;

    float* xn;  cudaGetSymbolAddress((void**)&xn,  g_xn);
    float* qkv; cudaGetSymbolAddress((void**)&qkv, g_qkv);
    float* oT;  cudaGetSymbolAddress((void**)&oT,  g_oT);

    ln_kernel<<<(B_ * HW + 127) / 128, 128>>>(x, norm_g);
    gemm_tc<C_, false><<<dim3(HW / 128, 3 * HID / 128, B_), 256>>>(w_qkv, xn, qkv, nullptr);
    dwconv_kernel<<<(B_ * 3 * HID * HW + 255) / 256, 256>>>(dw_q, dw_k, dw_v);
    rope_kernel<<<dim3(HW / 32, 3 * HEADS, B_), 256>>>();
    flash_tc<<<dim3(S_ / 128, HEADS, B_), 128>>>();
    gemm_tc<HID, true><<<dim3(HW / 128, C_ / 128, B_), 256>>>(w_out, oT, out, b_out);
}

// round 4
// speedup vs baseline: 4.1471x; 1.1118x over previous
#include <cuda_runtime.h>

#define B_   4
#define C_   256
#define H_   48
#define W_   48
#define HW   2304
#define HEADS 8
#define DH   64
#define HID  512
#define S_   2304
#define EPSF 1e-5f
#define SCALEF 0.125f
#define LOG2E 1.4426950408889634f
#define LOG2_10000 13.287712379549449f

// ---------------- scratch ----------------
__device__ float  g_mean[B_*HW];
__device__ float  g_rstd[B_*HW];
__device__ float  g_qkv [B_*3*HID*HW];
__device__ float  g_conv[B_*3*HID*HW];
__device__ float4 g_qf4 [32*144*8*32];
__device__ float4 g_kf4 [32*36*8*4*32];
__device__ float4 g_vf4 [32*36*8*4*32];
__device__ float  g_oT  [B_*HID*HW];     // attention out, channel-major [b][c][s]

__device__ __forceinline__ unsigned f2tf(float f) {
    unsigned u;
    asm("cvt.rna.tf32.f32 %0, %1;" : "=r"(u) : "f"(f));
    return u;
}
__device__ __forceinline__ float f2tff(float f) {
    return __uint_as_float(f2tf(f));
}

__device__ __forceinline__ void mma8(float* c, const unsigned* a, unsigned b0, unsigned b1) {
    asm("mma.sync.aligned.m16n8k8.row.col.f32.tf32.tf32.f32 "
        "{%0,%1,%2,%3},{%4,%5,%6,%7},{%8,%9},{%0,%1,%2,%3};"
        : "+f"(c[0]), "+f"(c[1]), "+f"(c[2]), "+f"(c[3])
        : "r"(a[0]), "r"(a[1]), "r"(a[2]), "r"(a[3]), "r"(b0), "r"(b1));
}

__device__ __forceinline__ unsigned smem_u32(const void* p) {
    return (unsigned)__cvta_generic_to_shared(p);
}
__device__ __forceinline__ void cp16(unsigned dst, const void* src) {
    asm volatile("cp.async.cg.shared.global [%0], [%1], 16;" :: "r"(dst), "l"(src));
}
__device__ __forceinline__ void cp_commit() {
    asm volatile("cp.async.commit_group;");
}
template<int N>
__device__ __forceinline__ void cp_wait() {
    asm volatile("cp.async.wait_group %0;" :: "n"(N));
}

// ---------------- 1) layernorm stats (mean, rstd) ----------------
__global__ void ln_stats(const float* __restrict__ x) {
    int idx = blockIdx.x * blockDim.x + threadIdx.x;
    if (idx >= B_ * HW) return;
    const float* xp = x + (size_t)(idx / HW) * C_ * HW + (idx % HW);
    float s0 = 0.f, s1 = 0.f, s2 = 0.f, s3 = 0.f;
    float q0 = 0.f, q1 = 0.f, q2 = 0.f, q3 = 0.f;
    #pragma unroll 4
    for (int c = 0; c < C_; c += 4) {
        float v0 = xp[(size_t)(c + 0) * HW];
        float v1 = xp[(size_t)(c + 1) * HW];
        float v2 = xp[(size_t)(c + 2) * HW];
        float v3 = xp[(size_t)(c + 3) * HW];
        s0 += v0; q0 += v0 * v0;
        s1 += v1; q1 += v1 * v1;
        s2 += v2; q2 += v2 * v2;
        s3 += v3; q3 += v3 * v3;
    }
    float mean = (s0 + s1 + s2 + s3) * (1.f / C_);
    float var  = (q0 + q1 + q2 + q3) * (1.f / C_) - mean * mean;
    g_mean[idx] = mean;
    g_rstd[idx] = rsqrtf(var + EPSF);
}

// ---------------- 2/6) tf32 tensor-core GEMM, optional fused-LN B operand ----------------
// C[b][m][n] = A[m][k] * B[b][k][n]; LN: B = (x - mean[n]) * rstd[n] * gvec[k]
template<int KD, bool BIAS, bool LN>
__global__ void __launch_bounds__(256) gemm_tc(const float* __restrict__ A,
                                               const float* __restrict__ Bmat,
                                               float* __restrict__ Cmat,
                                               const float* __restrict__ bias,
                                               const float* __restrict__ gvec) {
    __shared__ float As[128][20];
    __shared__ float Bs[16][136];
    const int b  = blockIdx.z;
    const int n0 = blockIdx.x * 128, m0 = blockIdx.y * 128;
    const int tid = threadIdx.x;
    const int w = tid >> 5, lane = tid & 31;
    const int wm = w >> 1, wn = w & 1;
    const int g = lane >> 2, q = lane & 3;
    const float* Bb = Bmat + (size_t)b * KD * HW;
    float c[2][8][4] = {};
    const int ar = tid >> 2, ac = tid & 3;
    const int br = tid >> 4, bc = tid & 15;

    // fused-LN per-column factors (each thread covers 2 float4 column sets)
    float4 mn[2], rs[2];
    if (LN) {
        #pragma unroll
        for (int i = 0; i < 2; i++) {
            int n = 4 * (bc + 16 * i);
            mn[i] = *(const float4*)(g_mean + (size_t)b * HW + n0 + n);
            rs[i] = *(const float4*)(g_rstd + (size_t)b * HW + n0 + n);
        }
    }

    for (int k0 = 0; k0 < KD; k0 += 16) {
        #pragma unroll
        for (int i = 0; i < 2; i++) {
            int m = ar + 64 * i;
            float4 v = *(const float4*)(A + (size_t)(m0 + m) * KD + k0 + 4 * ac);
            float* d = &As[m][4 * ac];
            d[0] = f2tff(v.x); d[1] = f2tff(v.y); d[2] = f2tff(v.z); d[3] = f2tff(v.w);
        }
        float gk = LN ? gvec[k0 + br] : 0.f;
        #pragma unroll
        for (int i = 0; i < 2; i++) {
            int n = 4 * (bc + 16 * i);
            float4 v = *(const float4*)(Bb + (size_t)(k0 + br) * HW + n0 + n);
            if (LN) {
                v.x = (v.x - mn[i].x) * rs[i].x * gk;
                v.y = (v.y - mn[i].y) * rs[i].y * gk;
                v.z = (v.z - mn[i].z) * rs[i].z * gk;
                v.w = (v.w - mn[i].w) * rs[i].w * gk;
            }
            float* d = &Bs[br][n];
            d[0] = f2tff(v.x); d[1] = f2tff(v.y); d[2] = f2tff(v.z); d[3] = f2tff(v.w);
        }
        __syncthreads();
        #pragma unroll
        for (int h8 = 0; h8 < 2; h8++) {
            unsigned a[2][4];
            #pragma unroll
            for (int i = 0; i < 2; i++) {
                int m = wm * 32 + i * 16;
                a[i][0] = __float_as_uint(As[m + g    ][8 * h8 + q]);
                a[i][1] = __float_as_uint(As[m + g + 8][8 * h8 + q]);
                a[i][2] = __float_as_uint(As[m + g    ][8 * h8 + q + 4]);
                a[i][3] = __float_as_uint(As[m + g + 8][8 * h8 + q + 4]);
            }
            #pragma unroll
            for (int nb = 0; nb < 8; nb++) {
                int n = wn * 64 + nb * 8 + g;
                unsigned b0 = __float_as_uint(Bs[8 * h8 + q    ][n]);
                unsigned b1 = __float_as_uint(Bs[8 * h8 + q + 4][n]);
                mma8(c[0][nb], a[0], b0, b1);
                mma8(c[1][nb], a[1], b0, b1);
            }
        }
        __syncthreads();
    }

    float* Cb = Cmat + (size_t)b * (BIAS ? C_ : 3 * HID) * HW;
    #pragma unroll
    for (int i = 0; i < 2; i++) {
        int m = m0 + wm * 32 + i * 16 + g;
        float bb0 = BIAS ? bias[m] : 0.f;
        float bb8 = BIAS ? bias[m + 8] : 0.f;
        #pragma unroll
        for (int nb = 0; nb < 8; nb++) {
            int n = n0 + wn * 64 + nb * 8 + 2 * q;
            *(float2*)(Cb + (size_t)m * HW + n) =
                make_float2(c[i][nb][0] + bb0, c[i][nb][1] + bb0);
            *(float2*)(Cb + (size_t)(m + 8) * HW + n) =
                make_float2(c[i][nb][2] + bb8, c[i][nb][3] + bb8);
        }
    }
}

// ---------------- 3) depthwise 3x3 conv ----------------
__global__ void dwconv_kernel(const float* __restrict__ wq,
                              const float* __restrict__ wk,
                              const float* __restrict__ wv) {
    int idx = blockIdx.x * blockDim.x + threadIdx.x;
    if (idx >= B_ * 3 * HID * HW) return;
    int xx = idx % W_;
    int yy = (idx / W_) % H_;
    int c  = (idx / HW) % (3 * HID);
    const float* wsel = (c < HID) ? wq : (c < 2 * HID) ? wk : wv;
    const float* w = wsel + (size_t)(c & (HID - 1)) * 9;
    float w9[9];
    #pragma unroll
    for (int i = 0; i < 9; i++) w9[i] = __ldg(&w[i]);
    const float* ip = g_qkv + (size_t)(idx / HW) * HW;
    float acc = 0.f;
    #pragma unroll
    for (int dy = -1; dy <= 1; dy++) {
        int y = yy + dy;
        if (y < 0 || y >= H_) continue;
        #pragma unroll
        for (int dx = -1; dx <= 1; dx++) {
            int x = xx + dx;
            if (x < 0 || x >= W_) continue;
            acc += ip[y * W_ + x] * w9[(dy + 1) * 3 + (dx + 1)];
        }
    }
    g_conv[idx] = acc;
}

// ---------------- 4) rope + tf32 round + mma-fragment packing ----------------
__global__ void __launch_bounds__(256) rope_kernel() {
    __shared__ float tile[64][33];
    const int b   = blockIdx.z;
    const int sel = blockIdx.y >> 3;
    const int h   = blockIdx.y & 7;
    const int bh  = b * HEADS + h;
    const int i0  = blockIdx.x * 32;
    const int cbase = sel * HID + h * DH;
    const int t  = threadIdx.x;
    const int ii = t & 31, dr = t >> 5;
    const float* src = g_conv + ((size_t)(b * 3 * HID + cbase)) * HW + i0;
    #pragma unroll
    for (int r = 0; r < 8; r++) {
        int dd = dr + r * 8;
        tile[dd][ii] = src[(size_t)dd * HW + ii];
    }
    __syncthreads();
    #pragma unroll
    for (int p = 0; p < 8; p++) {
        int e  = p * 256 + t;
        int dd = e & 63, jj = e >> 6;
        int s  = i0 + jj;
        float t1 = tile[dd][jj];
        float val;
        if (sel == 2) {
            val = t1;
        } else {
            int j = dd & 31;
            float invf = exp2f(-((float)(2 * j) * (1.0f / 64.0f)) * LOG2_10000);
            float a = (float)s * invf;
            float sa, ca;
            sincosf(a, &sa, &ca);
            float t2 = tile[dd ^ 32][jj];
            val = (dd < 32) ? (t1 * ca - t2 * sa) : (t1 * ca + t2 * sa);
            if (sel == 0) val *= SCALEF * LOG2E;
        }
        float fv = f2tff(val);
        if (sel == 0) {
            int r16 = s >> 4, g = s & 7, half = (s >> 3) & 1;
            int ks = dd >> 3, q2 = dd & 3, dh2 = (dd >> 2) & 1;
            int lane = 4 * g + q2, j4 = half + 2 * dh2;
            ((float*)g_qf4)[(size_t)((((bh * 144 + r16) * 8 + ks) * 32 + lane)) * 4 + j4] = fv;
        } else if (sel == 1) {
            int tl = s >> 6, nb = (s >> 3) & 7, g = s & 7;
            int ks = dd >> 3, q2 = dd & 3, bb = (dd >> 2) & 1;
            int lane = 4 * g + q2, j4 = (ks & 1) * 2 + bb;
            ((float*)g_kf4)[(size_t)(((((bh * 36 + tl) * 8 + nb) * 4 + (ks >> 1)) * 32 + lane)) * 4 + j4] = fv;
        } else {
            int tl = s >> 6, ks2 = (s >> 3) & 7, q2 = s & 3, bb = (s >> 2) & 1;
            int nb2 = dd >> 3, g = dd & 7;
            int lane = 4 * g + q2, j4 = (ks2 & 1) * 2 + bb;
            ((float*)g_vf4)[(size_t)(((((bh * 36 + tl) * 8 + nb2) * 4 + (ks2 >> 1)) * 32 + lane)) * 4 + j4] = fv;
        }
    }
}

// ---------------- 5) flash attention: tf32 MMA + cp.async double buffer ----------------
__global__ void __launch_bounds__(128) flash_tc() {
    // [stage][ K:0..1023 | V:1024..2047 ]  -> 64 KB
    __shared__ float4 KV[2][2048];
    const int b = blockIdx.z, h = blockIdx.y;
    const int bh = b * HEADS + h;
    const int w    = threadIdx.x >> 5, lane = threadIdx.x & 31;
    const int q    = lane & 3, g = lane >> 2;
    const int grp0 = blockIdx.x * 8 + w * 2;

    unsigned qa[2][8][4];
    {
        const float4* qf = g_qf4 + (size_t)bh * 144 * 8 * 32;
        #pragma unroll
        for (int h2 = 0; h2 < 2; h2++)
            #pragma unroll
            for (int ks = 0; ks < 8; ks++) {
                float4 v = qf[(size_t)((grp0 + h2) * 8 + ks) * 32 + lane];
                qa[h2][ks][0] = __float_as_uint(v.x);
                qa[h2][ks][1] = __float_as_uint(v.y);
                qa[h2][ks][2] = __float_as_uint(v.z);
                qa[h2][ks][3] = __float_as_uint(v.w);
            }
    }

    float o[2][8][4] = {};
    float m0[2] = {-1e30f, -1e30f}, m1[2] = {-1e30f, -1e30f};
    float l0[2] = {0.f, 0.f}, l1[2] = {0.f, 0.f};

    const float4* kg = g_kf4 + (size_t)bh * 36 * 1024;
    const float4* vg = g_vf4 + (size_t)bh * 36 * 1024;

    // issue tile 0 into stage 0
    #pragma unroll
    for (int i = 0; i < 8; i++) {
        int e = threadIdx.x + 128 * i;
        cp16(smem_u32(&KV[0][e]),        kg + e);
        cp16(smem_u32(&KV[0][1024 + e]), vg + e);
    }
    cp_commit();

    for (int t = 0; t < 36; t++) {
        const int cur = t & 1;
        if (t + 1 < 36) {
            const int nxt = cur ^ 1;
            #pragma unroll
            for (int i = 0; i < 8; i++) {
                int e = threadIdx.x + 128 * i;
                cp16(smem_u32(&KV[nxt][e]),        kg + (size_t)(t + 1) * 1024 + e);
                cp16(smem_u32(&KV[nxt][1024 + e]), vg + (size_t)(t + 1) * 1024 + e);
            }
            cp_commit();
            cp_wait<1>();
        } else {
            cp_wait<0>();
        }
        __syncthreads();
        const float4* Ks = KV[cur];
        const float4* Vs = KV[cur] + 1024;

        float s[2][8][4] = {};
        #pragma unroll
        for (int nb = 0; nb < 8; nb++) {
            #pragma unroll
            for (int kp = 0; kp < 4; kp++) {
                float4 bb = Ks[(nb * 4 + kp) * 32 + lane];
                unsigned b0 = __float_as_uint(bb.x), b1 = __float_as_uint(bb.y);
                unsigned b2 = __float_as_uint(bb.z), b3 = __float_as_uint(bb.w);
                mma8(s[0][nb], qa[0][2 * kp + 0], b0, b1);
                mma8(s[0][nb], qa[0][2 * kp + 1], b2, b3);
                mma8(s[1][nb], qa[1][2 * kp + 0], b0, b1);
                mma8(s[1][nb], qa[1][2 * kp + 1], b2, b3);
            }
        }

        #pragma unroll
        for (int h2 = 0; h2 < 2; h2++) {
            float mx0 = -1e30f, mx1 = -1e30f;
            #pragma unroll
            for (int nb = 0; nb < 8; nb++) {
                mx0 = fmaxf(mx0, fmaxf(s[h2][nb][0], s[h2][nb][1]));
                mx1 = fmaxf(mx1, fmaxf(s[h2][nb][2], s[h2][nb][3]));
            }
            mx0 = fmaxf(mx0, __shfl_xor_sync(0xffffffffu, mx0, 1));
            mx0 = fmaxf(mx0, __shfl_xor_sync(0xffffffffu, mx0, 2));
            mx1 = fmaxf(mx1, __shfl_xor_sync(0xffffffffu, mx1, 1));
            mx1 = fmaxf(mx1, __shfl_xor_sync(0xffffffffu, mx1, 2));
            float nm0 = fmaxf(m0[h2], mx0), nm1 = fmaxf(m1[h2], mx1);
            float cf0 = exp2f(m0[h2] - nm0), cf1 = exp2f(m1[h2] - nm1);
            m0[h2] = nm0; m1[h2] = nm1;
            l0[h2] *= cf0; l1[h2] *= cf1;
            #pragma unroll
            for (int nb = 0; nb < 8; nb++) {
                o[h2][nb][0] *= cf0; o[h2][nb][1] *= cf0;
                o[h2][nb][2] *= cf1; o[h2][nb][3] *= cf1;
            }
            #pragma unroll
            for (int nb = 0; nb < 8; nb++) {
                float p0 = exp2f(s[h2][nb][0] - nm0);
                float p1 = exp2f(s[h2][nb][1] - nm0);
                float p2 = exp2f(s[h2][nb][2] - nm1);
                float p3 = exp2f(s[h2][nb][3] - nm1);
                l0[h2] += p0 + p1; l1[h2] += p2 + p3;
                s[h2][nb][0] = p0; s[h2][nb][1] = p1;
                s[h2][nb][2] = p2; s[h2][nb][3] = p3;
            }
        }

        const int src1 = (lane & ~3) | (q >> 1);
        const int src2 = src1 + 2;
        const bool odd = (q & 1);
        #pragma unroll
        for (int kp = 0; kp < 4; kp++) {
            unsigned a[2][2][4];
            #pragma unroll
            for (int h2 = 0; h2 < 2; h2++) {
                #pragma unroll
                for (int e = 0; e < 2; e++) {
                    int ks2 = 2 * kp + e;
                    float c0 = s[h2][ks2][0], c1 = s[h2][ks2][1];
                    float c2 = s[h2][ks2][2], c3 = s[h2][ks2][3];
                    float t0 = __shfl_sync(0xffffffffu, c0, src1);
                    float t1 = __shfl_sync(0xffffffffu, c1, src1);
                    float u0 = __shfl_sync(0xffffffffu, c2, src1);
                    float u1 = __shfl_sync(0xffffffffu, c3, src1);
                    float t2 = __shfl_sync(0xffffffffu, c0, src2);
                    float t3 = __shfl_sync(0xffffffffu, c1, src2);
                    float u2 = __shfl_sync(0xffffffffu, c2, src2);
                    float u3 = __shfl_sync(0xffffffffu, c3, src2);
                    a[h2][e][0] = f2tf(odd ? t1 : t0);
                    a[h2][e][1] = f2tf(odd ? u1 : u0);
                    a[h2][e][2] = f2tf(odd ? t3 : t2);
                    a[h2][e][3] = f2tf(odd ? u3 : u2);
                }
            }
            #pragma unroll
            for (int nb2 = 0; nb2 < 8; nb2++) {
                float4 bb = Vs[(nb2 * 4 + kp) * 32 + lane];
                unsigned b0 = __float_as_uint(bb.x), b1 = __float_as_uint(bb.y);
                unsigned b2 = __float_as_uint(bb.z), b3 = __float_as_uint(bb.w);
                mma8(o[0][nb2], a[0][0], b0, b1);
                mma8(o[0][nb2], a[0][1], b2, b3);
                mma8(o[1][nb2], a[1][0], b0, b1);
                mma8(o[1][nb2], a[1][1], b2, b3);
            }
        }
        __syncthreads();
    }

    // ---- epilogue: normalize, write channel-major O^T [b][c][s] ----
    #pragma unroll
    for (int h2 = 0; h2 < 2; h2++) {
        float L0 = l0[h2];
        L0 += __shfl_xor_sync(0xffffffffu, L0, 1);
        L0 += __shfl_xor_sync(0xffffffffu, L0, 2);
        float L1 = l1[h2];
        L1 += __shfl_xor_sync(0xffffffffu, L1, 1);
        L1 += __shfl_xor_sync(0xffffffffu, L1, 2);
        float inv0 = 1.f / L0, inv1 = 1.f / L1;
        int r0 = (grp0 + h2) * 16 + g;
        float* base = g_oT + ((size_t)b * HID + h * DH) * HW;
        #pragma unroll
        for (int nb2 = 0; nb2 < 8; nb2++) {
            int col = nb2 * 8 + 2 * q;
            base[(size_t)(col    ) * HW + r0    ] = o[h2][nb2][0] * inv0;
            base[(size_t)(col + 1) * HW + r0    ] = o[h2][nb2][1] * inv0;
            base[(size_t)(col    ) * HW + r0 + 8] = o[h2][nb2][2] * inv1;
            base[(size_t)(col + 1) * HW + r0 + 8] = o[h2][nb2][3] * inv1;
        }
    }
}

// ---------------- launcher ----------------
extern "C" void kernel_launch(void* const* d_in, const int* in_sizes, int n_in,
                              void* d_out, int out_size) {
    const float* x      = (const float*)d_in[0];
    const float* norm_g = (const float*)d_in[1];
    const float* w_qkv  = (const float*)d_in[2];
    const float* dw_q   = (const float*)d_in[3];
    const float* dw_k   = (const float*)d_in[4];
    const float* dw_v   = (const float*)d_in[5];
    const float* w_out  = (const float*)d_in[6];
    const float* b_out  = (const float*)d_in[7];
    float* out = (float*)d_out;

    float* qkv; cudaGetSymbolAddress((void**)&qkv, g_qkv);
    float* oT;  cudaGetSymbolAddress((void**)&oT,  g_oT);

    ln_stats<<<(B_ * HW + 127) / 128, 128>>>(x);
    gemm_tc<C_, false, true><<<dim3(HW / 128, 3 * HID / 128, B_), 256>>>(w_qkv, x, qkv, nullptr, norm_g);
    dwconv_kernel<<<(B_ * 3 * HID * HW + 255) / 256, 256>>>(dw_q, dw_k, dw_v);
    rope_kernel<<<dim3(HW / 32, 3 * HEADS, B_), 256>>>();
    flash_tc<<<dim3(S_ / 128, HEADS, B_), 128>>>();
    gemm_tc<HID, true, false><<<dim3(HW / 128, C_ / 128, B_), 256>>>(w_out, oT, out, b_out, nullptr);
}

// round 5
// speedup vs baseline: 5.7989x; 1.3983x over previous
#include <cuda_runtime.h>
#include <cuda_fp16.h>

#define B_   4
#define C_   256
#define H_   48
#define W_   48
#define HW   2304
#define HEADS 8
#define DH   64
#define HID  512
#define S_   2304
#define EPSF 1e-5f
#define SCALEF 0.125f
#define LOG2E 1.4426950408889634f
#define LOG2_10000 13.287712379549449f

// ---------------- scratch ----------------
__device__ float  g_mean[B_*HW];
__device__ float  g_rstd[B_*HW];
__device__ float  g_qkv [B_*3*HID*HW];
__device__ float  g_conv[B_*3*HID*HW];
__device__ uint4  g_qu  [32*144*4*32];   // Q  A-frags fp16: [bh][r16 144][ks 4][lane 32] -> 8 halves
__device__ uint4  g_ku  [32*36*512];     // K  B-frags fp16: [bh][tile 36] -> 512 uint4 (8KB/tile)
__device__ uint4  g_vu  [32*36*512];     // V  B-frags fp16
__device__ float  g_oT  [B_*HID*HW];     // attention out, channel-major [b][c][s]

__device__ __forceinline__ unsigned pack_h2(float lo, float hi) {
    unsigned u;
    asm("cvt.rn.f16x2.f32 %0, %1, %2;" : "=r"(u) : "f"(hi), "f"(lo));
    return u;
}

__device__ __forceinline__ void mma16(float* c, const unsigned* a, unsigned b0, unsigned b1) {
    asm("mma.sync.aligned.m16n8k16.row.col.f32.f16.f16.f32 "
        "{%0,%1,%2,%3},{%4,%5,%6,%7},{%8,%9},{%0,%1,%2,%3};"
        : "+f"(c[0]), "+f"(c[1]), "+f"(c[2]), "+f"(c[3])
        : "r"(a[0]), "r"(a[1]), "r"(a[2]), "r"(a[3]), "r"(b0), "r"(b1));
}

__device__ __forceinline__ unsigned smem_u32(const void* p) {
    return (unsigned)__cvta_generic_to_shared(p);
}
__device__ __forceinline__ void cp16(unsigned dst, const void* src) {
    asm volatile("cp.async.cg.shared.global [%0], [%1], 16;" :: "r"(dst), "l"(src));
}
__device__ __forceinline__ void cp_commit() {
    asm volatile("cp.async.commit_group;");
}
template<int N>
__device__ __forceinline__ void cp_wait() {
    asm volatile("cp.async.wait_group %0;" :: "n"(N));
}

// ---------------- 1) layernorm stats ----------------
__global__ void ln_stats(const float* __restrict__ x) {
    int idx = blockIdx.x * blockDim.x + threadIdx.x;
    if (idx >= B_ * HW) return;
    const float* xp = x + (size_t)(idx / HW) * C_ * HW + (idx % HW);
    float s0 = 0.f, s1 = 0.f, s2 = 0.f, s3 = 0.f;
    float q0 = 0.f, q1 = 0.f, q2 = 0.f, q3 = 0.f;
    #pragma unroll 4
    for (int c = 0; c < C_; c += 4) {
        float v0 = xp[(size_t)(c + 0) * HW];
        float v1 = xp[(size_t)(c + 1) * HW];
        float v2 = xp[(size_t)(c + 2) * HW];
        float v3 = xp[(size_t)(c + 3) * HW];
        s0 += v0; q0 += v0 * v0;
        s1 += v1; q1 += v1 * v1;
        s2 += v2; q2 += v2 * v2;
        s3 += v3; q3 += v3 * v3;
    }
    float mean = (s0 + s1 + s2 + s3) * (1.f / C_);
    float var  = (q0 + q1 + q2 + q3) * (1.f / C_) - mean * mean;
    g_mean[idx] = mean;
    g_rstd[idx] = rsqrtf(var + EPSF);
}

// ---------------- 2/6) fp16 tensor-core GEMM (m16n8k16), optional fused-LN B ----------------
// C[b][m][n] = A[m][k] * B[b][k][n]; LN: B = (x - mean[n]) * rstd[n] * gvec[k]
template<int KD, bool BIAS, bool LN>
__global__ void __launch_bounds__(256) gemm_tc(const float* __restrict__ A,
                                               const float* __restrict__ Bmat,
                                               float* __restrict__ Cmat,
                                               const float* __restrict__ bias,
                                               const float* __restrict__ gvec) {
    __shared__ unsigned As[128][12];    // [m][kk] kk packs k=2kk,2kk+1 (pad 12: conflict-free)
    __shared__ unsigned Bs[8][136];     // [kk][n] (stride 136: conflict-free)
    const int b  = blockIdx.z;
    const int n0 = blockIdx.x * 128, m0 = blockIdx.y * 128;
    const int tid = threadIdx.x;
    const int w = tid >> 5, lane = tid & 31;
    const int wm = w >> 1, wn = w & 1;
    const int g = lane >> 2, q = lane & 3;
    const float* Bb = Bmat + (size_t)b * KD * HW;
    float c[2][8][4] = {};
    const int am = tid >> 1, apart = tid & 1;       // A: row am, k-half apart
    const int bkk = tid >> 5, bn4 = (tid & 31) * 4; // B: kk row pair, 4 cols

    float4 mn, rs;
    if (LN) {
        mn = *(const float4*)(g_mean + (size_t)b * HW + n0 + bn4);
        rs = *(const float4*)(g_rstd + (size_t)b * HW + n0 + bn4);
    }

    for (int k0 = 0; k0 < KD; k0 += 16) {
        {
            const float* ap = A + (size_t)(m0 + am) * KD + k0 + 8 * apart;
            float4 v0 = *(const float4*)(ap);
            float4 v1 = *(const float4*)(ap + 4);
            uint4 u;
            u.x = pack_h2(v0.x, v0.y); u.y = pack_h2(v0.z, v0.w);
            u.z = pack_h2(v1.x, v1.y); u.w = pack_h2(v1.z, v1.w);
            *(uint4*)(&As[am][4 * apart]) = u;
        }
        {
            const float* bp0 = Bb + (size_t)(k0 + 2 * bkk) * HW + n0 + bn4;
            float4 r0 = *(const float4*)(bp0);
            float4 r1 = *(const float4*)(bp0 + HW);
            if (LN) {
                float gk0 = gvec[k0 + 2 * bkk], gk1 = gvec[k0 + 2 * bkk + 1];
                r0.x = (r0.x - mn.x) * rs.x * gk0; r1.x = (r1.x - mn.x) * rs.x * gk1;
                r0.y = (r0.y - mn.y) * rs.y * gk0; r1.y = (r1.y - mn.y) * rs.y * gk1;
                r0.z = (r0.z - mn.z) * rs.z * gk0; r1.z = (r1.z - mn.z) * rs.z * gk1;
                r0.w = (r0.w - mn.w) * rs.w * gk0; r1.w = (r1.w - mn.w) * rs.w * gk1;
            }
            Bs[bkk][bn4 + 0] = pack_h2(r0.x, r1.x);
            Bs[bkk][bn4 + 1] = pack_h2(r0.y, r1.y);
            Bs[bkk][bn4 + 2] = pack_h2(r0.z, r1.z);
            Bs[bkk][bn4 + 3] = pack_h2(r0.w, r1.w);
        }
        __syncthreads();
        unsigned a[2][4];
        #pragma unroll
        for (int i = 0; i < 2; i++) {
            int m = wm * 32 + i * 16;
            a[i][0] = As[m + g    ][q];
            a[i][1] = As[m + g + 8][q];
            a[i][2] = As[m + g    ][q + 4];
            a[i][3] = As[m + g + 8][q + 4];
        }
        #pragma unroll
        for (int nb = 0; nb < 8; nb++) {
            int n = wn * 64 + nb * 8 + g;
            unsigned b0 = Bs[q    ][n];
            unsigned b1 = Bs[q + 4][n];
            mma16(c[0][nb], a[0], b0, b1);
            mma16(c[1][nb], a[1], b0, b1);
        }
        __syncthreads();
    }

    float* Cb = Cmat + (size_t)b * (BIAS ? C_ : 3 * HID) * HW;
    #pragma unroll
    for (int i = 0; i < 2; i++) {
        int m = m0 + wm * 32 + i * 16 + g;
        float bb0 = BIAS ? bias[m] : 0.f;
        float bb8 = BIAS ? bias[m + 8] : 0.f;
        #pragma unroll
        for (int nb = 0; nb < 8; nb++) {
            int n = n0 + wn * 64 + nb * 8 + 2 * q;
            *(float2*)(Cb + (size_t)m * HW + n) =
                make_float2(c[i][nb][0] + bb0, c[i][nb][1] + bb0);
            *(float2*)(Cb + (size_t)(m + 8) * HW + n) =
                make_float2(c[i][nb][2] + bb8, c[i][nb][3] + bb8);
        }
    }
}

// ---------------- 3) depthwise 3x3 conv ----------------
__global__ void dwconv_kernel(const float* __restrict__ wq,
                              const float* __restrict__ wk,
                              const float* __restrict__ wv) {
    int idx = blockIdx.x * blockDim.x + threadIdx.x;
    if (idx >= B_ * 3 * HID * HW) return;
    int xx = idx % W_;
    int yy = (idx / W_) % H_;
    int c  = (idx / HW) % (3 * HID);
    const float* wsel = (c < HID) ? wq : (c < 2 * HID) ? wk : wv;
    const float* w = wsel + (size_t)(c & (HID - 1)) * 9;
    float w9[9];
    #pragma unroll
    for (int i = 0; i < 9; i++) w9[i] = __ldg(&w[i]);
    const float* ip = g_qkv + (size_t)(idx / HW) * HW;
    float acc = 0.f;
    #pragma unroll
    for (int dy = -1; dy <= 1; dy++) {
        int y = yy + dy;
        if (y < 0 || y >= H_) continue;
        #pragma unroll
        for (int dx = -1; dx <= 1; dx++) {
            int x = xx + dx;
            if (x < 0 || x >= W_) continue;
            acc += ip[y * W_ + x] * w9[(dy + 1) * 3 + (dx + 1)];
        }
    }
    g_conv[idx] = acc;
}

// ---------------- 4) rope + fp16 round + mma-fragment packing ----------------
__global__ void __launch_bounds__(256) rope_kernel() {
    __shared__ float tile[64][33];
    const int b   = blockIdx.z;
    const int sel = blockIdx.y >> 3;
    const int h   = blockIdx.y & 7;
    const int bh  = b * HEADS + h;
    const int i0  = blockIdx.x * 32;
    const int cbase = sel * HID + h * DH;
    const int t  = threadIdx.x;
    const int ii = t & 31, dr = t >> 5;
    const float* src = g_conv + ((size_t)(b * 3 * HID + cbase)) * HW + i0;
    #pragma unroll
    for (int r = 0; r < 8; r++) {
        int dd = dr + r * 8;
        tile[dd][ii] = src[(size_t)dd * HW + ii];
    }
    __syncthreads();
    #pragma unroll
    for (int p = 0; p < 8; p++) {
        int e  = p * 256 + t;
        int dd = e & 63, jj = e >> 6;
        int s  = i0 + jj;
        float t1 = tile[dd][jj];
        float val;
        if (sel == 2) {
            val = t1;
        } else {
            int j = dd & 31;
            float invf = exp2f(-((float)(2 * j) * (1.0f / 64.0f)) * LOG2_10000);
            float a = (float)s * invf;
            float sa, ca;
            sincosf(a, &sa, &ca);
            float t2 = tile[dd ^ 32][jj];
            val = (dd < 32) ? (t1 * ca - t2 * sa) : (t1 * ca + t2 * sa);
            if (sel == 0) val *= SCALEF * LOG2E;
        }
        __half hv = __float2half_rn(val);
        if (sel == 0) {
            // Q A-fragment (m16n8k16): reg j4 = hi8 + 2*hiK, packed pair elem
            int r16 = s >> 4, row = s & 15;
            int gq = row & 7, hi8 = row >> 3;
            int ks = dd >> 4, rem = dd & 15;
            int q2 = (rem & 7) >> 1, elem = rem & 1, hiK = rem >> 3;
            int lane = 4 * gq + q2, j4 = hi8 + 2 * hiK;
            size_t hidx = ((size_t)(((bh * 144 + r16) * 4 + ks) * 32 + lane) << 3) + j4 * 2 + elem;
            ((__half*)g_qu)[hidx] = hv;
        } else if (sel == 1) {
            // K B-fragment: n = key, k = dh
            int tl = s >> 6, kk = s & 63;
            int nb = kk >> 3, gq = kk & 7;
            int ks = dd >> 4, rem = dd & 15;
            int breg = rem >> 3, q2 = (rem & 7) >> 1, elem = rem & 1;
            int lane = 4 * gq + q2;
            size_t hidx = ((size_t)((((bh * 36 + tl) * 8 + nb) * 4 + ks) * 32 + lane) << 2) + breg * 2 + elem;
            ((__half*)g_ku)[hidx] = hv;
        } else {
            // V B-fragment: n = dh, k = key
            int tl = s >> 6, kk = s & 63;
            int ks = kk >> 4, rem = kk & 15;
            int breg = rem >> 3, q2 = (rem & 7) >> 1, elem = rem & 1;
            int nb = dd >> 3, gq = dd & 7;
            int lane = 4 * gq + q2;
            size_t hidx = ((size_t)((((bh * 36 + tl) * 8 + nb) * 4 + ks) * 32 + lane) << 2) + breg * 2 + elem;
            ((__half*)g_vu)[hidx] = hv;
        }
    }
}

// ---------------- 5) flash attention: fp16 MMA + cp.async double buffer ----------------
__global__ void __launch_bounds__(128) flash_tc() {
    // [stage][ K: 0..511 | V: 512..1023 ] uint4 -> 32 KB total
    __shared__ uint4 KV[2][1024];
    const int b = blockIdx.z, h = blockIdx.y;
    const int bh = b * HEADS + h;
    const int w    = threadIdx.x >> 5, lane = threadIdx.x & 31;
    const int q    = lane & 3, g = lane >> 2;
    const int grp0 = blockIdx.x * 8 + w * 2;

    // Q fragments: [h2][ks] -> 4 regs
    uint4 qa[2][4];
    {
        const uint4* qf = g_qu + (size_t)(bh * 144) * 4 * 32;
        #pragma unroll
        for (int h2 = 0; h2 < 2; h2++)
            #pragma unroll
            for (int ks = 0; ks < 4; ks++)
                qa[h2][ks] = qf[(size_t)((grp0 + h2) * 4 + ks) * 32 + lane];
    }

    float o[2][8][4] = {};
    float m0[2] = {-1e30f, -1e30f}, m1[2] = {-1e30f, -1e30f};
    float l0[2] = {0.f, 0.f}, l1[2] = {0.f, 0.f};

    const uint4* kg = g_ku + (size_t)(bh * 36) * 512;
    const uint4* vg = g_vu + (size_t)(bh * 36) * 512;

    #pragma unroll
    for (int i = 0; i < 4; i++) {
        int e = threadIdx.x + 128 * i;
        cp16(smem_u32(&KV[0][e]),       kg + e);
        cp16(smem_u32(&KV[0][512 + e]), vg + e);
    }
    cp_commit();

    for (int t = 0; t < 36; t++) {
        const int cur = t & 1;
        if (t + 1 < 36) {
            const int nxt = cur ^ 1;
            #pragma unroll
            for (int i = 0; i < 4; i++) {
                int e = threadIdx.x + 128 * i;
                cp16(smem_u32(&KV[nxt][e]),       kg + (size_t)(t + 1) * 512 + e);
                cp16(smem_u32(&KV[nxt][512 + e]), vg + (size_t)(t + 1) * 512 + e);
            }
            cp_commit();
            cp_wait<1>();
        } else {
            cp_wait<0>();
        }
        __syncthreads();
        const uint2* Ku = (const uint2*)(KV[cur]);
        const uint2* Vu = (const uint2*)(KV[cur] + 512);

        // ---- S = Q K^T ----
        float s[2][8][4] = {};
        #pragma unroll
        for (int nb = 0; nb < 8; nb++) {
            #pragma unroll
            for (int ks = 0; ks < 4; ks++) {
                uint2 bb = Ku[(nb * 4 + ks) * 32 + lane];
                mma16(s[0][nb], (const unsigned*)&qa[0][ks], bb.x, bb.y);
                mma16(s[1][nb], (const unsigned*)&qa[1][ks], bb.x, bb.y);
            }
        }

        // ---- online softmax (base-2; LOG2E folded into Q) ----
        #pragma unroll
        for (int h2 = 0; h2 < 2; h2++) {
            float mx0 = -1e30f, mx1 = -1e30f;
            #pragma unroll
            for (int nb = 0; nb < 8; nb++) {
                mx0 = fmaxf(mx0, fmaxf(s[h2][nb][0], s[h2][nb][1]));
                mx1 = fmaxf(mx1, fmaxf(s[h2][nb][2], s[h2][nb][3]));
            }
            mx0 = fmaxf(mx0, __shfl_xor_sync(0xffffffffu, mx0, 1));
            mx0 = fmaxf(mx0, __shfl_xor_sync(0xffffffffu, mx0, 2));
            mx1 = fmaxf(mx1, __shfl_xor_sync(0xffffffffu, mx1, 1));
            mx1 = fmaxf(mx1, __shfl_xor_sync(0xffffffffu, mx1, 2));
            float nm0 = fmaxf(m0[h2], mx0), nm1 = fmaxf(m1[h2], mx1);
            float cf0 = exp2f(m0[h2] - nm0), cf1 = exp2f(m1[h2] - nm1);
            m0[h2] = nm0; m1[h2] = nm1;
            l0[h2] *= cf0; l1[h2] *= cf1;
            #pragma unroll
            for (int nb = 0; nb < 8; nb++) {
                o[h2][nb][0] *= cf0; o[h2][nb][1] *= cf0;
                o[h2][nb][2] *= cf1; o[h2][nb][3] *= cf1;
            }
            #pragma unroll
            for (int nb = 0; nb < 8; nb++) {
                float p0 = exp2f(s[h2][nb][0] - nm0);
                float p1 = exp2f(s[h2][nb][1] - nm0);
                float p2 = exp2f(s[h2][nb][2] - nm1);
                float p3 = exp2f(s[h2][nb][3] - nm1);
                l0[h2] += p0 + p1; l1[h2] += p2 + p3;
                s[h2][nb][0] = p0; s[h2][nb][1] = p1;
                s[h2][nb][2] = p2; s[h2][nb][3] = p3;
            }
        }

        // ---- O += P V  (C-frag packs directly into fp16 A-frag: zero shuffles) ----
        #pragma unroll
        for (int ks = 0; ks < 4; ks++) {
            unsigned a[2][4];
            #pragma unroll
            for (int h2 = 0; h2 < 2; h2++) {
                a[h2][0] = pack_h2(s[h2][2 * ks    ][0], s[h2][2 * ks    ][1]);
                a[h2][1] = pack_h2(s[h2][2 * ks    ][2], s[h2][2 * ks    ][3]);
                a[h2][2] = pack_h2(s[h2][2 * ks + 1][0], s[h2][2 * ks + 1][1]);
                a[h2][3] = pack_h2(s[h2][2 * ks + 1][2], s[h2][2 * ks + 1][3]);
            }
            #pragma unroll
            for (int nb2 = 0; nb2 < 8; nb2++) {
                uint2 bb = Vu[(nb2 * 4 + ks) * 32 + lane];
                mma16(o[0][nb2], a[0], bb.x, bb.y);
                mma16(o[1][nb2], a[1], bb.x, bb.y);
            }
        }
        __syncthreads();
    }

    // ---- epilogue: normalize, write channel-major O^T [b][c][s] ----
    #pragma unroll
    for (int h2 = 0; h2 < 2; h2++) {
        float L0 = l0[h2];
        L0 += __shfl_xor_sync(0xffffffffu, L0, 1);
        L0 += __shfl_xor_sync(0xffffffffu, L0, 2);
        float L1 = l1[h2];
        L1 += __shfl_xor_sync(0xffffffffu, L1, 1);
        L1 += __shfl_xor_sync(0xffffffffu, L1, 2);
        float inv0 = 1.f / L0, inv1 = 1.f / L1;
        int r0 = (grp0 + h2) * 16 + g;
        float* base = g_oT + ((size_t)b * HID + h * DH) * HW;
        #pragma unroll
        for (int nb2 = 0; nb2 < 8; nb2++) {
            int col = nb2 * 8 + 2 * q;
            base[(size_t)(col    ) * HW + r0    ] = o[h2][nb2][0] * inv0;
            base[(size_t)(col + 1) * HW + r0    ] = o[h2][nb2][1] * inv0;
            base[(size_t)(col    ) * HW + r0 + 8] = o[h2][nb2][2] * inv1;
            base[(size_t)(col + 1) * HW + r0 + 8] = o[h2][nb2][3] * inv1;
        }
    }
}

// ---------------- launcher ----------------
extern "C" void kernel_launch(void* const* d_in, const int* in_sizes, int n_in,
                              void* d_out, int out_size) {
    const float* x      = (const float*)d_in[0];
    const float* norm_g = (const float*)d_in[1];
    const float* w_qkv  = (const float*)d_in[2];
    const float* dw_q   = (const float*)d_in[3];
    const float* dw_k   = (const float*)d_in[4];
    const float* dw_v   = (const float*)d_in[5];
    const float* w_out  = (const float*)d_in[6];
    const float* b_out  = (const float*)d_in[7];
    float* out = (float*)d_out;

    float* qkv; cudaGetSymbolAddress((void**)&qkv, g_qkv);
    float* oT;  cudaGetSymbolAddress((void**)&oT,  g_oT);

    ln_stats<<<(B_ * HW + 127) / 128, 128>>>(x);
    gemm_tc<C_, false, true><<<dim3(HW / 128, 3 * HID / 128, B_), 256>>>(w_qkv, x, qkv, nullptr, norm_g);
    dwconv_kernel<<<(B_ * 3 * HID * HW + 255) / 256, 256>>>(dw_q, dw_k, dw_v);
    rope_kernel<<<dim3(HW / 32, 3 * HEADS, B_), 256>>>();
    flash_tc<<<dim3(S_ / 128, HEADS, B_), 128>>>();
    gemm_tc<HID, true, false><<<dim3(HW / 128, C_ / 128, B_), 256>>>(w_out, oT, out, b_out, nullptr);
}

// round 6
// speedup vs baseline: 7.1732x; 1.2370x over previous
#include <cuda_runtime.h>
#include <cuda_fp16.h>

#define B_   4
#define C_   256
#define H_   48
#define W_   48
#define HW   2304
#define HEADS 8
#define DH   64
#define HID  512
#define S_   2304
#define EPSF 1e-5f
#define SCALEF 0.125f
#define LOG2E 1.4426950408889634f
#define LOG2_10000 13.287712379549449f

// ---------------- scratch ----------------
__device__ float  g_mean[B_*HW];
__device__ float  g_rstd[B_*HW];
__device__ float  g_qkv [B_*3*HID*HW];
__device__ float  g_conv[B_*3*HID*HW];
__device__ float  g_cosT[S_*32];
__device__ float  g_sinT[S_*32];
__device__ uint4  g_qu  [32*144*4*32];   // Q  A-frags fp16
__device__ uint4  g_ku  [32*36*512];     // K  B-frags fp16 (8KB/tile)
__device__ uint4  g_vu  [32*36*512];     // V  B-frags fp16
__device__ float  g_oT  [B_*HID*HW];     // attention out, channel-major [b][c][s]

__device__ __forceinline__ unsigned pack_h2(float lo, float hi) {
    unsigned u;
    asm("cvt.rn.f16x2.f32 %0, %1, %2;" : "=r"(u) : "f"(hi), "f"(lo));
    return u;
}

__device__ __forceinline__ void mma16(float* c, const unsigned* a, unsigned b0, unsigned b1) {
    asm("mma.sync.aligned.m16n8k16.row.col.f32.f16.f16.f32 "
        "{%0,%1,%2,%3},{%4,%5,%6,%7},{%8,%9},{%0,%1,%2,%3};"
        : "+f"(c[0]), "+f"(c[1]), "+f"(c[2]), "+f"(c[3])
        : "r"(a[0]), "r"(a[1]), "r"(a[2]), "r"(a[3]), "r"(b0), "r"(b1));
}

__device__ __forceinline__ unsigned smem_u32(const void* p) {
    return (unsigned)__cvta_generic_to_shared(p);
}
__device__ __forceinline__ void cp16(unsigned dst, const void* src) {
    asm volatile("cp.async.cg.shared.global [%0], [%1], 16;" :: "r"(dst), "l"(src));
}
__device__ __forceinline__ void cp_commit() {
    asm volatile("cp.async.commit_group;");
}
template<int N>
__device__ __forceinline__ void cp_wait() {
    asm volatile("cp.async.wait_group %0;" :: "n"(N));
}

// ---------------- 1) layernorm stats ----------------
__global__ void ln_stats(const float* __restrict__ x) {
    int idx = blockIdx.x * blockDim.x + threadIdx.x;
    if (idx >= B_ * HW) return;
    const float* xp = x + (size_t)(idx / HW) * C_ * HW + (idx % HW);
    float s0 = 0.f, s1 = 0.f, s2 = 0.f, s3 = 0.f;
    float q0 = 0.f, q1 = 0.f, q2 = 0.f, q3 = 0.f;
    #pragma unroll 4
    for (int c = 0; c < C_; c += 4) {
        float v0 = xp[(size_t)(c + 0) * HW];
        float v1 = xp[(size_t)(c + 1) * HW];
        float v2 = xp[(size_t)(c + 2) * HW];
        float v3 = xp[(size_t)(c + 3) * HW];
        s0 += v0; q0 += v0 * v0;
        s1 += v1; q1 += v1 * v1;
        s2 += v2; q2 += v2 * v2;
        s3 += v3; q3 += v3 * v3;
    }
    float mean = (s0 + s1 + s2 + s3) * (1.f / C_);
    float var  = (q0 + q1 + q2 + q3) * (1.f / C_) - mean * mean;
    g_mean[idx] = mean;
    g_rstd[idx] = rsqrtf(var + EPSF);
}

// ---------------- rope cos/sin tables ----------------
__global__ void rope_tab() {
    int idx = blockIdx.x * blockDim.x + threadIdx.x;
    if (idx >= S_ * 32) return;
    int s = idx >> 5, j = idx & 31;
    float invf = exp2f(-((float)(2 * j) * (1.0f / 64.0f)) * LOG2_10000);
    float a = (float)s * invf;
    float sa, ca;
    sincosf(a, &sa, &ca);
    g_cosT[idx] = ca;
    g_sinT[idx] = sa;
}

// ---------------- 2/6) fp16 tensor-core GEMM (m16n8k16), optional fused-LN B ----------------
template<int KD, bool BIAS, bool LN>
__global__ void __launch_bounds__(256) gemm_tc(const float* __restrict__ A,
                                               const float* __restrict__ Bmat,
                                               float* __restrict__ Cmat,
                                               const float* __restrict__ bias,
                                               const float* __restrict__ gvec) {
    __shared__ unsigned As[128][12];
    __shared__ unsigned Bs[8][136];
    const int b  = blockIdx.z;
    const int n0 = blockIdx.x * 128, m0 = blockIdx.y * 128;
    const int tid = threadIdx.x;
    const int w = tid >> 5, lane = tid & 31;
    const int wm = w >> 1, wn = w & 1;
    const int g = lane >> 2, q = lane & 3;
    const float* Bb = Bmat + (size_t)b * KD * HW;
    float c[2][8][4] = {};
    const int am = tid >> 1, apart = tid & 1;
    const int bkk = tid >> 5, bn4 = (tid & 31) * 4;

    float4 mn, rs;
    if (LN) {
        mn = *(const float4*)(g_mean + (size_t)b * HW + n0 + bn4);
        rs = *(const float4*)(g_rstd + (size_t)b * HW + n0 + bn4);
    }

    for (int k0 = 0; k0 < KD; k0 += 16) {
        {
            const float* ap = A + (size_t)(m0 + am) * KD + k0 + 8 * apart;
            float4 v0 = *(const float4*)(ap);
            float4 v1 = *(const float4*)(ap + 4);
            uint4 u;
            u.x = pack_h2(v0.x, v0.y); u.y = pack_h2(v0.z, v0.w);
            u.z = pack_h2(v1.x, v1.y); u.w = pack_h2(v1.z, v1.w);
            *(uint4*)(&As[am][4 * apart]) = u;
        }
        {
            const float* bp0 = Bb + (size_t)(k0 + 2 * bkk) * HW + n0 + bn4;
            float4 r0 = *(const float4*)(bp0);
            float4 r1 = *(const float4*)(bp0 + HW);
            if (LN) {
                float gk0 = gvec[k0 + 2 * bkk], gk1 = gvec[k0 + 2 * bkk + 1];
                r0.x = (r0.x - mn.x) * rs.x * gk0; r1.x = (r1.x - mn.x) * rs.x * gk1;
                r0.y = (r0.y - mn.y) * rs.y * gk0; r1.y = (r1.y - mn.y) * rs.y * gk1;
                r0.z = (r0.z - mn.z) * rs.z * gk0; r1.z = (r1.z - mn.z) * rs.z * gk1;
                r0.w = (r0.w - mn.w) * rs.w * gk0; r1.w = (r1.w - mn.w) * rs.w * gk1;
            }
            Bs[bkk][bn4 + 0] = pack_h2(r0.x, r1.x);
            Bs[bkk][bn4 + 1] = pack_h2(r0.y, r1.y);
            Bs[bkk][bn4 + 2] = pack_h2(r0.z, r1.z);
            Bs[bkk][bn4 + 3] = pack_h2(r0.w, r1.w);
        }
        __syncthreads();
        unsigned a[2][4];
        #pragma unroll
        for (int i = 0; i < 2; i++) {
            int m = wm * 32 + i * 16;
            a[i][0] = As[m + g    ][q];
            a[i][1] = As[m + g + 8][q];
            a[i][2] = As[m + g    ][q + 4];
            a[i][3] = As[m + g + 8][q + 4];
        }
        #pragma unroll
        for (int nb = 0; nb < 8; nb++) {
            int n = wn * 64 + nb * 8 + g;
            unsigned b0 = Bs[q    ][n];
            unsigned b1 = Bs[q + 4][n];
            mma16(c[0][nb], a[0], b0, b1);
            mma16(c[1][nb], a[1], b0, b1);
        }
        __syncthreads();
    }

    float* Cb = Cmat + (size_t)b * (BIAS ? C_ : 3 * HID) * HW;
    #pragma unroll
    for (int i = 0; i < 2; i++) {
        int m = m0 + wm * 32 + i * 16 + g;
        float bb0 = BIAS ? bias[m] : 0.f;
        float bb8 = BIAS ? bias[m + 8] : 0.f;
        #pragma unroll
        for (int nb = 0; nb < 8; nb++) {
            int n = n0 + wn * 64 + nb * 8 + 2 * q;
            *(float2*)(Cb + (size_t)m * HW + n) =
                make_float2(c[i][nb][0] + bb0, c[i][nb][1] + bb0);
            *(float2*)(Cb + (size_t)(m + 8) * HW + n) =
                make_float2(c[i][nb][2] + bb8, c[i][nb][3] + bb8);
        }
    }
}

// ---------------- 3) depthwise 3x3 conv (4 pixels/thread) ----------------
__global__ void dwconv4(const float* __restrict__ wq,
                        const float* __restrict__ wk,
                        const float* __restrict__ wv) {
    int idx = blockIdx.x * blockDim.x + threadIdx.x;
    if (idx >= B_ * 3 * HID * H_ * 12) return;
    int x0 = (idx % 12) * 4;
    int y  = (idx / 12) % H_;
    int ch = idx / (12 * H_);                 // b*3HID + c
    int c  = ch % (3 * HID);
    const float* wsel = (c < HID) ? wq : (c < 2 * HID) ? wk : wv;
    const float* w = wsel + (size_t)(c & (HID - 1)) * 9;
    float w9[9];
    #pragma unroll
    for (int i = 0; i < 9; i++) w9[i] = __ldg(&w[i]);
    const float* ip = g_qkv + (size_t)ch * HW + y * W_;
    float a0 = 0.f, a1 = 0.f, a2 = 0.f, a3 = 0.f;
    #pragma unroll
    for (int dy = -1; dy <= 1; dy++) {
        int yy = y + dy;
        if (yy < 0 || yy >= H_) continue;
        const float* row = ip + dy * W_;
        float l = (x0 > 0)        ? row[x0 - 1] : 0.f;
        float4 cv = *(const float4*)(row + x0);
        float r = (x0 + 4 < W_)   ? row[x0 + 4] : 0.f;
        float arr0 = l, arr1 = cv.x, arr2 = cv.y, arr3 = cv.z, arr4 = cv.w, arr5 = r;
        const float* wr = w9 + (dy + 1) * 3;
        a0 += arr0 * wr[0] + arr1 * wr[1] + arr2 * wr[2];
        a1 += arr1 * wr[0] + arr2 * wr[1] + arr3 * wr[2];
        a2 += arr2 * wr[0] + arr3 * wr[1] + arr4 * wr[2];
        a3 += arr3 * wr[0] + arr4 * wr[1] + arr5 * wr[2];
    }
    *(float4*)(g_conv + (size_t)ch * HW + y * W_ + x0) = make_float4(a0, a1, a2, a3);
}

// ---------------- 4) rope via tables + direct fragment packing ----------------
// grid: (36 tiles, 96 = sel*32 + bh), 256 threads.
__global__ void __launch_bounds__(256) pack_qkv() {
    const int tl  = blockIdx.x;
    const int sel = blockIdx.y >> 5;
    const int bh  = blockIdx.y & 31;
    const int b = bh >> 3, h = bh & 7;
    const int t = threadIdx.x, w = t >> 5, lane = t & 31;
    const int g = lane >> 2, q = lane & 3;
    const float* cb = g_conv + ((size_t)(b * 3 * HID + sel * HID + h * DH)) * HW;

    if (sel == 2) {
        // V: warp = dh block nb2; no rope, pure convert
        const int dd = w * 8 + g;
        const float* col = cb + (size_t)dd * HW + tl * 64;
        uint2* dst = ((uint2*)g_vu) + ((size_t)(bh * 36 + tl)) * 1024 + w * 128 + lane;
        #pragma unroll
        for (int ks = 0; ks < 4; ks++) {
            float2 v0 = *(const float2*)(col + 16 * ks + 2 * q);
            float2 v1 = *(const float2*)(col + 16 * ks + 8 + 2 * q);
            dst[ks * 32] = make_uint2(pack_h2(v0.x, v0.y), pack_h2(v1.x, v1.y));
        }
    } else if (sel == 1) {
        // K: warp = key block nb
        const int nb = w;
        const int s = tl * 64 + nb * 8 + g;
        float xv[4][2][2];   // [hi16][b8][e]
        #pragma unroll
        for (int hi = 0; hi < 4; hi++)
            #pragma unroll
            for (int bb = 0; bb < 2; bb++) {
                int dd = 16 * hi + 8 * bb + 2 * q;
                xv[hi][bb][0] = cb[(size_t)dd * HW + s];
                xv[hi][bb][1] = cb[(size_t)(dd + 1) * HW + s];
            }
        float2 cT[2][2], sT[2][2];   // [k1][b8]
        #pragma unroll
        for (int k1 = 0; k1 < 2; k1++)
            #pragma unroll
            for (int bb = 0; bb < 2; bb++) {
                int j = 16 * k1 + 8 * bb + 2 * q;
                cT[k1][bb] = *(const float2*)(g_cosT + s * 32 + j);
                sT[k1][bb] = *(const float2*)(g_sinT + s * 32 + j);
            }
        uint2* dst = ((uint2*)g_ku) + ((size_t)(bh * 36 + tl)) * 1024 + nb * 128 + lane;
        #pragma unroll
        for (int ks = 0; ks < 4; ks++) {
            int k1 = ks & 1;
            unsigned uu[2];
            #pragma unroll
            for (int bb = 0; bb < 2; bb++) {
                float v[2];
                #pragma unroll
                for (int e = 0; e < 2; e++) {
                    float cc = e ? cT[k1][bb].y : cT[k1][bb].x;
                    float ss = e ? sT[k1][bb].y : sT[k1][bb].x;
                    float t1 = xv[ks][bb][e], t2 = xv[ks ^ 2][bb][e];
                    v[e] = (ks < 2) ? (t1 * cc - t2 * ss) : (t1 * cc + t2 * ss);
                }
                uu[bb] = pack_h2(v[0], v[1]);
            }
            dst[ks * 32] = make_uint2(uu[0], uu[1]);
        }
    } else {
        // Q: warp w -> r16 = tl*4 + (w&3), ks pair p = w>>2 handles ks {p, p+2}
        const int p = w >> 2;
        const int r16 = tl * 4 + (w & 3);
        const int s0 = r16 * 16 + g;
        float xv[2][2][2][2];   // [kk][hiK][e][si]
        #pragma unroll
        for (int kk = 0; kk < 2; kk++)
            #pragma unroll
            for (int hiK = 0; hiK < 2; hiK++)
                #pragma unroll
                for (int e = 0; e < 2; e++) {
                    int dd = 16 * (p + 2 * kk) + 8 * hiK + 2 * q + e;
                    const float* rowp = cb + (size_t)dd * HW;
                    xv[kk][hiK][e][0] = rowp[s0];
                    xv[kk][hiK][e][1] = rowp[s0 + 8];
                }
        float2 cT[2][2], sT[2][2];   // [hiK][si]
        #pragma unroll
        for (int hiK = 0; hiK < 2; hiK++)
            #pragma unroll
            for (int si = 0; si < 2; si++) {
                int j = 16 * p + 8 * hiK + 2 * q;
                int off = (s0 + 8 * si) * 32 + j;
                cT[hiK][si] = *(const float2*)(g_cosT + off);
                sT[hiK][si] = *(const float2*)(g_sinT + off);
            }
        const float QS = SCALEF * LOG2E;
        uint4* dst = g_qu + ((size_t)(bh * 144 + r16)) * 4 * 32 + lane;
        #pragma unroll
        for (int kk = 0; kk < 2; kk++) {
            unsigned r[4];
            #pragma unroll
            for (int hiK = 0; hiK < 2; hiK++)
                #pragma unroll
                for (int si = 0; si < 2; si++) {
                    float v[2];
                    #pragma unroll
                    for (int e = 0; e < 2; e++) {
                        float cc = e ? cT[hiK][si].y : cT[hiK][si].x;
                        float ss = e ? sT[hiK][si].y : sT[hiK][si].x;
                        float t1 = xv[kk][hiK][e][si], t2 = xv[kk ^ 1][hiK][e][si];
                        float vv = (kk == 0) ? (t1 * cc - t2 * ss) : (t1 * cc + t2 * ss);
                        v[e] = vv * QS;
                    }
                    r[si + 2 * hiK] = pack_h2(v[0], v[1]);
                }
            dst[(p + 2 * kk) * 32] = make_uint4(r[0], r[1], r[2], r[3]);
        }
    }
}

// ---------------- 5) flash attention: fp16 MMA + cp.async double buffer ----------------
__global__ void __launch_bounds__(128) flash_tc() {
    __shared__ uint4 KV[2][1024];
    const int b = blockIdx.z, h = blockIdx.y;
    const int bh = b * HEADS + h;
    const int w    = threadIdx.x >> 5, lane = threadIdx.x & 31;
    const int q    = lane & 3, g = lane >> 2;
    const int grp0 = blockIdx.x * 8 + w * 2;

    uint4 qa[2][4];
    {
        const uint4* qf = g_qu + (size_t)(bh * 144) * 4 * 32;
        #pragma unroll
        for (int h2 = 0; h2 < 2; h2++)
            #pragma unroll
            for (int ks = 0; ks < 4; ks++)
                qa[h2][ks] = qf[(size_t)((grp0 + h2) * 4 + ks) * 32 + lane];
    }

    float o[2][8][4] = {};
    float m0[2] = {-1e30f, -1e30f}, m1[2] = {-1e30f, -1e30f};
    float l0[2] = {0.f, 0.f}, l1[2] = {0.f, 0.f};

    const uint4* kg = g_ku + (size_t)(bh * 36) * 512;
    const uint4* vg = g_vu + (size_t)(bh * 36) * 512;

    #pragma unroll
    for (int i = 0; i < 4; i++) {
        int e = threadIdx.x + 128 * i;
        cp16(smem_u32(&KV[0][e]),       kg + e);
        cp16(smem_u32(&KV[0][512 + e]), vg + e);
    }
    cp_commit();

    for (int t = 0; t < 36; t++) {
        const int cur = t & 1;
        if (t + 1 < 36) {
            const int nxt = cur ^ 1;
            #pragma unroll
            for (int i = 0; i < 4; i++) {
                int e = threadIdx.x + 128 * i;
                cp16(smem_u32(&KV[nxt][e]),       kg + (size_t)(t + 1) * 512 + e);
                cp16(smem_u32(&KV[nxt][512 + e]), vg + (size_t)(t + 1) * 512 + e);
            }
            cp_commit();
            cp_wait<1>();
        } else {
            cp_wait<0>();
        }
        __syncthreads();
        const uint2* Ku = (const uint2*)(KV[cur]);
        const uint2* Vu = (const uint2*)(KV[cur] + 512);

        float s[2][8][4] = {};
        #pragma unroll
        for (int nb = 0; nb < 8; nb++) {
            #pragma unroll
            for (int ks = 0; ks < 4; ks++) {
                uint2 bb = Ku[(nb * 4 + ks) * 32 + lane];
                mma16(s[0][nb], (const unsigned*)&qa[0][ks], bb.x, bb.y);
                mma16(s[1][nb], (const unsigned*)&qa[1][ks], bb.x, bb.y);
            }
        }

        #pragma unroll
        for (int h2 = 0; h2 < 2; h2++) {
            float mx0 = -1e30f, mx1 = -1e30f;
            #pragma unroll
            for (int nb = 0; nb < 8; nb++) {
                mx0 = fmaxf(mx0, fmaxf(s[h2][nb][0], s[h2][nb][1]));
                mx1 = fmaxf(mx1, fmaxf(s[h2][nb][2], s[h2][nb][3]));
            }
            mx0 = fmaxf(mx0, __shfl_xor_sync(0xffffffffu, mx0, 1));
            mx0 = fmaxf(mx0, __shfl_xor_sync(0xffffffffu, mx0, 2));
            mx1 = fmaxf(mx1, __shfl_xor_sync(0xffffffffu, mx1, 1));
            mx1 = fmaxf(mx1, __shfl_xor_sync(0xffffffffu, mx1, 2));
            float nm0 = fmaxf(m0[h2], mx0), nm1 = fmaxf(m1[h2], mx1);
            float cf0 = exp2f(m0[h2] - nm0), cf1 = exp2f(m1[h2] - nm1);
            m0[h2] = nm0; m1[h2] = nm1;
            l0[h2] *= cf0; l1[h2] *= cf1;
            #pragma unroll
            for (int nb = 0; nb < 8; nb++) {
                o[h2][nb][0] *= cf0; o[h2][nb][1] *= cf0;
                o[h2][nb][2] *= cf1; o[h2][nb][3] *= cf1;
            }
            #pragma unroll
            for (int nb = 0; nb < 8; nb++) {
                float p0 = exp2f(s[h2][nb][0] - nm0);
                float p1 = exp2f(s[h2][nb][1] - nm0);
                float p2 = exp2f(s[h2][nb][2] - nm1);
                float p3 = exp2f(s[h2][nb][3] - nm1);
                l0[h2] += p0 + p1; l1[h2] += p2 + p3;
                s[h2][nb][0] = p0; s[h2][nb][1] = p1;
                s[h2][nb][2] = p2; s[h2][nb][3] = p3;
            }
        }

        #pragma unroll
        for (int ks = 0; ks < 4; ks++) {
            unsigned a[2][4];
            #pragma unroll
            for (int h2 = 0; h2 < 2; h2++) {
                a[h2][0] = pack_h2(s[h2][2 * ks    ][0], s[h2][2 * ks    ][1]);
                a[h2][1] = pack_h2(s[h2][2 * ks    ][2], s[h2][2 * ks    ][3]);
                a[h2][2] = pack_h2(s[h2][2 * ks + 1][0], s[h2][2 * ks + 1][1]);
                a[h2][3] = pack_h2(s[h2][2 * ks + 1][2], s[h2][2 * ks + 1][3]);
            }
            #pragma unroll
            for (int nb2 = 0; nb2 < 8; nb2++) {
                uint2 bb = Vu[(nb2 * 4 + ks) * 32 + lane];
                mma16(o[0][nb2], a[0], bb.x, bb.y);
                mma16(o[1][nb2], a[1], bb.x, bb.y);
            }
        }
        __syncthreads();
    }

    #pragma unroll
    for (int h2 = 0; h2 < 2; h2++) {
        float L0 = l0[h2];
        L0 += __shfl_xor_sync(0xffffffffu, L0, 1);
        L0 += __shfl_xor_sync(0xffffffffu, L0, 2);
        float L1 = l1[h2];
        L1 += __shfl_xor_sync(0xffffffffu, L1, 1);
        L1 += __shfl_xor_sync(0xffffffffu, L1, 2);
        float inv0 = 1.f / L0, inv1 = 1.f / L1;
        int r0 = (grp0 + h2) * 16 + g;
        float* base = g_oT + ((size_t)b * HID + h * DH) * HW;
        #pragma unroll
        for (int nb2 = 0; nb2 < 8; nb2++) {
            int col = nb2 * 8 + 2 * q;
            base[(size_t)(col    ) * HW + r0    ] = o[h2][nb2][0] * inv0;
            base[(size_t)(col + 1) * HW + r0    ] = o[h2][nb2][1] * inv0;
            base[(size_t)(col    ) * HW + r0 + 8] = o[h2][nb2][2] * inv1;
            base[(size_t)(col + 1) * HW + r0 + 8] = o[h2][nb2][3] * inv1;
        }
    }
}

// ---------------- launcher ----------------
extern "C" void kernel_launch(void* const* d_in, const int* in_sizes, int n_in,
                              void* d_out, int out_size) {
    const float* x      = (const float*)d_in[0];
    const float* norm_g = (const float*)d_in[1];
    const float* w_qkv  = (const float*)d_in[2];
    const float* dw_q   = (const float*)d_in[3];
    const float* dw_k   = (const float*)d_in[4];
    const float* dw_v   = (const float*)d_in[5];
    const float* w_out  = (const float*)d_in[6];
    const float* b_out  = (const float*)d_in[7];
    float* out = (float*)d_out;

    float* qkv; cudaGetSymbolAddress((void**)&qkv, g_qkv);
    float* oT;  cudaGetSymbolAddress((void**)&oT,  g_oT);

    ln_stats<<<(B_ * HW + 127) / 128, 128>>>(x);
    rope_tab<<<(S_ * 32 + 255) / 256, 256>>>();
    gemm_tc<C_, false, true><<<dim3(HW / 128, 3 * HID / 128, B_), 256>>>(w_qkv, x, qkv, nullptr, norm_g);
    dwconv4<<<(B_ * 3 * HID * H_ * 12 + 255) / 256, 256>>>(dw_q, dw_k, dw_v);
    pack_qkv<<<dim3(36, 96), 256>>>();
    flash_tc<<<dim3(S_ / 128, HEADS, B_), 128>>>();
    gemm_tc<HID, true, false><<<dim3(HW / 128, C_ / 128, B_), 256>>>(w_out, oT, out, b_out, nullptr);
}

// round 7
// speedup vs baseline: 7.1801x; 1.0010x over previous
#include <cuda_runtime.h>
#include <cuda_fp16.h>

#define B_   4
#define C_   256
#define H_   48
#define W_   48
#define HW   2304
#define HEADS 8
#define DH   64
#define HID  512
#define S_   2304
#define EPSF 1e-5f
#define SCALEF 0.125f
#define LOG2E 1.4426950408889634f
#define LOG2_10000 13.287712379549449f

// ---------------- scratch ----------------
__device__ float  g_mean[B_*HW];
__device__ float  g_rstd[B_*HW];
__device__ float  g_qkv [B_*3*HID*HW];
__device__ float  g_conv[B_*3*HID*HW];
__device__ float  g_cosT[S_*32];
__device__ float  g_sinT[S_*32];
__device__ uint4  g_qu  [32*144*4*32];   // Q  A-frags fp16
__device__ uint4  g_ku  [32*36*512];     // K  B-frags fp16 (8KB/tile)
__device__ uint4  g_vu  [32*36*512];     // V  B-frags fp16
__device__ float  g_oT  [B_*HID*HW];     // attention out, channel-major [b][c][s]

__device__ __forceinline__ unsigned pack_h2(float lo, float hi) {
    unsigned u;
    asm("cvt.rn.f16x2.f32 %0, %1, %2;" : "=r"(u) : "f"(hi), "f"(lo));
    return u;
}

__device__ __forceinline__ void mma16(float* c, const unsigned* a, unsigned b0, unsigned b1) {
    asm("mma.sync.aligned.m16n8k16.row.col.f32.f16.f16.f32 "
        "{%0,%1,%2,%3},{%4,%5,%6,%7},{%8,%9},{%0,%1,%2,%3};"
        : "+f"(c[0]), "+f"(c[1]), "+f"(c[2]), "+f"(c[3])
        : "r"(a[0]), "r"(a[1]), "r"(a[2]), "r"(a[3]), "r"(b0), "r"(b1));
}

__device__ __forceinline__ unsigned smem_u32(const void* p) {
    return (unsigned)__cvta_generic_to_shared(p);
}
__device__ __forceinline__ void cp16(unsigned dst, const void* src) {
    asm volatile("cp.async.cg.shared.global [%0], [%1], 16;" :: "r"(dst), "l"(src));
}
__device__ __forceinline__ void cp_commit() {
    asm volatile("cp.async.commit_group;");
}
template<int N>
__device__ __forceinline__ void cp_wait() {
    asm volatile("cp.async.wait_group %0;" :: "n"(N));
}

// ---------------- 1) layernorm stats ----------------
__global__ void ln_stats(const float* __restrict__ x) {
    int idx = blockIdx.x * blockDim.x + threadIdx.x;
    if (idx >= B_ * HW) return;
    const float* xp = x + (size_t)(idx / HW) * C_ * HW + (idx % HW);
    float s0 = 0.f, s1 = 0.f, s2 = 0.f, s3 = 0.f;
    float q0 = 0.f, q1 = 0.f, q2 = 0.f, q3 = 0.f;
    #pragma unroll 4
    for (int c = 0; c < C_; c += 4) {
        float v0 = xp[(size_t)(c + 0) * HW];
        float v1 = xp[(size_t)(c + 1) * HW];
        float v2 = xp[(size_t)(c + 2) * HW];
        float v3 = xp[(size_t)(c + 3) * HW];
        s0 += v0; q0 += v0 * v0;
        s1 += v1; q1 += v1 * v1;
        s2 += v2; q2 += v2 * v2;
        s3 += v3; q3 += v3 * v3;
    }
    float mean = (s0 + s1 + s2 + s3) * (1.f / C_);
    float var  = (q0 + q1 + q2 + q3) * (1.f / C_) - mean * mean;
    g_mean[idx] = mean;
    g_rstd[idx] = rsqrtf(var + EPSF);
}

// ---------------- rope cos/sin tables ----------------
__global__ void rope_tab() {
    int idx = blockIdx.x * blockDim.x + threadIdx.x;
    if (idx >= S_ * 32) return;
    int s = idx >> 5, j = idx & 31;
    float invf = exp2f(-((float)(2 * j) * (1.0f / 64.0f)) * LOG2_10000);
    float a = (float)s * invf;
    float sa, ca;
    sincosf(a, &sa, &ca);
    g_cosT[idx] = ca;
    g_sinT[idx] = sa;
}

// ---------------- 2/6) fp16 tensor-core GEMM (m16n8k16), optional fused-LN B ----------------
template<int KD, bool BIAS, bool LN>
__global__ void __launch_bounds__(256) gemm_tc(const float* __restrict__ A,
                                               const float* __restrict__ Bmat,
                                               float* __restrict__ Cmat,
                                               const float* __restrict__ bias,
                                               const float* __restrict__ gvec) {
    __shared__ unsigned As[128][12];
    __shared__ unsigned Bs[8][136];
    const int b  = blockIdx.z;
    const int n0 = blockIdx.x * 128, m0 = blockIdx.y * 128;
    const int tid = threadIdx.x;
    const int w = tid >> 5, lane = tid & 31;
    const int wm = w >> 1, wn = w & 1;
    const int g = lane >> 2, q = lane & 3;
    const float* Bb = Bmat + (size_t)b * KD * HW;
    float c[2][8][4] = {};
    const int am = tid >> 1, apart = tid & 1;
    const int bkk = tid >> 5, bn4 = (tid & 31) * 4;

    float4 mn, rs;
    if (LN) {
        mn = *(const float4*)(g_mean + (size_t)b * HW + n0 + bn4);
        rs = *(const float4*)(g_rstd + (size_t)b * HW + n0 + bn4);
    }

    for (int k0 = 0; k0 < KD; k0 += 16) {
        {
            const float* ap = A + (size_t)(m0 + am) * KD + k0 + 8 * apart;
            float4 v0 = *(const float4*)(ap);
            float4 v1 = *(const float4*)(ap + 4);
            uint4 u;
            u.x = pack_h2(v0.x, v0.y); u.y = pack_h2(v0.z, v0.w);
            u.z = pack_h2(v1.x, v1.y); u.w = pack_h2(v1.z, v1.w);
            *(uint4*)(&As[am][4 * apart]) = u;
        }
        {
            const float* bp0 = Bb + (size_t)(k0 + 2 * bkk) * HW + n0 + bn4;
            float4 r0 = *(const float4*)(bp0);
            float4 r1 = *(const float4*)(bp0 + HW);
            if (LN) {
                float gk0 = gvec[k0 + 2 * bkk], gk1 = gvec[k0 + 2 * bkk + 1];
                r0.x = (r0.x - mn.x) * rs.x * gk0; r1.x = (r1.x - mn.x) * rs.x * gk1;
                r0.y = (r0.y - mn.y) * rs.y * gk0; r1.y = (r1.y - mn.y) * rs.y * gk1;
                r0.z = (r0.z - mn.z) * rs.z * gk0; r1.z = (r1.z - mn.z) * rs.z * gk1;
                r0.w = (r0.w - mn.w) * rs.w * gk0; r1.w = (r1.w - mn.w) * rs.w * gk1;
            }
            Bs[bkk][bn4 + 0] = pack_h2(r0.x, r1.x);
            Bs[bkk][bn4 + 1] = pack_h2(r0.y, r1.y);
            Bs[bkk][bn4 + 2] = pack_h2(r0.z, r1.z);
            Bs[bkk][bn4 + 3] = pack_h2(r0.w, r1.w);
        }
        __syncthreads();
        unsigned a[2][4];
        #pragma unroll
        for (int i = 0; i < 2; i++) {
            int m = wm * 32 + i * 16;
            a[i][0] = As[m + g    ][q];
            a[i][1] = As[m + g + 8][q];
            a[i][2] = As[m + g    ][q + 4];
            a[i][3] = As[m + g + 8][q + 4];
        }
        #pragma unroll
        for (int nb = 0; nb < 8; nb++) {
            int n = wn * 64 + nb * 8 + g;
            unsigned b0 = Bs[q    ][n];
            unsigned b1 = Bs[q + 4][n];
            mma16(c[0][nb], a[0], b0, b1);
            mma16(c[1][nb], a[1], b0, b1);
        }
        __syncthreads();
    }

    float* Cb = Cmat + (size_t)b * (BIAS ? C_ : 3 * HID) * HW;
    #pragma unroll
    for (int i = 0; i < 2; i++) {
        int m = m0 + wm * 32 + i * 16 + g;
        float bb0 = BIAS ? bias[m] : 0.f;
        float bb8 = BIAS ? bias[m + 8] : 0.f;
        #pragma unroll
        for (int nb = 0; nb < 8; nb++) {
            int n = n0 + wn * 64 + nb * 8 + 2 * q;
            *(float2*)(Cb + (size_t)m * HW + n) =
                make_float2(c[i][nb][0] + bb0, c[i][nb][1] + bb0);
            *(float2*)(Cb + (size_t)(m + 8) * HW + n) =
                make_float2(c[i][nb][2] + bb8, c[i][nb][3] + bb8);
        }
    }
}

// ---------------- 3) depthwise 3x3 conv (4x4 patch per thread) ----------------
__global__ void dwconv44(const float* __restrict__ wq,
                         const float* __restrict__ wk,
                         const float* __restrict__ wv) {
    int idx = blockIdx.x * blockDim.x + threadIdx.x;
    if (idx >= B_ * 3 * HID * 144) return;
    int x0 = (idx % 12) * 4;
    int y0 = ((idx / 12) % 12) * 4;
    int ch = idx / 144;                       // b*3HID + c
    int c  = ch % (3 * HID);
    const float* wsel = (c < HID) ? wq : (c < 2 * HID) ? wk : wv;
    const float* w = wsel + (size_t)(c & (HID - 1)) * 9;
    float w9[9];
    #pragma unroll
    for (int i = 0; i < 9; i++) w9[i] = __ldg(&w[i]);

    const float* ip = g_qkv + (size_t)ch * HW;
    float in[6][6];
    #pragma unroll
    for (int r = 0; r < 6; r++) {
        int y = y0 - 1 + r;
        if (y < 0 || y >= H_) {
            #pragma unroll
            for (int cc = 0; cc < 6; cc++) in[r][cc] = 0.f;
        } else {
            const float* row = ip + y * W_ + x0;
            in[r][0] = (x0 > 0) ? row[-1] : 0.f;
            float4 cv = *(const float4*)(row);
            in[r][1] = cv.x; in[r][2] = cv.y; in[r][3] = cv.z; in[r][4] = cv.w;
            in[r][5] = (x0 + 4 < W_) ? row[4] : 0.f;
        }
    }
    #pragma unroll
    for (int ry = 0; ry < 4; ry++) {
        float4 o;
        float* op = (float*)&o;
        #pragma unroll
        for (int rx = 0; rx < 4; rx++) {
            float acc = 0.f;
            #pragma unroll
            for (int dy = 0; dy < 3; dy++)
                #pragma unroll
                for (int dx = 0; dx < 3; dx++)
                    acc += in[ry + dy][rx + dx] * w9[dy * 3 + dx];
            op[rx] = acc;
        }
        *(float4*)(g_conv + (size_t)ch * HW + (y0 + ry) * W_ + x0) = o;
    }
}

// ---------------- 4) rope via tables + direct fragment packing ----------------
__global__ void __launch_bounds__(256) pack_qkv() {
    const int tl  = blockIdx.x;
    const int sel = blockIdx.y >> 5;
    const int bh  = blockIdx.y & 31;
    const int b = bh >> 3, h = bh & 7;
    const int t = threadIdx.x, w = t >> 5, lane = t & 31;
    const int g = lane >> 2, q = lane & 3;
    const float* cb = g_conv + ((size_t)(b * 3 * HID + sel * HID + h * DH)) * HW;

    if (sel == 2) {
        const int dd = w * 8 + g;
        const float* col = cb + (size_t)dd * HW + tl * 64;
        uint2* dst = ((uint2*)g_vu) + ((size_t)(bh * 36 + tl)) * 1024 + w * 128 + lane;
        #pragma unroll
        for (int ks = 0; ks < 4; ks++) {
            float2 v0 = *(const float2*)(col + 16 * ks + 2 * q);
            float2 v1 = *(const float2*)(col + 16 * ks + 8 + 2 * q);
            dst[ks * 32] = make_uint2(pack_h2(v0.x, v0.y), pack_h2(v1.x, v1.y));
        }
    } else if (sel == 1) {
        const int nb = w;
        const int s = tl * 64 + nb * 8 + g;
        float xv[4][2][2];
        #pragma unroll
        for (int hi = 0; hi < 4; hi++)
            #pragma unroll
            for (int bb = 0; bb < 2; bb++) {
                int dd = 16 * hi + 8 * bb + 2 * q;
                xv[hi][bb][0] = cb[(size_t)dd * HW + s];
                xv[hi][bb][1] = cb[(size_t)(dd + 1) * HW + s];
            }
        float2 cT[2][2], sT[2][2];
        #pragma unroll
        for (int k1 = 0; k1 < 2; k1++)
            #pragma unroll
            for (int bb = 0; bb < 2; bb++) {
                int j = 16 * k1 + 8 * bb + 2 * q;
                cT[k1][bb] = *(const float2*)(g_cosT + s * 32 + j);
                sT[k1][bb] = *(const float2*)(g_sinT + s * 32 + j);
            }
        uint2* dst = ((uint2*)g_ku) + ((size_t)(bh * 36 + tl)) * 1024 + nb * 128 + lane;
        #pragma unroll
        for (int ks = 0; ks < 4; ks++) {
            int k1 = ks & 1;
            unsigned uu[2];
            #pragma unroll
            for (int bb = 0; bb < 2; bb++) {
                float v[2];
                #pragma unroll
                for (int e = 0; e < 2; e++) {
                    float cc = e ? cT[k1][bb].y : cT[k1][bb].x;
                    float ss = e ? sT[k1][bb].y : sT[k1][bb].x;
                    float t1 = xv[ks][bb][e], t2 = xv[ks ^ 2][bb][e];
                    v[e] = (ks < 2) ? (t1 * cc - t2 * ss) : (t1 * cc + t2 * ss);
                }
                uu[bb] = pack_h2(v[0], v[1]);
            }
            dst[ks * 32] = make_uint2(uu[0], uu[1]);
        }
    } else {
        const int p = w >> 2;
        const int r16 = tl * 4 + (w & 3);
        const int s0 = r16 * 16 + g;
        float xv[2][2][2][2];
        #pragma unroll
        for (int kk = 0; kk < 2; kk++)
            #pragma unroll
            for (int hiK = 0; hiK < 2; hiK++)
                #pragma unroll
                for (int e = 0; e < 2; e++) {
                    int dd = 16 * (p + 2 * kk) + 8 * hiK + 2 * q + e;
                    const float* rowp = cb + (size_t)dd * HW;
                    xv[kk][hiK][e][0] = rowp[s0];
                    xv[kk][hiK][e][1] = rowp[s0 + 8];
                }
        float2 cT[2][2], sT[2][2];
        #pragma unroll
        for (int hiK = 0; hiK < 2; hiK++)
            #pragma unroll
            for (int si = 0; si < 2; si++) {
                int j = 16 * p + 8 * hiK + 2 * q;
                int off = (s0 + 8 * si) * 32 + j;
                cT[hiK][si] = *(const float2*)(g_cosT + off);
                sT[hiK][si] = *(const float2*)(g_sinT + off);
            }
        const float QS = SCALEF * LOG2E;
        uint4* dst = g_qu + ((size_t)(bh * 144 + r16)) * 4 * 32 + lane;
        #pragma unroll
        for (int kk = 0; kk < 2; kk++) {
            unsigned r[4];
            #pragma unroll
            for (int hiK = 0; hiK < 2; hiK++)
                #pragma unroll
                for (int si = 0; si < 2; si++) {
                    float v[2];
                    #pragma unroll
                    for (int e = 0; e < 2; e++) {
                        float cc = e ? cT[hiK][si].y : cT[hiK][si].x;
                        float ss = e ? sT[hiK][si].y : sT[hiK][si].x;
                        float t1 = xv[kk][hiK][e][si], t2 = xv[kk ^ 1][hiK][e][si];
                        float vv = (kk == 0) ? (t1 * cc - t2 * ss) : (t1 * cc + t2 * ss);
                        v[e] = vv * QS;
                    }
                    r[si + 2 * hiK] = pack_h2(v[0], v[1]);
                }
            dst[(p + 2 * kk) * 32] = make_uint4(r[0], r[1], r[2], r[3]);
        }
    }
}

// ---------------- 5) flash attention: 256 threads / 256 q rows per CTA ----------------
__global__ void __launch_bounds__(256) flash_tc() {
    __shared__ uint4 KV[2][1024];   // [stage][ K:0..511 | V:512..1023 ]
    const int b = blockIdx.z, h = blockIdx.y;
    const int bh = b * HEADS + h;
    const int w    = threadIdx.x >> 5, lane = threadIdx.x & 31;
    const int q    = lane & 3, g = lane >> 2;
    const int grp0 = blockIdx.x * 16 + w * 2;

    uint4 qa[2][4];
    {
        const uint4* qf = g_qu + (size_t)(bh * 144) * 4 * 32;
        #pragma unroll
        for (int h2 = 0; h2 < 2; h2++)
            #pragma unroll
            for (int ks = 0; ks < 4; ks++)
                qa[h2][ks] = qf[(size_t)((grp0 + h2) * 4 + ks) * 32 + lane];
    }

    float o[2][8][4] = {};
    float m0[2] = {-1e30f, -1e30f}, m1[2] = {-1e30f, -1e30f};
    float l0[2] = {0.f, 0.f}, l1[2] = {0.f, 0.f};

    const uint4* kg = g_ku + (size_t)(bh * 36) * 512;
    const uint4* vg = g_vu + (size_t)(bh * 36) * 512;

    #pragma unroll
    for (int i = 0; i < 2; i++) {
        int e = threadIdx.x + 256 * i;
        cp16(smem_u32(&KV[0][e]),       kg + e);
        cp16(smem_u32(&KV[0][512 + e]), vg + e);
    }
    cp_commit();

    for (int t = 0; t < 36; t++) {
        const int cur = t & 1;
        if (t + 1 < 36) {
            const int nxt = cur ^ 1;
            #pragma unroll
            for (int i = 0; i < 2; i++) {
                int e = threadIdx.x + 256 * i;
                cp16(smem_u32(&KV[nxt][e]),       kg + (size_t)(t + 1) * 512 + e);
                cp16(smem_u32(&KV[nxt][512 + e]), vg + (size_t)(t + 1) * 512 + e);
            }
            cp_commit();
            cp_wait<1>();
        } else {
            cp_wait<0>();
        }
        __syncthreads();
        const uint2* Ku = (const uint2*)(KV[cur]);
        const uint2* Vu = (const uint2*)(KV[cur] + 512);

        // ---- S = Q K^T ----
        float s[2][8][4] = {};
        #pragma unroll
        for (int nb = 0; nb < 8; nb++) {
            #pragma unroll
            for (int ks = 0; ks < 4; ks++) {
                uint2 bb = Ku[(nb * 4 + ks) * 32 + lane];
                mma16(s[0][nb], (const unsigned*)&qa[0][ks], bb.x, bb.y);
                mma16(s[1][nb], (const unsigned*)&qa[1][ks], bb.x, bb.y);
            }
        }

        // ---- online softmax ----
        #pragma unroll
        for (int h2 = 0; h2 < 2; h2++) {
            float mx0 = -1e30f, mx1 = -1e30f;
            #pragma unroll
            for (int nb = 0; nb < 8; nb++) {
                mx0 = fmaxf(mx0, fmaxf(s[h2][nb][0], s[h2][nb][1]));
                mx1 = fmaxf(mx1, fmaxf(s[h2][nb][2], s[h2][nb][3]));
            }
            mx0 = fmaxf(mx0, __shfl_xor_sync(0xffffffffu, mx0, 1));
            mx0 = fmaxf(mx0, __shfl_xor_sync(0xffffffffu, mx0, 2));
            mx1 = fmaxf(mx1, __shfl_xor_sync(0xffffffffu, mx1, 1));
            mx1 = fmaxf(mx1, __shfl_xor_sync(0xffffffffu, mx1, 2));
            float nm0 = fmaxf(m0[h2], mx0), nm1 = fmaxf(m1[h2], mx1);
            bool nochg = (nm0 == m0[h2]) && (nm1 == m1[h2]);
            if (!__all_sync(0xffffffffu, nochg)) {
                float cf0 = exp2f(m0[h2] - nm0), cf1 = exp2f(m1[h2] - nm1);
                m0[h2] = nm0; m1[h2] = nm1;
                l0[h2] *= cf0; l1[h2] *= cf1;
                #pragma unroll
                for (int nb = 0; nb < 8; nb++) {
                    o[h2][nb][0] *= cf0; o[h2][nb][1] *= cf0;
                    o[h2][nb][2] *= cf1; o[h2][nb][3] *= cf1;
                }
            }
            #pragma unroll
            for (int nb = 0; nb < 8; nb++) {
                float p0 = exp2f(s[h2][nb][0] - nm0);
                float p1 = exp2f(s[h2][nb][1] - nm0);
                float p2 = exp2f(s[h2][nb][2] - nm1);
                float p3 = exp2f(s[h2][nb][3] - nm1);
                l0[h2] += p0 + p1; l1[h2] += p2 + p3;
                s[h2][nb][0] = p0; s[h2][nb][1] = p1;
                s[h2][nb][2] = p2; s[h2][nb][3] = p3;
            }
        }

        // ---- O += P V ----
        #pragma unroll
        for (int ks = 0; ks < 4; ks++) {
            unsigned a[2][4];
            #pragma unroll
            for (int h2 = 0; h2 < 2; h2++) {
                a[h2][0] = pack_h2(s[h2][2 * ks    ][0], s[h2][2 * ks    ][1]);
                a[h2][1] = pack_h2(s[h2][2 * ks    ][2], s[h2][2 * ks    ][3]);
                a[h2][2] = pack_h2(s[h2][2 * ks + 1][0], s[h2][2 * ks + 1][1]);
                a[h2][3] = pack_h2(s[h2][2 * ks + 1][2], s[h2][2 * ks + 1][3]);
            }
            #pragma unroll
            for (int nb2 = 0; nb2 < 8; nb2++) {
                uint2 bb = Vu[(nb2 * 4 + ks) * 32 + lane];
                mma16(o[0][nb2], a[0], bb.x, bb.y);
                mma16(o[1][nb2], a[1], bb.x, bb.y);
            }
        }
        __syncthreads();
    }

    #pragma unroll
    for (int h2 = 0; h2 < 2; h2++) {
        float L0 = l0[h2];
        L0 += __shfl_xor_sync(0xffffffffu, L0, 1);
        L0 += __shfl_xor_sync(0xffffffffu, L0, 2);
        float L1 = l1[h2];
        L1 += __shfl_xor_sync(0xffffffffu, L1, 1);
        L1 += __shfl_xor_sync(0xffffffffu, L1, 2);
        float inv0 = 1.f / L0, inv1 = 1.f / L1;
        int r0 = (grp0 + h2) * 16 + g;
        float* base = g_oT + ((size_t)b * HID + h * DH) * HW;
        #pragma unroll
        for (int nb2 = 0; nb2 < 8; nb2++) {
            int col = nb2 * 8 + 2 * q;
            base[(size_t)(col    ) * HW + r0    ] = o[h2][nb2][0] * inv0;
            base[(size_t)(col + 1) * HW + r0    ] = o[h2][nb2][1] * inv0;
            base[(size_t)(col    ) * HW + r0 + 8] = o[h2][nb2][2] * inv1;
            base[(size_t)(col + 1) * HW + r0 + 8] = o[h2][nb2][3] * inv1;
        }
    }
}

// ---------------- launcher ----------------
extern "C" void kernel_launch(void* const* d_in, const int* in_sizes, int n_in,
                              void* d_out, int out_size) {
    const float* x      = (const float*)d_in[0];
    const float* norm_g = (const float*)d_in[1];
    const float* w_qkv  = (const float*)d_in[2];
    const float* dw_q   = (const float*)d_in[3];
    const float* dw_k   = (const float*)d_in[4];
    const float* dw_v   = (const float*)d_in[5];
    const float* w_out  = (const float*)d_in[6];
    const float* b_out  = (const float*)d_in[7];
    float* out = (float*)d_out;

    float* qkv; cudaGetSymbolAddress((void**)&qkv, g_qkv);
    float* oT;  cudaGetSymbolAddress((void**)&oT,  g_oT);

    ln_stats<<<(B_ * HW + 127) / 128, 128>>>(x);
    rope_tab<<<(S_ * 32 + 255) / 256, 256>>>();
    gemm_tc<C_, false, true><<<dim3(HW / 128, 3 * HID / 128, B_), 256>>>(w_qkv, x, qkv, nullptr, norm_g);
    dwconv44<<<(B_ * 3 * HID * 144 + 255) / 256, 256>>>(dw_q, dw_k, dw_v);
    pack_qkv<<<dim3(36, 96), 256>>>();
    flash_tc<<<dim3(S_ / 256, HEADS, B_), 256>>>();
    gemm_tc<HID, true, false><<<dim3(HW / 128, C_ / 128, B_), 256>>>(w_out, oT, out, b_out, nullptr);
}

// round 8
// speedup vs baseline: 7.6461x; 1.0649x over previous
#include <cuda_runtime.h>
#include <cuda_fp16.h>

#define B_   4
#define C_   256
#define H_   48
#define W_   48
#define HW   2304
#define HEADS 8
#define DH   64
#define HID  512
#define S_   2304
#define EPSF 1e-5f
#define SCALEF 0.125f
#define LOG2E 1.4426950408889634f
#define LOG2_10000 13.287712379549449f

// ---------------- scratch ----------------
__device__ float  g_mean[B_*HW];
__device__ float  g_rstd[B_*HW];
__device__ float  g_qkv [B_*3*HID*HW];
__device__ float  g_conv[B_*3*HID*HW];
__device__ float  g_cosT[S_*32];
__device__ float  g_sinT[S_*32];
__device__ uint4  g_qu  [32*144*4*32];   // Q  A-frags fp16
__device__ uint4  g_ku  [32*36*512];     // K  B-frags fp16 (8KB/tile)
__device__ uint4  g_vu  [32*36*512];     // V  B-frags fp16
__device__ float  g_oT  [B_*HID*HW];     // attention out, channel-major [b][c][s]

__device__ __forceinline__ unsigned pack_h2(float lo, float hi) {
    unsigned u;
    asm("cvt.rn.f16x2.f32 %0, %1, %2;" : "=r"(u) : "f"(hi), "f"(lo));
    return u;
}

__device__ __forceinline__ void mma16(float* c, const unsigned* a, unsigned b0, unsigned b1) {
    asm("mma.sync.aligned.m16n8k16.row.col.f32.f16.f16.f32 "
        "{%0,%1,%2,%3},{%4,%5,%6,%7},{%8,%9},{%0,%1,%2,%3};"
        : "+f"(c[0]), "+f"(c[1]), "+f"(c[2]), "+f"(c[3])
        : "r"(a[0]), "r"(a[1]), "r"(a[2]), "r"(a[3]), "r"(b0), "r"(b1));
}

__device__ __forceinline__ unsigned smem_u32(const void* p) {
    return (unsigned)__cvta_generic_to_shared(p);
}
__device__ __forceinline__ void cp16(unsigned dst, const void* src) {
    asm volatile("cp.async.cg.shared.global [%0], [%1], 16;" :: "r"(dst), "l"(src));
}
__device__ __forceinline__ void cp_commit() {
    asm volatile("cp.async.commit_group;");
}
template<int N>
__device__ __forceinline__ void cp_wait() {
    asm volatile("cp.async.wait_group %0;" :: "n"(N));
}

// ---------------- 1) layernorm stats ----------------
__global__ void ln_stats(const float* __restrict__ x) {
    int idx = blockIdx.x * blockDim.x + threadIdx.x;
    if (idx >= B_ * HW) return;
    const float* xp = x + (size_t)(idx / HW) * C_ * HW + (idx % HW);
    float s0 = 0.f, s1 = 0.f, s2 = 0.f, s3 = 0.f;
    float q0 = 0.f, q1 = 0.f, q2 = 0.f, q3 = 0.f;
    #pragma unroll 4
    for (int c = 0; c < C_; c += 4) {
        float v0 = xp[(size_t)(c + 0) * HW];
        float v1 = xp[(size_t)(c + 1) * HW];
        float v2 = xp[(size_t)(c + 2) * HW];
        float v3 = xp[(size_t)(c + 3) * HW];
        s0 += v0; q0 += v0 * v0;
        s1 += v1; q1 += v1 * v1;
        s2 += v2; q2 += v2 * v2;
        s3 += v3; q3 += v3 * v3;
    }
    float mean = (s0 + s1 + s2 + s3) * (1.f / C_);
    float var  = (q0 + q1 + q2 + q3) * (1.f / C_) - mean * mean;
    g_mean[idx] = mean;
    g_rstd[idx] = rsqrtf(var + EPSF);
}

// ---------------- rope cos/sin tables ----------------
__global__ void rope_tab() {
    int idx = blockIdx.x * blockDim.x + threadIdx.x;
    if (idx >= S_ * 32) return;
    int s = idx >> 5, j = idx & 31;
    float invf = exp2f(-((float)(2 * j) * (1.0f / 64.0f)) * LOG2_10000);
    float a = (float)s * invf;
    float sa, ca;
    sincosf(a, &sa, &ca);
    g_cosT[idx] = ca;
    g_sinT[idx] = sa;
}

// ---------------- 2/6) fp16 TC GEMM with register-prefetch pipeline ----------------
template<int KD, bool BIAS, bool LN>
__global__ void __launch_bounds__(256) gemm_tc(const float* __restrict__ A,
                                               const float* __restrict__ Bmat,
                                               float* __restrict__ Cmat,
                                               const float* __restrict__ bias,
                                               const float* __restrict__ gvec) {
    __shared__ unsigned As[128][12];
    __shared__ unsigned Bs[8][136];
    const int b  = blockIdx.z;
    const int n0 = blockIdx.x * 128, m0 = blockIdx.y * 128;
    const int tid = threadIdx.x;
    const int w = tid >> 5, lane = tid & 31;
    const int wm = w >> 1, wn = w & 1;
    const int g = lane >> 2, q = lane & 3;
    const float* Bb = Bmat + (size_t)b * KD * HW;
    float c[2][8][4] = {};
    const int am = tid >> 1, apart = tid & 1;
    const int bkk = tid >> 5, bn4 = (tid & 31) * 4;

    float4 mn, rs;
    if (LN) {
        mn = *(const float4*)(g_mean + (size_t)b * HW + n0 + bn4);
        rs = *(const float4*)(g_rstd + (size_t)b * HW + n0 + bn4);
    }

    const float* apBase = A + (size_t)(m0 + am) * KD + 8 * apart;
    const float* bpBase = Bb + (size_t)(2 * bkk) * HW + n0 + bn4;

    // prefetch k-block 0 into registers
    float4 av0 = *(const float4*)(apBase);
    float4 av1 = *(const float4*)(apBase + 4);
    float4 r0  = *(const float4*)(bpBase);
    float4 r1  = *(const float4*)(bpBase + HW);
    float gk0 = 0.f, gk1 = 0.f;
    if (LN) { gk0 = gvec[2 * bkk]; gk1 = gvec[2 * bkk + 1]; }

    for (int k0 = 0; k0 < KD; k0 += 16) {
        // pack current block into smem
        {
            uint4 u;
            u.x = pack_h2(av0.x, av0.y); u.y = pack_h2(av0.z, av0.w);
            u.z = pack_h2(av1.x, av1.y); u.w = pack_h2(av1.z, av1.w);
            *(uint4*)(&As[am][4 * apart]) = u;
        }
        {
            float4 s0 = r0, s1 = r1;
            if (LN) {
                s0.x = (s0.x - mn.x) * rs.x * gk0; s1.x = (s1.x - mn.x) * rs.x * gk1;
                s0.y = (s0.y - mn.y) * rs.y * gk0; s1.y = (s1.y - mn.y) * rs.y * gk1;
                s0.z = (s0.z - mn.z) * rs.z * gk0; s1.z = (s1.z - mn.z) * rs.z * gk1;
                s0.w = (s0.w - mn.w) * rs.w * gk0; s1.w = (s1.w - mn.w) * rs.w * gk1;
            }
            Bs[bkk][bn4 + 0] = pack_h2(s0.x, s1.x);
            Bs[bkk][bn4 + 1] = pack_h2(s0.y, s1.y);
            Bs[bkk][bn4 + 2] = pack_h2(s0.z, s1.z);
            Bs[bkk][bn4 + 3] = pack_h2(s0.w, s1.w);
        }
        __syncthreads();

        // prefetch next k-block (overlaps with MMAs below)
        if (k0 + 16 < KD) {
            const float* ap = apBase + k0 + 16;
            av0 = *(const float4*)(ap);
            av1 = *(const float4*)(ap + 4);
            const float* bp = bpBase + (size_t)(k0 + 16) * HW;
            r0 = *(const float4*)(bp);
            r1 = *(const float4*)(bp + HW);
            if (LN) { gk0 = gvec[k0 + 16 + 2 * bkk]; gk1 = gvec[k0 + 17 + 2 * bkk]; }
        }

        unsigned a[2][4];
        #pragma unroll
        for (int i = 0; i < 2; i++) {
            int m = wm * 32 + i * 16;
            a[i][0] = As[m + g    ][q];
            a[i][1] = As[m + g + 8][q];
            a[i][2] = As[m + g    ][q + 4];
            a[i][3] = As[m + g + 8][q + 4];
        }
        #pragma unroll
        for (int nb = 0; nb < 8; nb++) {
            int n = wn * 64 + nb * 8 + g;
            unsigned b0 = Bs[q    ][n];
            unsigned b1 = Bs[q + 4][n];
            mma16(c[0][nb], a[0], b0, b1);
            mma16(c[1][nb], a[1], b0, b1);
        }
        __syncthreads();
    }

    float* Cb = Cmat + (size_t)b * (BIAS ? C_ : 3 * HID) * HW;
    #pragma unroll
    for (int i = 0; i < 2; i++) {
        int m = m0 + wm * 32 + i * 16 + g;
        float bb0 = BIAS ? bias[m] : 0.f;
        float bb8 = BIAS ? bias[m + 8] : 0.f;
        #pragma unroll
        for (int nb = 0; nb < 8; nb++) {
            int n = n0 + wn * 64 + nb * 8 + 2 * q;
            *(float2*)(Cb + (size_t)m * HW + n) =
                make_float2(c[i][nb][0] + bb0, c[i][nb][1] + bb0);
            *(float2*)(Cb + (size_t)(m + 8) * HW + n) =
                make_float2(c[i][nb][2] + bb8, c[i][nb][3] + bb8);
        }
    }
}

// ---------------- 3) depthwise 3x3 conv (4x4 patch per thread) ----------------
__global__ void dwconv44(const float* __restrict__ wq,
                         const float* __restrict__ wk,
                         const float* __restrict__ wv) {
    int idx = blockIdx.x * blockDim.x + threadIdx.x;
    if (idx >= B_ * 3 * HID * 144) return;
    int x0 = (idx % 12) * 4;
    int y0 = ((idx / 12) % 12) * 4;
    int ch = idx / 144;
    int c  = ch % (3 * HID);
    const float* wsel = (c < HID) ? wq : (c < 2 * HID) ? wk : wv;
    const float* w = wsel + (size_t)(c & (HID - 1)) * 9;
    float w9[9];
    #pragma unroll
    for (int i = 0; i < 9; i++) w9[i] = __ldg(&w[i]);

    const float* ip = g_qkv + (size_t)ch * HW;
    float in[6][6];
    #pragma unroll
    for (int r = 0; r < 6; r++) {
        int y = y0 - 1 + r;
        if (y < 0 || y >= H_) {
            #pragma unroll
            for (int cc = 0; cc < 6; cc++) in[r][cc] = 0.f;
        } else {
            const float* row = ip + y * W_ + x0;
            in[r][0] = (x0 > 0) ? row[-1] : 0.f;
            float4 cv = *(const float4*)(row);
            in[r][1] = cv.x; in[r][2] = cv.y; in[r][3] = cv.z; in[r][4] = cv.w;
            in[r][5] = (x0 + 4 < W_) ? row[4] : 0.f;
        }
    }
    #pragma unroll
    for (int ry = 0; ry < 4; ry++) {
        float4 o;
        float* op = (float*)&o;
        #pragma unroll
        for (int rx = 0; rx < 4; rx++) {
            float acc = 0.f;
            #pragma unroll
            for (int dy = 0; dy < 3; dy++)
                #pragma unroll
                for (int dx = 0; dx < 3; dx++)
                    acc += in[ry + dy][rx + dx] * w9[dy * 3 + dx];
            op[rx] = acc;
        }
        *(float4*)(g_conv + (size_t)ch * HW + (y0 + ry) * W_ + x0) = o;
    }
}

// ---------------- 4) rope via tables + direct fragment packing ----------------
__global__ void __launch_bounds__(256) pack_qkv() {
    const int tl  = blockIdx.x;
    const int sel = blockIdx.y >> 5;
    const int bh  = blockIdx.y & 31;
    const int b = bh >> 3, h = bh & 7;
    const int t = threadIdx.x, w = t >> 5, lane = t & 31;
    const int g = lane >> 2, q = lane & 3;
    const float* cb = g_conv + ((size_t)(b * 3 * HID + sel * HID + h * DH)) * HW;

    if (sel == 2) {
        const int dd = w * 8 + g;
        const float* col = cb + (size_t)dd * HW + tl * 64;
        uint2* dst = ((uint2*)g_vu) + ((size_t)(bh * 36 + tl)) * 1024 + w * 128 + lane;
        #pragma unroll
        for (int ks = 0; ks < 4; ks++) {
            float2 v0 = *(const float2*)(col + 16 * ks + 2 * q);
            float2 v1 = *(const float2*)(col + 16 * ks + 8 + 2 * q);
            dst[ks * 32] = make_uint2(pack_h2(v0.x, v0.y), pack_h2(v1.x, v1.y));
        }
    } else if (sel == 1) {
        const int nb = w;
        const int s = tl * 64 + nb * 8 + g;
        float xv[4][2][2];
        #pragma unroll
        for (int hi = 0; hi < 4; hi++)
            #pragma unroll
            for (int bb = 0; bb < 2; bb++) {
                int dd = 16 * hi + 8 * bb + 2 * q;
                xv[hi][bb][0] = cb[(size_t)dd * HW + s];
                xv[hi][bb][1] = cb[(size_t)(dd + 1) * HW + s];
            }
        float2 cT[2][2], sT[2][2];
        #pragma unroll
        for (int k1 = 0; k1 < 2; k1++)
            #pragma unroll
            for (int bb = 0; bb < 2; bb++) {
                int j = 16 * k1 + 8 * bb + 2 * q;
                cT[k1][bb] = *(const float2*)(g_cosT + s * 32 + j);
                sT[k1][bb] = *(const float2*)(g_sinT + s * 32 + j);
            }
        uint2* dst = ((uint2*)g_ku) + ((size_t)(bh * 36 + tl)) * 1024 + nb * 128 + lane;
        #pragma unroll
        for (int ks = 0; ks < 4; ks++) {
            int k1 = ks & 1;
            unsigned uu[2];
            #pragma unroll
            for (int bb = 0; bb < 2; bb++) {
                float v[2];
                #pragma unroll
                for (int e = 0; e < 2; e++) {
                    float cc = e ? cT[k1][bb].y : cT[k1][bb].x;
                    float ss = e ? sT[k1][bb].y : sT[k1][bb].x;
                    float t1 = xv[ks][bb][e], t2 = xv[ks ^ 2][bb][e];
                    v[e] = (ks < 2) ? (t1 * cc - t2 * ss) : (t1 * cc + t2 * ss);
                }
                uu[bb] = pack_h2(v[0], v[1]);
            }
            dst[ks * 32] = make_uint2(uu[0], uu[1]);
        }
    } else {
        const int p = w >> 2;
        const int r16 = tl * 4 + (w & 3);
        const int s0 = r16 * 16 + g;
        float xv[2][2][2][2];
        #pragma unroll
        for (int kk = 0; kk < 2; kk++)
            #pragma unroll
            for (int hiK = 0; hiK < 2; hiK++)
                #pragma unroll
                for (int e = 0; e < 2; e++) {
                    int dd = 16 * (p + 2 * kk) + 8 * hiK + 2 * q + e;
                    const float* rowp = cb + (size_t)dd * HW;
                    xv[kk][hiK][e][0] = rowp[s0];
                    xv[kk][hiK][e][1] = rowp[s0 + 8];
                }
        float2 cT[2][2], sT[2][2];
        #pragma unroll
        for (int hiK = 0; hiK < 2; hiK++)
            #pragma unroll
            for (int si = 0; si < 2; si++) {
                int j = 16 * p + 8 * hiK + 2 * q;
                int off = (s0 + 8 * si) * 32 + j;
                cT[hiK][si] = *(const float2*)(g_cosT + off);
                sT[hiK][si] = *(const float2*)(g_sinT + off);
            }
        const float QS = SCALEF * LOG2E;
        uint4* dst = g_qu + ((size_t)(bh * 144 + r16)) * 4 * 32 + lane;
        #pragma unroll
        for (int kk = 0; kk < 2; kk++) {
            unsigned r[4];
            #pragma unroll
            for (int hiK = 0; hiK < 2; hiK++)
                #pragma unroll
                for (int si = 0; si < 2; si++) {
                    float v[2];
                    #pragma unroll
                    for (int e = 0; e < 2; e++) {
                        float cc = e ? cT[hiK][si].y : cT[hiK][si].x;
                        float ss = e ? sT[hiK][si].y : sT[hiK][si].x;
                        float t1 = xv[kk][hiK][e][si], t2 = xv[kk ^ 1][hiK][e][si];
                        float vv = (kk == 0) ? (t1 * cc - t2 * ss) : (t1 * cc + t2 * ss);
                        v[e] = vv * QS;
                    }
                    r[si + 2 * hiK] = pack_h2(v[0], v[1]);
                }
            dst[(p + 2 * kk) * 32] = make_uint4(r[0], r[1], r[2], r[3]);
        }
    }
}

// ---------------- 5) flash attention: fp16 MMA + cp.async double buffer (128 thr) ----------------
__global__ void __launch_bounds__(128) flash_tc() {
    __shared__ uint4 KV[2][1024];
    const int b = blockIdx.z, h = blockIdx.y;
    const int bh = b * HEADS + h;
    const int w    = threadIdx.x >> 5, lane = threadIdx.x & 31;
    const int q    = lane & 3, g = lane >> 2;
    const int grp0 = blockIdx.x * 8 + w * 2;

    uint4 qa[2][4];
    {
        const uint4* qf = g_qu + (size_t)(bh * 144) * 4 * 32;
        #pragma unroll
        for (int h2 = 0; h2 < 2; h2++)
            #pragma unroll
            for (int ks = 0; ks < 4; ks++)
                qa[h2][ks] = qf[(size_t)((grp0 + h2) * 4 + ks) * 32 + lane];
    }

    float o[2][8][4] = {};
    float m0[2] = {-1e30f, -1e30f}, m1[2] = {-1e30f, -1e30f};
    float l0[2] = {0.f, 0.f}, l1[2] = {0.f, 0.f};

    const uint4* kg = g_ku + (size_t)(bh * 36) * 512;
    const uint4* vg = g_vu + (size_t)(bh * 36) * 512;

    #pragma unroll
    for (int i = 0; i < 4; i++) {
        int e = threadIdx.x + 128 * i;
        cp16(smem_u32(&KV[0][e]),       kg + e);
        cp16(smem_u32(&KV[0][512 + e]), vg + e);
    }
    cp_commit();

    for (int t = 0; t < 36; t++) {
        const int cur = t & 1;
        if (t + 1 < 36) {
            const int nxt = cur ^ 1;
            #pragma unroll
            for (int i = 0; i < 4; i++) {
                int e = threadIdx.x + 128 * i;
                cp16(smem_u32(&KV[nxt][e]),       kg + (size_t)(t + 1) * 512 + e);
                cp16(smem_u32(&KV[nxt][512 + e]), vg + (size_t)(t + 1) * 512 + e);
            }
            cp_commit();
            cp_wait<1>();
        } else {
            cp_wait<0>();
        }
        __syncthreads();
        const uint2* Ku = (const uint2*)(KV[cur]);
        const uint2* Vu = (const uint2*)(KV[cur] + 512);

        float s[2][8][4] = {};
        #pragma unroll
        for (int nb = 0; nb < 8; nb++) {
            #pragma unroll
            for (int ks = 0; ks < 4; ks++) {
                uint2 bb = Ku[(nb * 4 + ks) * 32 + lane];
                mma16(s[0][nb], (const unsigned*)&qa[0][ks], bb.x, bb.y);
                mma16(s[1][nb], (const unsigned*)&qa[1][ks], bb.x, bb.y);
            }
        }

        #pragma unroll
        for (int h2 = 0; h2 < 2; h2++) {
            float mx0 = -1e30f, mx1 = -1e30f;
            #pragma unroll
            for (int nb = 0; nb < 8; nb++) {
                mx0 = fmaxf(mx0, fmaxf(s[h2][nb][0], s[h2][nb][1]));
                mx1 = fmaxf(mx1, fmaxf(s[h2][nb][2], s[h2][nb][3]));
            }
            mx0 = fmaxf(mx0, __shfl_xor_sync(0xffffffffu, mx0, 1));
            mx0 = fmaxf(mx0, __shfl_xor_sync(0xffffffffu, mx0, 2));
            mx1 = fmaxf(mx1, __shfl_xor_sync(0xffffffffu, mx1, 1));
            mx1 = fmaxf(mx1, __shfl_xor_sync(0xffffffffu, mx1, 2));
            float nm0 = fmaxf(m0[h2], mx0), nm1 = fmaxf(m1[h2], mx1);
            float cf0 = exp2f(m0[h2] - nm0), cf1 = exp2f(m1[h2] - nm1);
            m0[h2] = nm0; m1[h2] = nm1;
            l0[h2] *= cf0; l1[h2] *= cf1;
            #pragma unroll
            for (int nb = 0; nb < 8; nb++) {
                o[h2][nb][0] *= cf0; o[h2][nb][1] *= cf0;
                o[h2][nb][2] *= cf1; o[h2][nb][3] *= cf1;
            }
            #pragma unroll
            for (int nb = 0; nb < 8; nb++) {
                float p0 = exp2f(s[h2][nb][0] - nm0);
                float p1 = exp2f(s[h2][nb][1] - nm0);
                float p2 = exp2f(s[h2][nb][2] - nm1);
                float p3 = exp2f(s[h2][nb][3] - nm1);
                l0[h2] += p0 + p1; l1[h2] += p2 + p3;
                s[h2][nb][0] = p0; s[h2][nb][1] = p1;
                s[h2][nb][2] = p2; s[h2][nb][3] = p3;
            }
        }

        #pragma unroll
        for (int ks = 0; ks < 4; ks++) {
            unsigned a[2][4];
            #pragma unroll
            for (int h2 = 0; h2 < 2; h2++) {
                a[h2][0] = pack_h2(s[h2][2 * ks    ][0], s[h2][2 * ks    ][1]);
                a[h2][1] = pack_h2(s[h2][2 * ks    ][2], s[h2][2 * ks    ][3]);
                a[h2][2] = pack_h2(s[h2][2 * ks + 1][0], s[h2][2 * ks + 1][1]);
                a[h2][3] = pack_h2(s[h2][2 * ks + 1][2], s[h2][2 * ks + 1][3]);
            }
            #pragma unroll
            for (int nb2 = 0; nb2 < 8; nb2++) {
                uint2 bb = Vu[(nb2 * 4 + ks) * 32 + lane];
                mma16(o[0][nb2], a[0], bb.x, bb.y);
                mma16(o[1][nb2], a[1], bb.x, bb.y);
            }
        }
        __syncthreads();
    }

    #pragma unroll
    for (int h2 = 0; h2 < 2; h2++) {
        float L0 = l0[h2];
        L0 += __shfl_xor_sync(0xffffffffu, L0, 1);
        L0 += __shfl_xor_sync(0xffffffffu, L0, 2);
        float L1 = l1[h2];
        L1 += __shfl_xor_sync(0xffffffffu, L1, 1);
        L1 += __shfl_xor_sync(0xffffffffu, L1, 2);
        float inv0 = 1.f / L0, inv1 = 1.f / L1;
        int r0 = (grp0 + h2) * 16 + g;
        float* base = g_oT + ((size_t)b * HID + h * DH) * HW;
        #pragma unroll
        for (int nb2 = 0; nb2 < 8; nb2++) {
            int col = nb2 * 8 + 2 * q;
            base[(size_t)(col    ) * HW + r0    ] = o[h2][nb2][0] * inv0;
            base[(size_t)(col + 1) * HW + r0    ] = o[h2][nb2][1] * inv0;
            base[(size_t)(col    ) * HW + r0 + 8] = o[h2][nb2][2] * inv1;
            base[(size_t)(col + 1) * HW + r0 + 8] = o[h2][nb2][3] * inv1;
        }
    }
}

// ---------------- launcher ----------------
extern "C" void kernel_launch(void* const* d_in, const int* in_sizes, int n_in,
                              void* d_out, int out_size) {
    const float* x      = (const float*)d_in[0];
    const float* norm_g = (const float*)d_in[1];
    const float* w_qkv  = (const float*)d_in[2];
    const float* dw_q   = (const float*)d_in[3];
    const float* dw_k   = (const float*)d_in[4];
    const float* dw_v   = (const float*)d_in[5];
    const float* w_out  = (const float*)d_in[6];
    const float* b_out  = (const float*)d_in[7];
    float* out = (float*)d_out;

    float* qkv; cudaGetSymbolAddress((void**)&qkv, g_qkv);
    float* oT;  cudaGetSymbolAddress((void**)&oT,  g_oT);

    ln_stats<<<(B_ * HW + 127) / 128, 128>>>(x);
    rope_tab<<<(S_ * 32 + 255) / 256, 256>>>();
    gemm_tc<C_, false, true><<<dim3(HW / 128, 3 * HID / 128, B_), 256>>>(w_qkv, x, qkv, nullptr, norm_g);
    dwconv44<<<(B_ * 3 * HID * 144 + 255) / 256, 256>>>(dw_q, dw_k, dw_v);
    pack_qkv<<<dim3(36, 96), 256>>>();
    flash_tc<<<dim3(S_ / 128, HEADS, B_), 128>>>();
    gemm_tc<HID, true, false><<<dim3(HW / 128, C_ / 128, B_), 256>>>(w_out, oT, out, b_out, nullptr);
}

// round 9
// speedup vs baseline: 7.7096x; 1.0083x over previous
#include <cuda_runtime.h>
#include <cuda_fp16.h>

#define B_   4
#define C_   256
#define H_   48
#define W_   48
#define HW   2304
#define HEADS 8
#define DH   64
#define HID  512
#define S_   2304
#define EPSF 1e-5f
#define SCALEF 0.125f
#define LOG2E 1.4426950408889634f
#define LOG2_10000 13.287712379549449f

// ---------------- scratch ----------------
__device__ float  g_mean[B_*HW];
__device__ float  g_rstd[B_*HW];
__device__ float  g_qkv [B_*3*HID*HW];
__device__ float  g_conv[B_*3*HID*HW];
__device__ float  g_cosT[S_*32];
__device__ float  g_sinT[S_*32];
__device__ uint4  g_qu  [32*144*4*32];   // Q  A-frags fp16
__device__ uint4  g_ku  [32*36*512];     // K  B-frags fp16 (8KB/tile)
__device__ uint4  g_vu  [32*36*512];     // V  B-frags fp16
__device__ float  g_oT  [B_*HID*HW];     // attention out, channel-major [b][c][s]

__device__ __forceinline__ unsigned pack_h2(float lo, float hi) {
    unsigned u;
    asm("cvt.rn.f16x2.f32 %0, %1, %2;" : "=r"(u) : "f"(hi), "f"(lo));
    return u;
}
__device__ __forceinline__ unsigned ex2h2(unsigned u) {
    unsigned r;
    asm("ex2.approx.f16x2 %0, %1;" : "=r"(r) : "r"(u));
    return r;
}

__device__ __forceinline__ void mma16(float* c, const unsigned* a, unsigned b0, unsigned b1) {
    asm("mma.sync.aligned.m16n8k16.row.col.f32.f16.f16.f32 "
        "{%0,%1,%2,%3},{%4,%5,%6,%7},{%8,%9},{%0,%1,%2,%3};"
        : "+f"(c[0]), "+f"(c[1]), "+f"(c[2]), "+f"(c[3])
        : "r"(a[0]), "r"(a[1]), "r"(a[2]), "r"(a[3]), "r"(b0), "r"(b1));
}

__device__ __forceinline__ unsigned smem_u32(const void* p) {
    return (unsigned)__cvta_generic_to_shared(p);
}
__device__ __forceinline__ void cp16(unsigned dst, const void* src) {
    asm volatile("cp.async.cg.shared.global [%0], [%1], 16;" :: "r"(dst), "l"(src));
}
__device__ __forceinline__ void cp_commit() {
    asm volatile("cp.async.commit_group;");
}
template<int N>
__device__ __forceinline__ void cp_wait() {
    asm volatile("cp.async.wait_group %0;" :: "n"(N));
}

// ---------------- 1) fused: rope tables + layernorm stats ----------------
__global__ void ln_tab(const float* __restrict__ x) {
    int idx = blockIdx.x * blockDim.x + threadIdx.x;
    if (idx < S_ * 32) {
        int s = idx >> 5, j = idx & 31;
        float invf = exp2f(-((float)(2 * j) * (1.0f / 64.0f)) * LOG2_10000);
        float a = (float)s * invf;
        float sa, ca;
        sincosf(a, &sa, &ca);
        g_cosT[idx] = ca;
        g_sinT[idx] = sa;
        return;
    }
    idx -= S_ * 32;
    if (idx >= B_ * HW) return;
    const float* xp = x + (size_t)(idx / HW) * C_ * HW + (idx % HW);
    float s0 = 0.f, s1 = 0.f, s2 = 0.f, s3 = 0.f;
    float q0 = 0.f, q1 = 0.f, q2 = 0.f, q3 = 0.f;
    #pragma unroll 4
    for (int c = 0; c < C_; c += 4) {
        float v0 = xp[(size_t)(c + 0) * HW];
        float v1 = xp[(size_t)(c + 1) * HW];
        float v2 = xp[(size_t)(c + 2) * HW];
        float v3 = xp[(size_t)(c + 3) * HW];
        s0 += v0; q0 += v0 * v0;
        s1 += v1; q1 += v1 * v1;
        s2 += v2; q2 += v2 * v2;
        s3 += v3; q3 += v3 * v3;
    }
    float mean = (s0 + s1 + s2 + s3) * (1.f / C_);
    float var  = (q0 + q1 + q2 + q3) * (1.f / C_) - mean * mean;
    g_mean[idx] = mean;
    g_rstd[idx] = rsqrtf(var + EPSF);
}

// ---------------- 2/6) fp16 TC GEMM with register-prefetch pipeline ----------------
template<int KD, bool BIAS, bool LN>
__global__ void __launch_bounds__(256) gemm_tc(const float* __restrict__ A,
                                               const float* __restrict__ Bmat,
                                               float* __restrict__ Cmat,
                                               const float* __restrict__ bias,
                                               const float* __restrict__ gvec) {
    __shared__ unsigned As[128][12];
    __shared__ unsigned Bs[8][136];
    const int b  = blockIdx.z;
    const int n0 = blockIdx.x * 128, m0 = blockIdx.y * 128;
    const int tid = threadIdx.x;
    const int w = tid >> 5, lane = tid & 31;
    const int wm = w >> 1, wn = w & 1;
    const int g = lane >> 2, q = lane & 3;
    const float* Bb = Bmat + (size_t)b * KD * HW;
    float c[2][8][4] = {};
    const int am = tid >> 1, apart = tid & 1;
    const int bkk = tid >> 5, bn4 = (tid & 31) * 4;

    float4 mn, rs;
    if (LN) {
        mn = *(const float4*)(g_mean + (size_t)b * HW + n0 + bn4);
        rs = *(const float4*)(g_rstd + (size_t)b * HW + n0 + bn4);
    }

    const float* apBase = A + (size_t)(m0 + am) * KD + 8 * apart;
    const float* bpBase = Bb + (size_t)(2 * bkk) * HW + n0 + bn4;

    float4 av0 = *(const float4*)(apBase);
    float4 av1 = *(const float4*)(apBase + 4);
    float4 r0  = *(const float4*)(bpBase);
    float4 r1  = *(const float4*)(bpBase + HW);
    float gk0 = 0.f, gk1 = 0.f;
    if (LN) { gk0 = gvec[2 * bkk]; gk1 = gvec[2 * bkk + 1]; }

    for (int k0 = 0; k0 < KD; k0 += 16) {
        {
            uint4 u;
            u.x = pack_h2(av0.x, av0.y); u.y = pack_h2(av0.z, av0.w);
            u.z = pack_h2(av1.x, av1.y); u.w = pack_h2(av1.z, av1.w);
            *(uint4*)(&As[am][4 * apart]) = u;
        }
        {
            float4 s0 = r0, s1 = r1;
            if (LN) {
                s0.x = (s0.x - mn.x) * rs.x * gk0; s1.x = (s1.x - mn.x) * rs.x * gk1;
                s0.y = (s0.y - mn.y) * rs.y * gk0; s1.y = (s1.y - mn.y) * rs.y * gk1;
                s0.z = (s0.z - mn.z) * rs.z * gk0; s1.z = (s1.z - mn.z) * rs.z * gk1;
                s0.w = (s0.w - mn.w) * rs.w * gk0; s1.w = (s1.w - mn.w) * rs.w * gk1;
            }
            Bs[bkk][bn4 + 0] = pack_h2(s0.x, s1.x);
            Bs[bkk][bn4 + 1] = pack_h2(s0.y, s1.y);
            Bs[bkk][bn4 + 2] = pack_h2(s0.z, s1.z);
            Bs[bkk][bn4 + 3] = pack_h2(s0.w, s1.w);
        }
        __syncthreads();

        if (k0 + 16 < KD) {
            const float* ap = apBase + k0 + 16;
            av0 = *(const float4*)(ap);
            av1 = *(const float4*)(ap + 4);
            const float* bp = bpBase + (size_t)(k0 + 16) * HW;
            r0 = *(const float4*)(bp);
            r1 = *(const float4*)(bp + HW);
            if (LN) { gk0 = gvec[k0 + 16 + 2 * bkk]; gk1 = gvec[k0 + 17 + 2 * bkk]; }
        }

        unsigned a[2][4];
        #pragma unroll
        for (int i = 0; i < 2; i++) {
            int m = wm * 32 + i * 16;
            a[i][0] = As[m + g    ][q];
            a[i][1] = As[m + g + 8][q];
            a[i][2] = As[m + g    ][q + 4];
            a[i][3] = As[m + g + 8][q + 4];
        }
        #pragma unroll
        for (int nb = 0; nb < 8; nb++) {
            int n = wn * 64 + nb * 8 + g;
            unsigned b0 = Bs[q    ][n];
            unsigned b1 = Bs[q + 4][n];
            mma16(c[0][nb], a[0], b0, b1);
            mma16(c[1][nb], a[1], b0, b1);
        }
        __syncthreads();
    }

    float* Cb = Cmat + (size_t)b * (BIAS ? C_ : 3 * HID) * HW;
    #pragma unroll
    for (int i = 0; i < 2; i++) {
        int m = m0 + wm * 32 + i * 16 + g;
        float bb0 = BIAS ? bias[m] : 0.f;
        float bb8 = BIAS ? bias[m + 8] : 0.f;
        #pragma unroll
        for (int nb = 0; nb < 8; nb++) {
            int n = n0 + wn * 64 + nb * 8 + 2 * q;
            *(float2*)(Cb + (size_t)m * HW + n) =
                make_float2(c[i][nb][0] + bb0, c[i][nb][1] + bb0);
            *(float2*)(Cb + (size_t)(m + 8) * HW + n) =
                make_float2(c[i][nb][2] + bb8, c[i][nb][3] + bb8);
        }
    }
}

// ---------------- 3) depthwise 3x3 conv (4x4 patch per thread) ----------------
__global__ void dwconv44(const float* __restrict__ wq,
                         const float* __restrict__ wk,
                         const float* __restrict__ wv) {
    int idx = blockIdx.x * blockDim.x + threadIdx.x;
    if (idx >= B_ * 3 * HID * 144) return;
    int x0 = (idx % 12) * 4;
    int y0 = ((idx / 12) % 12) * 4;
    int ch = idx / 144;
    int c  = ch % (3 * HID);
    const float* wsel = (c < HID) ? wq : (c < 2 * HID) ? wk : wv;
    const float* w = wsel + (size_t)(c & (HID - 1)) * 9;
    float w9[9];
    #pragma unroll
    for (int i = 0; i < 9; i++) w9[i] = __ldg(&w[i]);

    const float* ip = g_qkv + (size_t)ch * HW;
    float in[6][6];
    #pragma unroll
    for (int r = 0; r < 6; r++) {
        int y = y0 - 1 + r;
        if (y < 0 || y >= H_) {
            #pragma unroll
            for (int cc = 0; cc < 6; cc++) in[r][cc] = 0.f;
        } else {
            const float* row = ip + y * W_ + x0;
            in[r][0] = (x0 > 0) ? row[-1] : 0.f;
            float4 cv = *(const float4*)(row);
            in[r][1] = cv.x; in[r][2] = cv.y; in[r][3] = cv.z; in[r][4] = cv.w;
            in[r][5] = (x0 + 4 < W_) ? row[4] : 0.f;
        }
    }
    #pragma unroll
    for (int ry = 0; ry < 4; ry++) {
        float4 o;
        float* op = (float*)&o;
        #pragma unroll
        for (int rx = 0; rx < 4; rx++) {
            float acc = 0.f;
            #pragma unroll
            for (int dy = 0; dy < 3; dy++)
                #pragma unroll
                for (int dx = 0; dx < 3; dx++)
                    acc += in[ry + dy][rx + dx] * w9[dy * 3 + dx];
            op[rx] = acc;
        }
        *(float4*)(g_conv + (size_t)ch * HW + (y0 + ry) * W_ + x0) = o;
    }
}

// ---------------- 4) rope via tables + direct fragment packing ----------------
__global__ void __launch_bounds__(256) pack_qkv() {
    const int tl  = blockIdx.x;
    const int sel = blockIdx.y >> 5;
    const int bh  = blockIdx.y & 31;
    const int b = bh >> 3, h = bh & 7;
    const int t = threadIdx.x, w = t >> 5, lane = t & 31;
    const int g = lane >> 2, q = lane & 3;
    const float* cb = g_conv + ((size_t)(b * 3 * HID + sel * HID + h * DH)) * HW;

    if (sel == 2) {
        const int dd = w * 8 + g;
        const float* col = cb + (size_t)dd * HW + tl * 64;
        uint2* dst = ((uint2*)g_vu) + ((size_t)(bh * 36 + tl)) * 1024 + w * 128 + lane;
        #pragma unroll
        for (int ks = 0; ks < 4; ks++) {
            float2 v0 = *(const float2*)(col + 16 * ks + 2 * q);
            float2 v1 = *(const float2*)(col + 16 * ks + 8 + 2 * q);
            dst[ks * 32] = make_uint2(pack_h2(v0.x, v0.y), pack_h2(v1.x, v1.y));
        }
    } else if (sel == 1) {
        const int nb = w;
        const int s = tl * 64 + nb * 8 + g;
        float xv[4][2][2];
        #pragma unroll
        for (int hi = 0; hi < 4; hi++)
            #pragma unroll
            for (int bb = 0; bb < 2; bb++) {
                int dd = 16 * hi + 8 * bb + 2 * q;
                xv[hi][bb][0] = cb[(size_t)dd * HW + s];
                xv[hi][bb][1] = cb[(size_t)(dd + 1) * HW + s];
            }
        float2 cT[2][2], sT[2][2];
        #pragma unroll
        for (int k1 = 0; k1 < 2; k1++)
            #pragma unroll
            for (int bb = 0; bb < 2; bb++) {
                int j = 16 * k1 + 8 * bb + 2 * q;
                cT[k1][bb] = *(const float2*)(g_cosT + s * 32 + j);
                sT[k1][bb] = *(const float2*)(g_sinT + s * 32 + j);
            }
        uint2* dst = ((uint2*)g_ku) + ((size_t)(bh * 36 + tl)) * 1024 + nb * 128 + lane;
        #pragma unroll
        for (int ks = 0; ks < 4; ks++) {
            int k1 = ks & 1;
            unsigned uu[2];
            #pragma unroll
            for (int bb = 0; bb < 2; bb++) {
                float v[2];
                #pragma unroll
                for (int e = 0; e < 2; e++) {
                    float cc = e ? cT[k1][bb].y : cT[k1][bb].x;
                    float ss = e ? sT[k1][bb].y : sT[k1][bb].x;
                    float t1 = xv[ks][bb][e], t2 = xv[ks ^ 2][bb][e];
                    v[e] = (ks < 2) ? (t1 * cc - t2 * ss) : (t1 * cc + t2 * ss);
                }
                uu[bb] = pack_h2(v[0], v[1]);
            }
            dst[ks * 32] = make_uint2(uu[0], uu[1]);
        }
    } else {
        const int p = w >> 2;
        const int r16 = tl * 4 + (w & 3);
        const int s0 = r16 * 16 + g;
        float xv[2][2][2][2];
        #pragma unroll
        for (int kk = 0; kk < 2; kk++)
            #pragma unroll
            for (int hiK = 0; hiK < 2; hiK++)
                #pragma unroll
                for (int e = 0; e < 2; e++) {
                    int dd = 16 * (p + 2 * kk) + 8 * hiK + 2 * q + e;
                    const float* rowp = cb + (size_t)dd * HW;
                    xv[kk][hiK][e][0] = rowp[s0];
                    xv[kk][hiK][e][1] = rowp[s0 + 8];
                }
        float2 cT[2][2], sT[2][2];
        #pragma unroll
        for (int hiK = 0; hiK < 2; hiK++)
            #pragma unroll
            for (int si = 0; si < 2; si++) {
                int j = 16 * p + 8 * hiK + 2 * q;
                int off = (s0 + 8 * si) * 32 + j;
                cT[hiK][si] = *(const float2*)(g_cosT + off);
                sT[hiK][si] = *(const float2*)(g_sinT + off);
            }
        const float QS = SCALEF * LOG2E;
        uint4* dst = g_qu + ((size_t)(bh * 144 + r16)) * 4 * 32 + lane;
        #pragma unroll
        for (int kk = 0; kk < 2; kk++) {
            unsigned r[4];
            #pragma unroll
            for (int hiK = 0; hiK < 2; hiK++)
                #pragma unroll
                for (int si = 0; si < 2; si++) {
                    float v[2];
                    #pragma unroll
                    for (int e = 0; e < 2; e++) {
                        float cc = e ? cT[hiK][si].y : cT[hiK][si].x;
                        float ss = e ? sT[hiK][si].y : sT[hiK][si].x;
                        float t1 = xv[kk][hiK][e][si], t2 = xv[kk ^ 1][hiK][e][si];
                        float vv = (kk == 0) ? (t1 * cc - t2 * ss) : (t1 * cc + t2 * ss);
                        v[e] = vv * QS;
                    }
                    r[si + 2 * hiK] = pack_h2(v[0], v[1]);
                }
            dst[(p + 2 * kk) * 32] = make_uint4(r[0], r[1], r[2], r[3]);
        }
    }
}

// ---------------- 5) flash attention: fp16 MMA, ex2.f16x2 softmax ----------------
__global__ void __launch_bounds__(128) flash_tc() {
    __shared__ uint4 KV[2][1024];
    const int b = blockIdx.z, h = blockIdx.y;
    const int bh = b * HEADS + h;
    const int w    = threadIdx.x >> 5, lane = threadIdx.x & 31;
    const int q    = lane & 3, g = lane >> 2;
    const int grp0 = blockIdx.x * 8 + w * 2;

    uint4 qa[2][4];
    {
        const uint4* qf = g_qu + (size_t)(bh * 144) * 4 * 32;
        #pragma unroll
        for (int h2 = 0; h2 < 2; h2++)
            #pragma unroll
            for (int ks = 0; ks < 4; ks++)
                qa[h2][ks] = qf[(size_t)((grp0 + h2) * 4 + ks) * 32 + lane];
    }

    float o[2][8][4] = {};
    float m0[2] = {-1e30f, -1e30f}, m1[2] = {-1e30f, -1e30f};
    float l0[2] = {0.f, 0.f}, l1[2] = {0.f, 0.f};

    const uint4* kg = g_ku + (size_t)(bh * 36) * 512;
    const uint4* vg = g_vu + (size_t)(bh * 36) * 512;

    #pragma unroll
    for (int i = 0; i < 4; i++) {
        int e = threadIdx.x + 128 * i;
        cp16(smem_u32(&KV[0][e]),       kg + e);
        cp16(smem_u32(&KV[0][512 + e]), vg + e);
    }
    cp_commit();

    for (int t = 0; t < 36; t++) {
        const int cur = t & 1;
        if (t + 1 < 36) {
            const int nxt = cur ^ 1;
            #pragma unroll
            for (int i = 0; i < 4; i++) {
                int e = threadIdx.x + 128 * i;
                cp16(smem_u32(&KV[nxt][e]),       kg + (size_t)(t + 1) * 512 + e);
                cp16(smem_u32(&KV[nxt][512 + e]), vg + (size_t)(t + 1) * 512 + e);
            }
            cp_commit();
            cp_wait<1>();
        } else {
            cp_wait<0>();
        }
        __syncthreads();
        const uint2* Ku = (const uint2*)(KV[cur]);
        const uint2* Vu = (const uint2*)(KV[cur] + 512);

        // ---- S = Q K^T ----
        float s[2][8][4] = {};
        #pragma unroll
        for (int nb = 0; nb < 8; nb++) {
            #pragma unroll
            for (int ks = 0; ks < 4; ks++) {
                uint2 bb = Ku[(nb * 4 + ks) * 32 + lane];
                mma16(s[0][nb], (const unsigned*)&qa[0][ks], bb.x, bb.y);
                mma16(s[1][nb], (const unsigned*)&qa[1][ks], bb.x, bb.y);
            }
        }

        // ---- online softmax: P computed as packed fp16 via ex2.approx.f16x2 ----
        unsigned pp[2][8][2];   // [h2][nb][pair] -> PV A-frag registers, directly
        #pragma unroll
        for (int h2 = 0; h2 < 2; h2++) {
            float mx0 = -1e30f, mx1 = -1e30f;
            #pragma unroll
            for (int nb = 0; nb < 8; nb++) {
                mx0 = fmaxf(mx0, fmaxf(s[h2][nb][0], s[h2][nb][1]));
                mx1 = fmaxf(mx1, fmaxf(s[h2][nb][2], s[h2][nb][3]));
            }
            mx0 = fmaxf(mx0, __shfl_xor_sync(0xffffffffu, mx0, 1));
            mx0 = fmaxf(mx0, __shfl_xor_sync(0xffffffffu, mx0, 2));
            mx1 = fmaxf(mx1, __shfl_xor_sync(0xffffffffu, mx1, 1));
            mx1 = fmaxf(mx1, __shfl_xor_sync(0xffffffffu, mx1, 2));
            float nm0 = fmaxf(m0[h2], mx0), nm1 = fmaxf(m1[h2], mx1);
            float cf0 = exp2f(m0[h2] - nm0), cf1 = exp2f(m1[h2] - nm1);
            m0[h2] = nm0; m1[h2] = nm1;
            l0[h2] *= cf0; l1[h2] *= cf1;
            #pragma unroll
            for (int nb = 0; nb < 8; nb++) {
                o[h2][nb][0] *= cf0; o[h2][nb][1] *= cf0;
                o[h2][nb][2] *= cf1; o[h2][nb][3] *= cf1;
            }
            #pragma unroll
            for (int nb = 0; nb < 8; nb++) {
                unsigned u0 = ex2h2(pack_h2(s[h2][nb][0] - nm0, s[h2][nb][1] - nm0));
                unsigned u1 = ex2h2(pack_h2(s[h2][nb][2] - nm1, s[h2][nb][3] - nm1));
                pp[h2][nb][0] = u0;
                pp[h2][nb][1] = u1;
                float2 f0 = __half22float2(*reinterpret_cast<__half2*>(&u0));
                float2 f1 = __half22float2(*reinterpret_cast<__half2*>(&u1));
                l0[h2] += f0.x + f0.y;
                l1[h2] += f1.x + f1.y;
            }
        }

        // ---- O += P V  (pp regs are already the fp16 A-frags) ----
        #pragma unroll
        for (int ks = 0; ks < 4; ks++) {
            unsigned a0[4], a1[4];
            a0[0] = pp[0][2 * ks][0]; a0[1] = pp[0][2 * ks][1];
            a0[2] = pp[0][2 * ks + 1][0]; a0[3] = pp[0][2 * ks + 1][1];
            a1[0] = pp[1][2 * ks][0]; a1[1] = pp[1][2 * ks][1];
            a1[2] = pp[1][2 * ks + 1][0]; a1[3] = pp[1][2 * ks + 1][1];
            #pragma unroll
            for (int nb2 = 0; nb2 < 8; nb2++) {
                uint2 bb = Vu[(nb2 * 4 + ks) * 32 + lane];
                mma16(o[0][nb2], a0, bb.x, bb.y);
                mma16(o[1][nb2], a1, bb.x, bb.y);
            }
        }
        __syncthreads();
    }

    #pragma unroll
    for (int h2 = 0; h2 < 2; h2++) {
        float L0 = l0[h2];
        L0 += __shfl_xor_sync(0xffffffffu, L0, 1);
        L0 += __shfl_xor_sync(0xffffffffu, L0, 2);
        float L1 = l1[h2];
        L1 += __shfl_xor_sync(0xffffffffu, L1, 1);
        L1 += __shfl_xor_sync(0xffffffffu, L1, 2);
        float inv0 = 1.f / L0, inv1 = 1.f / L1;
        int r0 = (grp0 + h2) * 16 + g;
        float* base = g_oT + ((size_t)b * HID + h * DH) * HW;
        #pragma unroll
        for (int nb2 = 0; nb2 < 8; nb2++) {
            int col = nb2 * 8 + 2 * q;
            base[(size_t)(col    ) * HW + r0    ] = o[h2][nb2][0] * inv0;
            base[(size_t)(col + 1) * HW + r0    ] = o[h2][nb2][1] * inv0;
            base[(size_t)(col    ) * HW + r0 + 8] = o[h2][nb2][2] * inv1;
            base[(size_t)(col + 1) * HW + r0 + 8] = o[h2][nb2][3] * inv1;
        }
    }
}

// ---------------- launcher ----------------
extern "C" void kernel_launch(void* const* d_in, const int* in_sizes, int n_in,
                              void* d_out, int out_size) {
    const float* x      = (const float*)d_in[0];
    const float* norm_g = (const float*)d_in[1];
    const float* w_qkv  = (const float*)d_in[2];
    const float* dw_q   = (const float*)d_in[3];
    const float* dw_k   = (const float*)d_in[4];
    const float* dw_v   = (const float*)d_in[5];
    const float* w_out  = (const float*)d_in[6];
    const float* b_out  = (const float*)d_in[7];
    float* out = (float*)d_out;

    float* qkv; cudaGetSymbolAddress((void**)&qkv, g_qkv);
    float* oT;  cudaGetSymbolAddress((void**)&oT,  g_oT);

    ln_tab<<<(S_ * 32 + B_ * HW + 255) / 256, 256>>>(x);
    gemm_tc<C_, false, true><<<dim3(HW / 128, 3 * HID / 128, B_), 256>>>(w_qkv, x, qkv, nullptr, norm_g);
    dwconv44<<<(B_ * 3 * HID * 144 + 255) / 256, 256>>>(dw_q, dw_k, dw_v);
    pack_qkv<<<dim3(36, 96), 256>>>();
    flash_tc<<<dim3(S_ / 128, HEADS, B_), 128>>>();
    gemm_tc<HID, true, false><<<dim3(HW / 128, C_ / 128, B_), 256>>>(w_out, oT, out, b_out, nullptr);
}

// round 10
// speedup vs baseline: 7.7307x; 1.0027x over previous
#include <cuda_runtime.h>
#include <cuda_fp16.h>

#define B_   4
#define C_   256
#define H_   48
#define W_   48
#define HW   2304
#define HEADS 8
#define DH   64
#define HID  512
#define S_   2304
#define EPSF 1e-5f
#define SCALEF 0.125f
#define LOG2E 1.4426950408889634f
#define LOG2_10000 13.287712379549449f

// ---------------- scratch ----------------
__device__ float  g_mean[B_*HW];
__device__ float  g_rstd[B_*HW];
__device__ __half g_qkv [B_*3*HID*HW];   // fp16 intermediate (qkv gemm out)
__device__ __half g_conv[B_*3*HID*HW];   // fp16 intermediate (dwconv out)
__device__ float  g_cosT[S_*32];
__device__ float  g_sinT[S_*32];
__device__ uint4  g_qu  [32*144*4*32];   // Q  A-frags fp16
__device__ uint4  g_ku  [32*36*512];     // K  B-frags fp16 (8KB/tile)
__device__ uint4  g_vu  [32*36*512];     // V  B-frags fp16
__device__ float  g_oT  [B_*HID*HW];     // attention out, channel-major [b][c][s]

__device__ __forceinline__ unsigned pack_h2(float lo, float hi) {
    unsigned u;
    asm("cvt.rn.f16x2.f32 %0, %1, %2;" : "=r"(u) : "f"(hi), "f"(lo));
    return u;
}
__device__ __forceinline__ unsigned ex2h2(unsigned u) {
    unsigned r;
    asm("ex2.approx.f16x2 %0, %1;" : "=r"(r) : "r"(u));
    return r;
}

__device__ __forceinline__ void mma16(float* c, const unsigned* a, unsigned b0, unsigned b1) {
    asm("mma.sync.aligned.m16n8k16.row.col.f32.f16.f16.f32 "
        "{%0,%1,%2,%3},{%4,%5,%6,%7},{%8,%9},{%0,%1,%2,%3};"
        : "+f"(c[0]), "+f"(c[1]), "+f"(c[2]), "+f"(c[3])
        : "r"(a[0]), "r"(a[1]), "r"(a[2]), "r"(a[3]), "r"(b0), "r"(b1));
}

__device__ __forceinline__ unsigned smem_u32(const void* p) {
    return (unsigned)__cvta_generic_to_shared(p);
}
__device__ __forceinline__ void cp16(unsigned dst, const void* src) {
    asm volatile("cp.async.cg.shared.global [%0], [%1], 16;" :: "r"(dst), "l"(src));
}
__device__ __forceinline__ void cp_commit() {
    asm volatile("cp.async.commit_group;");
}
template<int N>
__device__ __forceinline__ void cp_wait() {
    asm volatile("cp.async.wait_group %0;" :: "n"(N));
}

// ---------------- 1) fused: rope tables + layernorm stats ----------------
__global__ void ln_tab(const float* __restrict__ x) {
    int idx = blockIdx.x * blockDim.x + threadIdx.x;
    if (idx < S_ * 32) {
        int s = idx >> 5, j = idx & 31;
        float invf = exp2f(-((float)(2 * j) * (1.0f / 64.0f)) * LOG2_10000);
        float a = (float)s * invf;
        float sa, ca;
        sincosf(a, &sa, &ca);
        g_cosT[idx] = ca;
        g_sinT[idx] = sa;
        return;
    }
    idx -= S_ * 32;
    if (idx >= B_ * HW) return;
    const float* xp = x + (size_t)(idx / HW) * C_ * HW + (idx % HW);
    float s0 = 0.f, s1 = 0.f, s2 = 0.f, s3 = 0.f;
    float q0 = 0.f, q1 = 0.f, q2 = 0.f, q3 = 0.f;
    #pragma unroll 4
    for (int c = 0; c < C_; c += 4) {
        float v0 = xp[(size_t)(c + 0) * HW];
        float v1 = xp[(size_t)(c + 1) * HW];
        float v2 = xp[(size_t)(c + 2) * HW];
        float v3 = xp[(size_t)(c + 3) * HW];
        s0 += v0; q0 += v0 * v0;
        s1 += v1; q1 += v1 * v1;
        s2 += v2; q2 += v2 * v2;
        s3 += v3; q3 += v3 * v3;
    }
    float mean = (s0 + s1 + s2 + s3) * (1.f / C_);
    float var  = (q0 + q1 + q2 + q3) * (1.f / C_) - mean * mean;
    g_mean[idx] = mean;
    g_rstd[idx] = rsqrtf(var + EPSF);
}

// ---------------- 2/6) fp16 TC GEMM; OUTH selects fp16 vs fp32 output ----------------
template<int KD, bool BIAS, bool LN, bool OUTH>
__global__ void __launch_bounds__(256) gemm_tc(const float* __restrict__ A,
                                               const float* __restrict__ Bmat,
                                               void* __restrict__ Cmat,
                                               const float* __restrict__ bias,
                                               const float* __restrict__ gvec) {
    __shared__ unsigned As[128][12];
    __shared__ unsigned Bs[8][136];
    const int b  = blockIdx.z;
    const int n0 = blockIdx.x * 128, m0 = blockIdx.y * 128;
    const int tid = threadIdx.x;
    const int w = tid >> 5, lane = tid & 31;
    const int wm = w >> 1, wn = w & 1;
    const int g = lane >> 2, q = lane & 3;
    const float* Bb = Bmat + (size_t)b * KD * HW;
    float c[2][8][4] = {};
    const int am = tid >> 1, apart = tid & 1;
    const int bkk = tid >> 5, bn4 = (tid & 31) * 4;

    float4 mn, rs;
    if (LN) {
        mn = *(const float4*)(g_mean + (size_t)b * HW + n0 + bn4);
        rs = *(const float4*)(g_rstd + (size_t)b * HW + n0 + bn4);
    }

    const float* apBase = A + (size_t)(m0 + am) * KD + 8 * apart;
    const float* bpBase = Bb + (size_t)(2 * bkk) * HW + n0 + bn4;

    float4 av0 = *(const float4*)(apBase);
    float4 av1 = *(const float4*)(apBase + 4);
    float4 r0  = *(const float4*)(bpBase);
    float4 r1  = *(const float4*)(bpBase + HW);
    float gk0 = 0.f, gk1 = 0.f;
    if (LN) { gk0 = gvec[2 * bkk]; gk1 = gvec[2 * bkk + 1]; }

    for (int k0 = 0; k0 < KD; k0 += 16) {
        {
            uint4 u;
            u.x = pack_h2(av0.x, av0.y); u.y = pack_h2(av0.z, av0.w);
            u.z = pack_h2(av1.x, av1.y); u.w = pack_h2(av1.z, av1.w);
            *(uint4*)(&As[am][4 * apart]) = u;
        }
        {
            float4 s0 = r0, s1 = r1;
            if (LN) {
                s0.x = (s0.x - mn.x) * rs.x * gk0; s1.x = (s1.x - mn.x) * rs.x * gk1;
                s0.y = (s0.y - mn.y) * rs.y * gk0; s1.y = (s1.y - mn.y) * rs.y * gk1;
                s0.z = (s0.z - mn.z) * rs.z * gk0; s1.z = (s1.z - mn.z) * rs.z * gk1;
                s0.w = (s0.w - mn.w) * rs.w * gk0; s1.w = (s1.w - mn.w) * rs.w * gk1;
            }
            Bs[bkk][bn4 + 0] = pack_h2(s0.x, s1.x);
            Bs[bkk][bn4 + 1] = pack_h2(s0.y, s1.y);
            Bs[bkk][bn4 + 2] = pack_h2(s0.z, s1.z);
            Bs[bkk][bn4 + 3] = pack_h2(s0.w, s1.w);
        }
        __syncthreads();

        if (k0 + 16 < KD) {
            const float* ap = apBase + k0 + 16;
            av0 = *(const float4*)(ap);
            av1 = *(const float4*)(ap + 4);
            const float* bp = bpBase + (size_t)(k0 + 16) * HW;
            r0 = *(const float4*)(bp);
            r1 = *(const float4*)(bp + HW);
            if (LN) { gk0 = gvec[k0 + 16 + 2 * bkk]; gk1 = gvec[k0 + 17 + 2 * bkk]; }
        }

        unsigned a[2][4];
        #pragma unroll
        for (int i = 0; i < 2; i++) {
            int m = wm * 32 + i * 16;
            a[i][0] = As[m + g    ][q];
            a[i][1] = As[m + g + 8][q];
            a[i][2] = As[m + g    ][q + 4];
            a[i][3] = As[m + g + 8][q + 4];
        }
        #pragma unroll
        for (int nb = 0; nb < 8; nb++) {
            int n = wn * 64 + nb * 8 + g;
            unsigned b0 = Bs[q    ][n];
            unsigned b1 = Bs[q + 4][n];
            mma16(c[0][nb], a[0], b0, b1);
            mma16(c[1][nb], a[1], b0, b1);
        }
        __syncthreads();
    }

    const int rows = BIAS ? C_ : 3 * HID;
    #pragma unroll
    for (int i = 0; i < 2; i++) {
        int m = m0 + wm * 32 + i * 16 + g;
        float bb0 = BIAS ? bias[m] : 0.f;
        float bb8 = BIAS ? bias[m + 8] : 0.f;
        #pragma unroll
        for (int nb = 0; nb < 8; nb++) {
            int n = n0 + wn * 64 + nb * 8 + 2 * q;
            if (OUTH) {
                __half* Cb = (__half*)Cmat + (size_t)b * rows * HW;
                *(unsigned*)(Cb + (size_t)m * HW + n) =
                    pack_h2(c[i][nb][0] + bb0, c[i][nb][1] + bb0);
                *(unsigned*)(Cb + (size_t)(m + 8) * HW + n) =
                    pack_h2(c[i][nb][2] + bb8, c[i][nb][3] + bb8);
            } else {
                float* Cb = (float*)Cmat + (size_t)b * rows * HW;
                *(float2*)(Cb + (size_t)m * HW + n) =
                    make_float2(c[i][nb][0] + bb0, c[i][nb][1] + bb0);
                *(float2*)(Cb + (size_t)(m + 8) * HW + n) =
                    make_float2(c[i][nb][2] + bb8, c[i][nb][3] + bb8);
            }
        }
    }
}

// ---------------- 3) depthwise 3x3 conv (4x4 patch per thread, fp16 io) ----------------
__global__ void dwconv44(const float* __restrict__ wq,
                         const float* __restrict__ wk,
                         const float* __restrict__ wv) {
    int idx = blockIdx.x * blockDim.x + threadIdx.x;
    if (idx >= B_ * 3 * HID * 144) return;
    int x0 = (idx % 12) * 4;
    int y0 = ((idx / 12) % 12) * 4;
    int ch = idx / 144;
    int c  = ch % (3 * HID);
    const float* wsel = (c < HID) ? wq : (c < 2 * HID) ? wk : wv;
    const float* w = wsel + (size_t)(c & (HID - 1)) * 9;
    float w9[9];
    #pragma unroll
    for (int i = 0; i < 9; i++) w9[i] = __ldg(&w[i]);

    const __half* ip = g_qkv + (size_t)ch * HW;
    float in[6][6];
    #pragma unroll
    for (int r = 0; r < 6; r++) {
        int y = y0 - 1 + r;
        if (y < 0 || y >= H_) {
            #pragma unroll
            for (int cc = 0; cc < 6; cc++) in[r][cc] = 0.f;
        } else {
            const __half* row = ip + y * W_ + x0;
            in[r][0] = (x0 > 0) ? __half2float(row[-1]) : 0.f;
            __half2 c01 = *(const __half2*)(row);
            __half2 c23 = *(const __half2*)(row + 2);
            float2 f01 = __half22float2(c01);
            float2 f23 = __half22float2(c23);
            in[r][1] = f01.x; in[r][2] = f01.y; in[r][3] = f23.x; in[r][4] = f23.y;
            in[r][5] = (x0 + 4 < W_) ? __half2float(row[4]) : 0.f;
        }
    }
    #pragma unroll
    for (int ry = 0; ry < 4; ry++) {
        float o[4];
        #pragma unroll
        for (int rx = 0; rx < 4; rx++) {
            float acc = 0.f;
            #pragma unroll
            for (int dy = 0; dy < 3; dy++)
                #pragma unroll
                for (int dx = 0; dx < 3; dx++)
                    acc += in[ry + dy][rx + dx] * w9[dy * 3 + dx];
            o[rx] = acc;
        }
        *(uint2*)(g_conv + (size_t)ch * HW + (y0 + ry) * W_ + x0) =
            make_uint2(pack_h2(o[0], o[1]), pack_h2(o[2], o[3]));
    }
}

// ---------------- 4) rope via tables + direct fragment packing (fp16 in) ----------------
__global__ void __launch_bounds__(256) pack_qkv() {
    const int tl  = blockIdx.x;
    const int sel = blockIdx.y >> 5;
    const int bh  = blockIdx.y & 31;
    const int b = bh >> 3, h = bh & 7;
    const int t = threadIdx.x, w = t >> 5, lane = t & 31;
    const int g = lane >> 2, q = lane & 3;
    const __half* cb = g_conv + ((size_t)(b * 3 * HID + sel * HID + h * DH)) * HW;

    if (sel == 2) {
        // V: already fp16 — pure half2 copy into fragment layout
        const int dd = w * 8 + g;
        const __half* col = cb + (size_t)dd * HW + tl * 64;
        uint2* dst = ((uint2*)g_vu) + ((size_t)(bh * 36 + tl)) * 1024 + w * 128 + lane;
        #pragma unroll
        for (int ks = 0; ks < 4; ks++) {
            unsigned u0 = *(const unsigned*)(col + 16 * ks + 2 * q);
            unsigned u1 = *(const unsigned*)(col + 16 * ks + 8 + 2 * q);
            dst[ks * 32] = make_uint2(u0, u1);
        }
    } else if (sel == 1) {
        const int nb = w;
        const int s = tl * 64 + nb * 8 + g;
        float xv[4][2][2];
        #pragma unroll
        for (int hi = 0; hi < 4; hi++)
            #pragma unroll
            for (int bb = 0; bb < 2; bb++) {
                int dd = 16 * hi + 8 * bb + 2 * q;
                xv[hi][bb][0] = __half2float(cb[(size_t)dd * HW + s]);
                xv[hi][bb][1] = __half2float(cb[(size_t)(dd + 1) * HW + s]);
            }
        float2 cT[2][2], sT[2][2];
        #pragma unroll
        for (int k1 = 0; k1 < 2; k1++)
            #pragma unroll
            for (int bb = 0; bb < 2; bb++) {
                int j = 16 * k1 + 8 * bb + 2 * q;
                cT[k1][bb] = *(const float2*)(g_cosT + s * 32 + j);
                sT[k1][bb] = *(const float2*)(g_sinT + s * 32 + j);
            }
        uint2* dst = ((uint2*)g_ku) + ((size_t)(bh * 36 + tl)) * 1024 + nb * 128 + lane;
        #pragma unroll
        for (int ks = 0; ks < 4; ks++) {
            int k1 = ks & 1;
            unsigned uu[2];
            #pragma unroll
            for (int bb = 0; bb < 2; bb++) {
                float v[2];
                #pragma unroll
                for (int e = 0; e < 2; e++) {
                    float cc = e ? cT[k1][bb].y : cT[k1][bb].x;
                    float ss = e ? sT[k1][bb].y : sT[k1][bb].x;
                    float t1 = xv[ks][bb][e], t2 = xv[ks ^ 2][bb][e];
                    v[e] = (ks < 2) ? (t1 * cc - t2 * ss) : (t1 * cc + t2 * ss);
                }
                uu[bb] = pack_h2(v[0], v[1]);
            }
            dst[ks * 32] = make_uint2(uu[0], uu[1]);
        }
    } else {
        const int p = w >> 2;
        const int r16 = tl * 4 + (w & 3);
        const int s0 = r16 * 16 + g;
        float xv[2][2][2][2];
        #pragma unroll
        for (int kk = 0; kk < 2; kk++)
            #pragma unroll
            for (int hiK = 0; hiK < 2; hiK++)
                #pragma unroll
                for (int e = 0; e < 2; e++) {
                    int dd = 16 * (p + 2 * kk) + 8 * hiK + 2 * q + e;
                    const __half* rowp = cb + (size_t)dd * HW;
                    xv[kk][hiK][e][0] = __half2float(rowp[s0]);
                    xv[kk][hiK][e][1] = __half2float(rowp[s0 + 8]);
                }
        float2 cT[2][2], sT[2][2];
        #pragma unroll
        for (int hiK = 0; hiK < 2; hiK++)
            #pragma unroll
            for (int si = 0; si < 2; si++) {
                int j = 16 * p + 8 * hiK + 2 * q;
                int off = (s0 + 8 * si) * 32 + j;
                cT[hiK][si] = *(const float2*)(g_cosT + off);
                sT[hiK][si] = *(const float2*)(g_sinT + off);
            }
        const float QS = SCALEF * LOG2E;
        uint4* dst = g_qu + ((size_t)(bh * 144 + r16)) * 4 * 32 + lane;
        #pragma unroll
        for (int kk = 0; kk < 2; kk++) {
            unsigned r[4];
            #pragma unroll
            for (int hiK = 0; hiK < 2; hiK++)
                #pragma unroll
                for (int si = 0; si < 2; si++) {
                    float v[2];
                    #pragma unroll
                    for (int e = 0; e < 2; e++) {
                        float cc = e ? cT[hiK][si].y : cT[hiK][si].x;
                        float ss = e ? sT[hiK][si].y : sT[hiK][si].x;
                        float t1 = xv[kk][hiK][e][si], t2 = xv[kk ^ 1][hiK][e][si];
                        float vv = (kk == 0) ? (t1 * cc - t2 * ss) : (t1 * cc + t2 * ss);
                        v[e] = vv * QS;
                    }
                    r[si + 2 * hiK] = pack_h2(v[0], v[1]);
                }
            dst[(p + 2 * kk) * 32] = make_uint4(r[0], r[1], r[2], r[3]);
        }
    }
}

// ---------------- 5) flash attention: 3-stage cp.async ring, one sync/tile ----------------
__global__ void __launch_bounds__(128) flash_tc() {
    __shared__ uint4 KV[3][1024];   // [stage][ K:0..511 | V:512..1023 ] 48KB
    const int b = blockIdx.z, h = blockIdx.y;
    const int bh = b * HEADS + h;
    const int w    = threadIdx.x >> 5, lane = threadIdx.x & 31;
    const int q    = lane & 3, g = lane >> 2;
    const int grp0 = blockIdx.x * 8 + w * 2;

    uint4 qa[2][4];
    {
        const uint4* qf = g_qu + (size_t)(bh * 144) * 4 * 32;
        #pragma unroll
        for (int h2 = 0; h2 < 2; h2++)
            #pragma unroll
            for (int ks = 0; ks < 4; ks++)
                qa[h2][ks] = qf[(size_t)((grp0 + h2) * 4 + ks) * 32 + lane];
    }

    float o[2][8][4] = {};
    float m0[2] = {-1e30f, -1e30f}, m1[2] = {-1e30f, -1e30f};
    float l0[2] = {0.f, 0.f}, l1[2] = {0.f, 0.f};

    const uint4* kg = g_ku + (size_t)(bh * 36) * 512;
    const uint4* vg = g_vu + (size_t)(bh * 36) * 512;

    // prologue: tiles 0 and 1 into stages 0 and 1 (separate groups)
    #pragma unroll
    for (int pt = 0; pt < 2; pt++) {
        #pragma unroll
        for (int i = 0; i < 4; i++) {
            int e = threadIdx.x + 128 * i;
            cp16(smem_u32(&KV[pt][e]),       kg + (size_t)pt * 512 + e);
            cp16(smem_u32(&KV[pt][512 + e]), vg + (size_t)pt * 512 + e);
        }
        cp_commit();
    }

    int st = 0;
    for (int t = 0; t < 36; t++) {
        if (t < 35) cp_wait<1>(); else cp_wait<0>();
        __syncthreads();   // single barrier per tile

        // issue tile t+2 into stage (st+2)%3 — last read two barriers ago
        if (t + 2 < 36) {
            int ns = st + 2; if (ns >= 3) ns -= 3;
            #pragma unroll
            for (int i = 0; i < 4; i++) {
                int e = threadIdx.x + 128 * i;
                cp16(smem_u32(&KV[ns][e]),       kg + (size_t)(t + 2) * 512 + e);
                cp16(smem_u32(&KV[ns][512 + e]), vg + (size_t)(t + 2) * 512 + e);
            }
            cp_commit();
        }

        const uint2* Ku = (const uint2*)(KV[st]);
        const uint2* Vu = (const uint2*)(KV[st] + 512);

        // ---- S = Q K^T ----
        float s[2][8][4] = {};
        #pragma unroll
        for (int nb = 0; nb < 8; nb++) {
            #pragma unroll
            for (int ks = 0; ks < 4; ks++) {
                uint2 bb = Ku[(nb * 4 + ks) * 32 + lane];
                mma16(s[0][nb], (const unsigned*)&qa[0][ks], bb.x, bb.y);
                mma16(s[1][nb], (const unsigned*)&qa[1][ks], bb.x, bb.y);
            }
        }

        // ---- online softmax: P as packed fp16 via ex2.approx.f16x2 ----
        unsigned pp[2][8][2];
        #pragma unroll
        for (int h2 = 0; h2 < 2; h2++) {
            float mx0 = -1e30f, mx1 = -1e30f;
            #pragma unroll
            for (int nb = 0; nb < 8; nb++) {
                mx0 = fmaxf(mx0, fmaxf(s[h2][nb][0], s[h2][nb][1]));
                mx1 = fmaxf(mx1, fmaxf(s[h2][nb][2], s[h2][nb][3]));
            }
            mx0 = fmaxf(mx0, __shfl_xor_sync(0xffffffffu, mx0, 1));
            mx0 = fmaxf(mx0, __shfl_xor_sync(0xffffffffu, mx0, 2));
            mx1 = fmaxf(mx1, __shfl_xor_sync(0xffffffffu, mx1, 1));
            mx1 = fmaxf(mx1, __shfl_xor_sync(0xffffffffu, mx1, 2));
            float nm0 = fmaxf(m0[h2], mx0), nm1 = fmaxf(m1[h2], mx1);
            float cf0 = exp2f(m0[h2] - nm0), cf1 = exp2f(m1[h2] - nm1);
            m0[h2] = nm0; m1[h2] = nm1;
            l0[h2] *= cf0; l1[h2] *= cf1;
            #pragma unroll
            for (int nb = 0; nb < 8; nb++) {
                o[h2][nb][0] *= cf0; o[h2][nb][1] *= cf0;
                o[h2][nb][2] *= cf1; o[h2][nb][3] *= cf1;
            }
            #pragma unroll
            for (int nb = 0; nb < 8; nb++) {
                unsigned u0 = ex2h2(pack_h2(s[h2][nb][0] - nm0, s[h2][nb][1] - nm0));
                unsigned u1 = ex2h2(pack_h2(s[h2][nb][2] - nm1, s[h2][nb][3] - nm1));
                pp[h2][nb][0] = u0;
                pp[h2][nb][1] = u1;
                float2 f0 = __half22float2(*reinterpret_cast<__half2*>(&u0));
                float2 f1 = __half22float2(*reinterpret_cast<__half2*>(&u1));
                l0[h2] += f0.x + f0.y;
                l1[h2] += f1.x + f1.y;
            }
        }

        // ---- O += P V ----
        #pragma unroll
        for (int ks = 0; ks < 4; ks++) {
            unsigned a0[4], a1[4];
            a0[0] = pp[0][2 * ks][0]; a0[1] = pp[0][2 * ks][1];
            a0[2] = pp[0][2 * ks + 1][0]; a0[3] = pp[0][2 * ks + 1][1];
            a1[0] = pp[1][2 * ks][0]; a1[1] = pp[1][2 * ks][1];
            a1[2] = pp[1][2 * ks + 1][0]; a1[3] = pp[1][2 * ks + 1][1];
            #pragma unroll
            for (int nb2 = 0; nb2 < 8; nb2++) {
                uint2 bb = Vu[(nb2 * 4 + ks) * 32 + lane];
                mma16(o[0][nb2], a0, bb.x, bb.y);
                mma16(o[1][nb2], a1, bb.x, bb.y);
            }
        }

        if (++st >= 3) st = 0;
    }

    #pragma unroll
    for (int h2 = 0; h2 < 2; h2++) {
        float L0 = l0[h2];
        L0 += __shfl_xor_sync(0xffffffffu, L0, 1);
        L0 += __shfl_xor_sync(0xffffffffu, L0, 2);
        float L1 = l1[h2];
        L1 += __shfl_xor_sync(0xffffffffu, L1, 1);
        L1 += __shfl_xor_sync(0xffffffffu, L1, 2);
        float inv0 = 1.f / L0, inv1 = 1.f / L1;
        int r0 = (grp0 + h2) * 16 + g;
        float* base = g_oT + ((size_t)b * HID + h * DH) * HW;
        #pragma unroll
        for (int nb2 = 0; nb2 < 8; nb2++) {
            int col = nb2 * 8 + 2 * q;
            base[(size_t)(col    ) * HW + r0    ] = o[h2][nb2][0] * inv0;
            base[(size_t)(col + 1) * HW + r0    ] = o[h2][nb2][1] * inv0;
            base[(size_t)(col    ) * HW + r0 + 8] = o[h2][nb2][2] * inv1;
            base[(size_t)(col + 1) * HW + r0 + 8] = o[h2][nb2][3] * inv1;
        }
    }
}

// ---------------- launcher ----------------
extern "C" void kernel_launch(void* const* d_in, const int* in_sizes, int n_in,
                              void* d_out, int out_size) {
    const float* x      = (const float*)d_in[0];
    const float* norm_g = (const float*)d_in[1];
    const float* w_qkv  = (const float*)d_in[2];
    const float* dw_q   = (const float*)d_in[3];
    const float* dw_k   = (const float*)d_in[4];
    const float* dw_v   = (const float*)d_in[5];
    const float* w_out  = (const float*)d_in[6];
    const float* b_out  = (const float*)d_in[7];
    float* out = (float*)d_out;

    void* qkv; cudaGetSymbolAddress(&qkv, g_qkv);
    float* oT; cudaGetSymbolAddress((void**)&oT, g_oT);

    ln_tab<<<(S_ * 32 + B_ * HW + 255) / 256, 256>>>(x);
    gemm_tc<C_, false, true, true><<<dim3(HW / 128, 3 * HID / 128, B_), 256>>>(w_qkv, x, qkv, nullptr, norm_g);
    dwconv44<<<(B_ * 3 * HID * 144 + 255) / 256, 256>>>(dw_q, dw_k, dw_v);
    pack_qkv<<<dim3(36, 96), 256>>>();
    flash_tc<<<dim3(S_ / 128, HEADS, B_), 128>>>();
    gemm_tc<HID, true, false, false><<<dim3(HW / 128, C_ / 128, B_), 256>>>(w_out, oT, out, b_out, nullptr);
}